// round 7
// baseline (speedup 1.0000x reference)
#include <cuda_runtime.h>
#include <math.h>
#include <stdint.h>

// ===========================================================================
// ForceFieldPredictor R7: mma.sync tf32, 512 threads (4x4 warp grid),
// scr aliased onto dead activation buffer to fit 227KB smem at 1 CTA/SM.
//
//  ffp_branch: fp32 (as R3) -> g_branchM[bo][k*3+j] = branch_out[k]*out_w[k][j]
//  ffp_main:   persistent, 512 thr, tile = 2 (b,o) = 128 rows.
//    Warp (wr,wc) owns 32 rows x 32 cols. Same total LDS/HMMA as R5 but
//    4 warps/SMSP for latency hiding.
// ===========================================================================

typedef unsigned long long ull;

// ---------------------------- small PTX helpers ----------------------------

__device__ __forceinline__ uint32_t f2tf32(float x) {
    uint32_t r; asm("cvt.rna.tf32.f32 %0, %1;" : "=r"(r) : "f"(x)); return r;
}
__device__ __forceinline__ float tf32f(float x) { return __uint_as_float(f2tf32(x)); }

__device__ __forceinline__ void mma8(float* d, const uint32_t* a, uint32_t b0, uint32_t b1) {
    asm volatile("mma.sync.aligned.m16n8k8.row.col.f32.tf32.tf32.f32 "
                 "{%0,%1,%2,%3}, {%4,%5,%6,%7}, {%8,%9}, {%0,%1,%2,%3};"
                 : "+f"(d[0]), "+f"(d[1]), "+f"(d[2]), "+f"(d[3])
                 : "r"(a[0]), "r"(a[1]), "r"(a[2]), "r"(a[3]), "r"(b0), "r"(b1));
}

// ------------------------- branch kernel (fp32, as R3) ---------------------

#define PADR 132
#define B_W     0
#define B_ACT0  16384
#define B_ACT1  (16384 + 64*PADR)
#define B_FEAT  (16384 + 2*64*PADR)
#define B_TOTAL (B_FEAT + 64*4)

__device__ float g_branchM[4096 * 384];   // [b*64+o][k*3+j]

#define FMA2(d, a, b) asm("fma.rn.f32x2 %0, %1, %2, %0;" : "+l"(d) : "l"(a), "l"(b))
#define SPLAT2(d, s)  asm("mov.b64 %0, {%1, %1};" : "=l"(d) : "r"(s))

__device__ __forceinline__ void stage_copy(float* dst, const float* src, int n, int tid)
{
    for (int i = tid * 4; i < n; i += 256 * 4)
        *(float4*)(dst + i) = *(const float4*)(src + i);
}

__device__ __forceinline__ void gemm_hidden_f2(const float* __restrict__ actIn,
                                               float* __restrict__ actOut,
                                               const float* __restrict__ sW,
                                               const float* __restrict__ bias_g,
                                               int ty, int tx, bool relu_in)
{
    const int r0 = ty * 4, c0 = tx * 8;
    ull acc[4][4];
    {
        ulonglong2 b0 = *(const ulonglong2*)(bias_g + c0);
        ulonglong2 b1 = *(const ulonglong2*)(bias_g + c0 + 4);
        #pragma unroll
        for (int i = 0; i < 4; i++) {
            acc[i][0] = b0.x; acc[i][1] = b0.y;
            acc[i][2] = b1.x; acc[i][3] = b1.y;
        }
    }
    for (int k = 0; k < 128; k += 4) {
        float4 av[4];
        #pragma unroll
        for (int i = 0; i < 4; i++) {
            float4 v = *(const float4*)(actIn + (r0 + i) * PADR + k);
            if (relu_in) {
                v.x = fmaxf(v.x, 0.f); v.y = fmaxf(v.y, 0.f);
                v.z = fmaxf(v.z, 0.f); v.w = fmaxf(v.w, 0.f);
            }
            av[i] = v;
        }
        #pragma unroll
        for (int kk = 0; kk < 4; kk++) {
            ulonglong2 w0 = *(const ulonglong2*)(sW + (k + kk) * 128 + c0);
            ulonglong2 w1 = *(const ulonglong2*)(sW + (k + kk) * 128 + c0 + 4);
            #pragma unroll
            for (int i = 0; i < 4; i++) {
                float a = (kk == 0) ? av[i].x : (kk == 1) ? av[i].y
                        : (kk == 2) ? av[i].z : av[i].w;
                ull a2;
                SPLAT2(a2, __float_as_uint(a));
                FMA2(acc[i][0], a2, w0.x);
                FMA2(acc[i][1], a2, w0.y);
                FMA2(acc[i][2], a2, w1.x);
                FMA2(acc[i][3], a2, w1.y);
            }
        }
    }
    #pragma unroll
    for (int i = 0; i < 4; i++) {
        ulonglong2 s0; s0.x = acc[i][0]; s0.y = acc[i][1];
        ulonglong2 s1; s1.x = acc[i][2]; s1.y = acc[i][3];
        *(ulonglong2*)(actOut + (r0 + i) * PADR + c0)     = s0;
        *(ulonglong2*)(actOut + (r0 + i) * PADR + c0 + 4) = s1;
    }
}

__device__ __forceinline__ void gemm_input(const float* __restrict__ feat, int fstride, int K,
                                           float* __restrict__ actOut,
                                           const float* __restrict__ sWin,
                                           const float* __restrict__ bias_g,
                                           int ty, int tx)
{
    const int r0 = ty * 4, c0 = tx * 8;
    float acc[4][8];
    float4 bv0 = *(const float4*)(bias_g + c0);
    float4 bv1 = *(const float4*)(bias_g + c0 + 4);
    #pragma unroll
    for (int i = 0; i < 4; i++) {
        acc[i][0] = bv0.x; acc[i][1] = bv0.y; acc[i][2] = bv0.z; acc[i][3] = bv0.w;
        acc[i][4] = bv1.x; acc[i][5] = bv1.y; acc[i][6] = bv1.z; acc[i][7] = bv1.w;
    }
    for (int k = 0; k < K; k++) {
        float4 w0 = *(const float4*)(sWin + k * 128 + c0);
        float4 w1 = *(const float4*)(sWin + k * 128 + c0 + 4);
        #pragma unroll
        for (int i = 0; i < 4; i++) {
            float a = feat[(r0 + i) * fstride + k];
            acc[i][0] = fmaf(a, w0.x, acc[i][0]);
            acc[i][1] = fmaf(a, w0.y, acc[i][1]);
            acc[i][2] = fmaf(a, w0.z, acc[i][2]);
            acc[i][3] = fmaf(a, w0.w, acc[i][3]);
            acc[i][4] = fmaf(a, w1.x, acc[i][4]);
            acc[i][5] = fmaf(a, w1.y, acc[i][5]);
            acc[i][6] = fmaf(a, w1.z, acc[i][6]);
            acc[i][7] = fmaf(a, w1.w, acc[i][7]);
        }
    }
    #pragma unroll
    for (int i = 0; i < 4; i++) {
        *(float4*)(actOut + (r0 + i) * PADR + c0)     = make_float4(acc[i][0], acc[i][1], acc[i][2], acc[i][3]);
        *(float4*)(actOut + (r0 + i) * PADR + c0 + 4) = make_float4(acc[i][4], acc[i][5], acc[i][6], acc[i][7]);
    }
}

__device__ __forceinline__ float segdist(float px, float py, float ax, float ay,
                                         float abx, float aby, float s)
{
    float t = ((px - ax) * abx + (py - ay) * aby) / s;
    t = fminf(fmaxf(t, 0.f), 1.f);
    float dx = px - (ax + t * abx);
    float dy = py - (ay + t * aby);
    return sqrtf(dx * dx + dy * dy);
}

extern "C" __global__ void __launch_bounds__(256, 1)
ffp_branch(const float* __restrict__ init_x,
           const float* __restrict__ branch_w0, const float* __restrict__ branch_b0,
           const float* __restrict__ branch_ws, const float* __restrict__ branch_bs,
           const float* __restrict__ out_w)
{
    extern __shared__ float sm[];
    float* sW   = sm + B_W;
    float* act0 = sm + B_ACT0;
    float* act1 = sm + B_ACT1;
    float* feat = sm + B_FEAT;
    const int tid = threadIdx.x, ty = tid >> 4, tx = tid & 15;
    const int b = blockIdx.x;

    stage_copy(sW, branch_w0 + 2 * 128, 384, tid);
    if (tid < 64) {
        const float* ix = init_x + (b * 64 + tid) * 9;
        feat[tid * 4 + 0] = ix[2];
        feat[tid * 4 + 1] = ix[3];
        feat[tid * 4 + 2] = ix[4];
    }
    __syncthreads();
    gemm_input(feat, 4, 3, act0, sW, branch_b0, ty, tx);
    __syncthreads();
    stage_copy(sW, branch_ws, 16384, tid);
    __syncthreads();
    gemm_hidden_f2(act0, act1, sW, branch_bs, ty, tx, true);
    __syncthreads();
    stage_copy(sW, branch_ws + 16384, 16384, tid);
    __syncthreads();
    gemm_hidden_f2(act1, act0, sW, branch_bs + 128, ty, tx, true);
    __syncthreads();

    for (int idx = tid; idx < 64 * 384; idx += 256) {
        int o = idx / 384;
        int r = idx - o * 384;
        int k = r / 3;
        int j = r - k * 3;
        g_branchM[(b * 64 + o) * 384 + r] = act0[o * PADR + k] * out_w[k * 3 + j];
    }
}

// ------------------------------- main kernel -------------------------------
// smem layout (float offsets)
#define S_W1    0                 // 16384 : trunk H1, tf32, swizzled [n][k]
#define S_W2    16384             // 16384 : trunk H2
#define S_ACT   32768             // 16896 : activations, stride 132
                                  //   featT aliases S_ACT+0     (stride 20, 2560)
                                  //   featJ aliases S_ACT+2560  (stride 20, 2560)
                                  //   scr   aliases S_ACT+0     (row*20, 2560)
#define S_W0T   49664             // 2304 : trunk W0t [n][k], stride 18, tf32
#define S_JW0T  51968             // 2304 : joint W0t
#define S_B0    54272
#define S_B1    54400
#define S_B2    54528
#define S_JB0   54656
#define S_JW1   54784             // 256 : [part][128]
#define S_MSH   55040             // 768 : tile*384 + part*128 + k
#define S_TOTAL 55808             // 223,232 B

#define ASTR 132                  // activation row stride
#define FSTR 20                   // feature / scratch row stride
#define WSTR 18                   // input-weight row stride
#define NT   512                  // threads

// d layout: d[rb*4+nt][4] ; warp (wr,wc): rows wr*32+[0,32), cols wc*32+[0,32)
__device__ __forceinline__ void layer_hidden(const float* __restrict__ sW,
                                             const float* __restrict__ act,
                                             float (*d)[4],
                                             int wr, int wc, int g, int t4)
{
    #pragma unroll
    for (int i = 0; i < 8; i++)
        d[i][0] = d[i][1] = d[i][2] = d[i][3] = 0.f;
    const float* a0p = act + (wr * 32 + g) * ASTR + t4;
    const float* b0p = sW + (wc * 32 + g) * 128 + t4;
    #pragma unroll 4
    for (int c = 0; c < 16; c++) {
        uint32_t A[2][4];
        #pragma unroll
        for (int rb = 0; rb < 2; rb++) {
            const float* ap = a0p + rb * 16 * ASTR + c * 8;
            A[rb][0] = __float_as_uint(ap[0]);
            A[rb][1] = __float_as_uint(ap[8 * ASTR]);
            A[rb][2] = __float_as_uint(ap[4]);
            A[rb][3] = __float_as_uint(ap[8 * ASTR + 4]);
        }
        const int w0 = ((2 * c) ^ g) << 2;
        const int w1 = ((2 * c + 1) ^ g) << 2;
        #pragma unroll
        for (int nt = 0; nt < 4; nt++) {
            const float* bp = b0p + nt * 8 * 128;
            uint32_t b0 = __float_as_uint(bp[w0]);
            uint32_t b1 = __float_as_uint(bp[w1]);
            mma8(d[nt],     A[0], b0, b1);
            mma8(d[4 + nt], A[1], b0, b1);
        }
    }
}

__device__ __forceinline__ void layer_input(const float* __restrict__ sWin,
                                            const float* __restrict__ feat,
                                            float (*d)[4],
                                            int wr, int wc, int g, int t4)
{
    #pragma unroll
    for (int i = 0; i < 8; i++)
        d[i][0] = d[i][1] = d[i][2] = d[i][3] = 0.f;
    const float* a0p = feat + (wr * 32 + g) * FSTR + t4;
    const float* b0p = sWin + (wc * 32 + g) * WSTR + t4;
    #pragma unroll
    for (int c = 0; c < 2; c++) {
        uint32_t A[2][4];
        #pragma unroll
        for (int rb = 0; rb < 2; rb++) {
            const float* ap = a0p + rb * 16 * FSTR + c * 8;
            A[rb][0] = __float_as_uint(ap[0]);
            A[rb][1] = __float_as_uint(ap[8 * FSTR]);
            A[rb][2] = __float_as_uint(ap[4]);
            A[rb][3] = __float_as_uint(ap[8 * FSTR + 4]);
        }
        #pragma unroll
        for (int nt = 0; nt < 4; nt++) {
            const float* bp = b0p + nt * 8 * WSTR + c * 8;
            uint32_t b0 = __float_as_uint(bp[0]);
            uint32_t b1 = __float_as_uint(bp[4]);
            mma8(d[nt],     A[0], b0, b1);
            mma8(d[4 + nt], A[1], b0, b1);
        }
    }
}

// relu(d + bias) -> tf32 -> act
__device__ __forceinline__ void writeback(float (*d)[4], float* __restrict__ act,
                                          const float* __restrict__ bias,
                                          int wr, int wc, int g, int t4)
{
    #pragma unroll
    for (int rb = 0; rb < 2; rb++) {
        const int r = wr * 32 + rb * 16 + g;
        #pragma unroll
        for (int nt = 0; nt < 4; nt++) {
            const int col = wc * 32 + nt * 8 + t4 * 2;
            float2 bb = *(const float2*)(bias + col);
            float* p = act + r * ASTR + col;
            const float* dd = d[rb * 4 + nt];
            p[0] = tf32f(fmaxf(dd[0] + bb.x, 0.f));
            p[1] = tf32f(fmaxf(dd[1] + bb.y, 0.f));
            p[8 * ASTR]     = tf32f(fmaxf(dd[2] + bb.x, 0.f));
            p[8 * ASTR + 1] = tf32f(fmaxf(dd[3] + bb.y, 0.f));
        }
    }
}

extern "C" __global__ void __launch_bounds__(NT, 1)
ffp_main(const float* __restrict__ init_x,  const float* __restrict__ query_x,
         const float* __restrict__ init_v,  const float* __restrict__ query_v,
         const float* __restrict__ init_av, const float* __restrict__ query_av,
         const float* __restrict__ trunk_w0, const float* __restrict__ trunk_b0,
         const float* __restrict__ trunk_ws, const float* __restrict__ trunk_bs,
         const float* __restrict__ out_b,
         const float* __restrict__ spring_w0, const float* __restrict__ spring_b0,
         const float* __restrict__ spring_w1, const float* __restrict__ spring_b1,
         const float* __restrict__ joint_w0, const float* __restrict__ joint_b0,
         const float* __restrict__ joint_w1, const float* __restrict__ joint_b1,
         float* __restrict__ out)
{
    extern __shared__ float sm[];
    float* act   = sm + S_ACT;
    float* featT = sm + S_ACT;          // aliases act (released at L0 writeback)
    float* featJ = sm + S_ACT + 2560;
    float* scr   = sm + S_ACT;          // aliases act (act dead in epilogue)
    float* msh   = sm + S_MSH;
    const int tid = threadIdx.x;
    const int wid = tid >> 5, lane = tid & 31;
    const int wr = wid & 3, wc = wid >> 2;
    const int g = lane >> 2, t4 = lane & 3;

    // ---- one-time weight staging (tf32) ----
    for (int i = tid * 4; i < 4608; i += NT * 4)
        *(float4*)(sm + S_W0T + i) = make_float4(0.f, 0.f, 0.f, 0.f);
    __syncthreads();
    for (int idx = tid; idx < 16384; idx += NT) {
        int k = idx >> 7, n = idx & 127;
        int f = n * 128 + (((k >> 2) ^ (n & 7)) << 2) + (k & 3);
        sm[S_W1 + f] = tf32f(trunk_ws[idx]);
        sm[S_W2 + f] = tf32f(trunk_ws[16384 + idx]);
    }
    for (int idx = tid; idx < 9 * 128; idx += NT) {
        int k = idx >> 7, n = idx & 127;
        sm[S_W0T + n * WSTR + k] = tf32f(trunk_w0[idx]);
    }
    for (int idx = tid; idx < 15 * 128; idx += NT) {
        int k = idx >> 7, n = idx & 127;
        sm[S_JW0T + n * WSTR + k] = tf32f(joint_w0[idx]);
    }
    for (int i = tid; i < 128; i += NT) {
        sm[S_B0 + i]  = trunk_b0[i];
        sm[S_B1 + i]  = trunk_bs[i];
        sm[S_B2 + i]  = trunk_bs[128 + i];
        sm[S_JB0 + i] = joint_b0[i];
    }
    if (tid < 256) sm[S_JW1 + tid] = joint_w1[(tid & 127) * 2 + (tid >> 7)];
    __syncthreads();

    for (int pp = blockIdx.x; pp < 2048; pp += gridDim.x) {
        const int bo0 = pp << 1;

        // stage msh planar: tile*384 + part*128 + k
        for (int d0 = tid; d0 < 768; d0 += NT) {
            int tile = d0 / 384, rr = d0 - tile * 384;
            int part = rr >> 7, k = rr & 127;
            msh[d0] = g_branchM[(bo0 + tile) * 384 + k * 3 + part];
        }

        // ---- features (tid<128), masks kept in registers ----
        float relx = 0.f, rely = 0.f, maskD = 0.f, maskJ = 0.f, maskS = 0.f;
        if (tid < 128) {
            const int r = tid, tile = r >> 6, t = r & 63;
            const int bo = bo0 + tile, b = bo >> 6;
            const float* ix = init_x + bo * 9;
            const float* qx = query_x + (b * 64 + t) * 9;
            float i2 = ix[2], i3 = ix[3], i4 = ix[4], i7 = ix[7], i8 = ix[8];
            float q2 = qx[2], q3 = qx[3], q4 = qx[4], q7 = qx[7], q8 = qx[8];
            relx = qx[0] - ix[0]; rely = qx[1] - ix[1];
            float qvx = query_v[(b * 64 + t) * 2 + 0] - init_v[bo * 2 + 0];
            float qvy = query_v[(b * 64 + t) * 2 + 1] - init_v[bo * 2 + 1];
            float iav = init_av[bo];
            float qav = query_av[b * 64 + t] - iav;

            float sn1, cs1; sincosf(i3 * 100.f, &sn1, &cs1);
            float sn2, cs2; sincosf(q3 * 100.f, &sn2, &cs2);
            float o1x = i2 * 0.5f * cs1, o1y = i2 * 0.5f * sn1;
            float o2x = q2 * 0.5f * cs2, o2y = q2 * 0.5f * sn2;
            float ab1x = 2.f * o1x, ab1y = 2.f * o1y;
            float ab2x = 2.f * o2x, ab2y = 2.f * o2y;
            float ss1 = ab1x * ab1x + ab1y * ab1y + 1e-8f;
            float ss2 = ab2x * ab2x + ab2y * ab2y + 1e-8f;
            float A2x = relx - o2x, A2y = rely - o2y;
            float B2x = relx + o2x, B2y = rely + o2y;
            float d1 = segdist(A2x, A2y, -o1x, -o1y, ab1x, ab1y, ss1);
            float d2 = segdist(B2x, B2y, -o1x, -o1y, ab1x, ab1y, ss1);
            float d3 = segdist(-o1x, -o1y, A2x, A2y, ab2x, ab2y, ss2);
            float d4 = segdist(o1x, o1y, A2x, A2y, ab2x, ab2y, ss2);
            float dist = fminf(fminf(d1, d2), fminf(d3, d4)) - i4 - q4;
            maskD = (dist <= 0.f) ? 1.f : 0.f;
            float ti = truncf(i7), tq = truncf(q7);
            maskJ = (ti == tq && i7 > 0.f) ? 1.f : 0.f;
            maskS = (i8 == q8 && i8 > 0.f) ? 1.f : 0.f;

            uint32_t ft[16], fj[16];
            ft[0] = f2tf32(relx); ft[1] = f2tf32(rely);
            ft[2] = f2tf32(q2);   ft[3] = f2tf32(q3);  ft[4] = f2tf32(q4);
            ft[5] = f2tf32(qvx);  ft[6] = f2tf32(qvy); ft[7] = f2tf32(qav);
            ft[8] = f2tf32(dist * maskD * 100.f);
            #pragma unroll
            for (int j = 9; j < 16; j++) ft[j] = 0u;
            fj[0] = 0u; fj[1] = 0u;
            fj[2] = f2tf32(i2);  fj[3] = f2tf32(i3);  fj[4] = f2tf32(i4);
            fj[5] = ft[0]; fj[6] = ft[1];
            fj[7] = ft[2]; fj[8] = ft[3]; fj[9] = ft[4];
            fj[10] = ft[5]; fj[11] = ft[6];
            fj[12] = f2tf32(iav); fj[13] = ft[7];
            fj[14] = f2tf32(i7 - ti); fj[15] = 0u;
            #pragma unroll
            for (int j = 0; j < 4; j++) {
                *(float4*)(featT + r * FSTR + j * 4) = *(float4*)(ft + j * 4);
                *(float4*)(featJ + r * FSTR + j * 4) = *(float4*)(fj + j * 4);
            }
        }
        __syncthreads();   // (1) features + msh ready

        float d[8][4];
        float pj[4][2];    // joint epilogue partials, held in regs until scr write

        // ---- joint L0 -> pj (registers only) ----
        {
            layer_input(sm + S_JW0T, featJ, d, wr, wc, g, t4);
            #pragma unroll
            for (int q = 0; q < 4; q++) pj[q][0] = pj[q][1] = 0.f;
            #pragma unroll
            for (int rb = 0; rb < 2; rb++)
            #pragma unroll
            for (int nt = 0; nt < 4; nt++) {
                const int col = wc * 32 + nt * 8 + 2 * t4;
                float2 jb = *(const float2*)(sm + S_JB0 + col);
                float2 w0v = *(const float2*)(sm + S_JW1 + col);
                float2 w1v = *(const float2*)(sm + S_JW1 + 128 + col);
                const float* dd = d[rb * 4 + nt];
                float h0 = fmaxf(dd[0] + jb.x, 0.f), h1 = fmaxf(dd[1] + jb.y, 0.f);
                float h2 = fmaxf(dd[2] + jb.x, 0.f), h3 = fmaxf(dd[3] + jb.y, 0.f);
                pj[rb * 2][0]     += h0 * w0v.x + h1 * w0v.y;
                pj[rb * 2][1]     += h0 * w1v.x + h1 * w1v.y;
                pj[rb * 2 + 1][0] += h2 * w0v.x + h3 * w0v.y;
                pj[rb * 2 + 1][1] += h2 * w1v.x + h3 * w1v.y;
            }
        }

        // ---- trunk L0 ----
        layer_input(sm + S_W0T, featT, d, wr, wc, g, t4);
        __syncthreads();   // (2) feat reads done; act region may be overwritten
        writeback(d, act, sm + S_B0, wr, wc, g, t4);
        __syncthreads();   // (3)

        // ---- trunk H1 ----
        layer_hidden(sm + S_W1, act, d, wr, wc, g, t4);
        __syncthreads();   // (4)
        writeback(d, act, sm + S_B1, wr, wc, g, t4);
        __syncthreads();   // (5)

        // ---- trunk H2 (fragments consumed directly) ----
        layer_hidden(sm + S_W2, act, d, wr, wc, g, t4);
        float p[4][3];
        {
            const float* mb = msh + (wr >> 1) * 384;
            #pragma unroll
            for (int q = 0; q < 4; q++) p[q][0] = p[q][1] = p[q][2] = 0.f;
            #pragma unroll
            for (int rb = 0; rb < 2; rb++)
            #pragma unroll
            for (int nt = 0; nt < 4; nt++) {
                const int col = wc * 32 + nt * 8 + 2 * t4;
                float2 bb = *(const float2*)(sm + S_B2 + col);
                float2 m0 = *(const float2*)(mb + col);
                float2 m1 = *(const float2*)(mb + 128 + col);
                float2 m2 = *(const float2*)(mb + 256 + col);
                const float* dd = d[rb * 4 + nt];
                float h0 = dd[0] + bb.x, h1 = dd[1] + bb.y;
                float h2 = dd[2] + bb.x, h3 = dd[3] + bb.y;
                p[rb * 2][0]     += h0 * m0.x + h1 * m0.y;
                p[rb * 2][1]     += h0 * m1.x + h1 * m1.y;
                p[rb * 2][2]     += h0 * m2.x + h1 * m2.y;
                p[rb * 2 + 1][0] += h2 * m0.x + h3 * m0.y;
                p[rb * 2 + 1][1] += h2 * m1.x + h3 * m1.y;
                p[rb * 2 + 1][2] += h2 * m2.x + h3 * m2.y;
            }
        }
        __syncthreads();   // (6) all act reads done; scr (alias of act) writable

        // ---- shfl-reduce partials, write scr[row*20 + wc*5 + {0..4}] ----
        #pragma unroll
        for (int q = 0; q < 4; q++) {
            const int row = wr * 32 + (q >> 1) * 16 + g + (q & 1) * 8;
            #pragma unroll
            for (int j = 0; j < 3; j++) {
                float v = p[q][j];
                v += __shfl_xor_sync(0xffffffffu, v, 1);
                v += __shfl_xor_sync(0xffffffffu, v, 2);
                if (t4 == 0) scr[row * FSTR + wc * 5 + j] = v;
            }
            #pragma unroll
            for (int j = 0; j < 2; j++) {
                float v = pj[q][j];
                v += __shfl_xor_sync(0xffffffffu, v, 1);
                v += __shfl_xor_sync(0xffffffffu, v, 2);
                if (t4 == 0) scr[row * FSTR + wc * 5 + 3 + j] = v;
            }
        }
        __syncthreads();   // (7) scr complete

        // ---- combine + masks + spring + store ----
        if (tid < 128) {
            const int r = tid, tile = r >> 6, t = r & 63;
            const int bo = bo0 + tile;
            const float* s = scr + r * FSTR;
            float f0 = (s[0] + s[5] + s[10] + s[15] + out_b[0]) * maskD;
            float f1 = (s[1] + s[6] + s[11] + s[16] + out_b[1]) * maskD;
            float f2 = (s[2] + s[7] + s[12] + s[17] + out_b[2]) * maskD;
            if (maskJ > 0.f) {
                f0 += s[3] + s[8] + s[13] + s[18] + joint_b1[0];
                f1 += s[4] + s[9] + s[14] + s[19] + joint_b1[1];
            }
            if (maskS > 0.f) {
                float len = sqrtf(relx * relx + rely * rely);
                float sf = spring_b1[0];
                for (int k = 0; k < 128; k++)
                    sf = fmaf(fmaxf(fmaf(len, spring_w0[k], spring_b0[k]), 0.f),
                              spring_w1[k], sf);
                float inv = 1.f / (len + 1e-8f);
                f0 = fmaf(sf, -relx * inv, f0);
                f1 = fmaf(sf, -rely * inv, f1);
            }
            float* op = out + (bo * 64 + t) * 3;
            op[0] = f0; op[1] = f1; op[2] = f2;
        }
        __syncthreads();   // (8) protect msh/scr/feat for next iteration
    }
}

// ---------------------------------------------------------------------------

extern "C" void kernel_launch(void* const* d_in, const int* in_sizes, int n_in,
                              void* d_out, int out_size)
{
    const float* init_x    = (const float*)d_in[0];
    const float* query_x   = (const float*)d_in[1];
    const float* init_v    = (const float*)d_in[2];
    const float* query_v   = (const float*)d_in[3];
    const float* init_av   = (const float*)d_in[4];
    const float* query_av  = (const float*)d_in[5];
    const float* trunk_w0  = (const float*)d_in[6];
    const float* trunk_b0  = (const float*)d_in[7];
    const float* trunk_ws  = (const float*)d_in[8];
    const float* trunk_bs  = (const float*)d_in[9];
    const float* branch_w0 = (const float*)d_in[10];
    const float* branch_b0 = (const float*)d_in[11];
    const float* branch_ws = (const float*)d_in[12];
    const float* branch_bs = (const float*)d_in[13];
    const float* out_w     = (const float*)d_in[14];
    const float* out_b     = (const float*)d_in[15];
    const float* spring_w0 = (const float*)d_in[16];
    const float* spring_b0 = (const float*)d_in[17];
    const float* spring_w1 = (const float*)d_in[18];
    const float* spring_b1 = (const float*)d_in[19];
    const float* joint_w0  = (const float*)d_in[20];
    const float* joint_b0  = (const float*)d_in[21];
    const float* joint_w1  = (const float*)d_in[22];
    const float* joint_b1  = (const float*)d_in[23];
    float* out = (float*)d_out;

    int nsm = 148;
    cudaDeviceGetAttribute(&nsm, cudaDevAttrMultiProcessorCount, 0);

    const int smem_b = B_TOTAL * sizeof(float);
    const int smem_m = S_TOTAL * sizeof(float);
    cudaFuncSetAttribute(ffp_branch, cudaFuncAttributeMaxDynamicSharedMemorySize, smem_b);
    cudaFuncSetAttribute(ffp_main,   cudaFuncAttributeMaxDynamicSharedMemorySize, smem_m);

    ffp_branch<<<64, 256, smem_b>>>(init_x, branch_w0, branch_b0, branch_ws, branch_bs, out_w);
    ffp_main<<<nsm, NT, smem_m>>>(init_x, query_x, init_v, query_v, init_av, query_av,
                                  trunk_w0, trunk_b0, trunk_ws, trunk_bs,
                                  out_b,
                                  spring_w0, spring_b0, spring_w1, spring_b1,
                                  joint_w0, joint_b0, joint_w1, joint_b1,
                                  out);
}

// round 8
// speedup vs baseline: 1.0047x; 1.0047x over previous
#include <cuda_runtime.h>
#include <math.h>
#include <stdint.h>

// ===========================================================================
// ForceFieldPredictor R8: two phase-shifted 8-warp worker groups per CTA.
// Each group processes its own (b,o) 64-row tile through the full MLP chain,
// synced by named barriers (bar.sync 1/2, 256). Shared tf32 weights in smem;
// groups anti-phase so crossbar and tensor pipes overlap across groups.
// ===========================================================================

typedef unsigned long long ull;

// ---------------------------- small PTX helpers ----------------------------

__device__ __forceinline__ uint32_t f2tf32(float x) {
    uint32_t r; asm("cvt.rna.tf32.f32 %0, %1;" : "=r"(r) : "f"(x)); return r;
}
__device__ __forceinline__ float tf32f(float x) { return __uint_as_float(f2tf32(x)); }

__device__ __forceinline__ void mma8(float* d, const uint32_t* a, uint32_t b0, uint32_t b1) {
    asm volatile("mma.sync.aligned.m16n8k8.row.col.f32.tf32.tf32.f32 "
                 "{%0,%1,%2,%3}, {%4,%5,%6,%7}, {%8,%9}, {%0,%1,%2,%3};"
                 : "+f"(d[0]), "+f"(d[1]), "+f"(d[2]), "+f"(d[3])
                 : "r"(a[0]), "r"(a[1]), "r"(a[2]), "r"(a[3]), "r"(b0), "r"(b1));
}

#define BARG(id) asm volatile("bar.sync %0, %1;" :: "r"(id), "r"(256) : "memory")

// ------------------------- branch kernel (fp32, as R3) ---------------------

#define PADR 132
#define B_W     0
#define B_ACT0  16384
#define B_ACT1  (16384 + 64*PADR)
#define B_FEAT  (16384 + 2*64*PADR)
#define B_TOTAL (B_FEAT + 64*4)

__device__ float g_branchM[4096 * 384];   // [b*64+o][k*3+j]

#define FMA2(d, a, b) asm("fma.rn.f32x2 %0, %1, %2, %0;" : "+l"(d) : "l"(a), "l"(b))
#define SPLAT2(d, s)  asm("mov.b64 %0, {%1, %1};" : "=l"(d) : "r"(s))

__device__ __forceinline__ void stage_copy(float* dst, const float* src, int n, int tid)
{
    for (int i = tid * 4; i < n; i += 256 * 4)
        *(float4*)(dst + i) = *(const float4*)(src + i);
}

__device__ __forceinline__ void gemm_hidden_f2(const float* __restrict__ actIn,
                                               float* __restrict__ actOut,
                                               const float* __restrict__ sW,
                                               const float* __restrict__ bias_g,
                                               int ty, int tx, bool relu_in)
{
    const int r0 = ty * 4, c0 = tx * 8;
    ull acc[4][4];
    {
        ulonglong2 b0 = *(const ulonglong2*)(bias_g + c0);
        ulonglong2 b1 = *(const ulonglong2*)(bias_g + c0 + 4);
        #pragma unroll
        for (int i = 0; i < 4; i++) {
            acc[i][0] = b0.x; acc[i][1] = b0.y;
            acc[i][2] = b1.x; acc[i][3] = b1.y;
        }
    }
    for (int k = 0; k < 128; k += 4) {
        float4 av[4];
        #pragma unroll
        for (int i = 0; i < 4; i++) {
            float4 v = *(const float4*)(actIn + (r0 + i) * PADR + k);
            if (relu_in) {
                v.x = fmaxf(v.x, 0.f); v.y = fmaxf(v.y, 0.f);
                v.z = fmaxf(v.z, 0.f); v.w = fmaxf(v.w, 0.f);
            }
            av[i] = v;
        }
        #pragma unroll
        for (int kk = 0; kk < 4; kk++) {
            ulonglong2 w0 = *(const ulonglong2*)(sW + (k + kk) * 128 + c0);
            ulonglong2 w1 = *(const ulonglong2*)(sW + (k + kk) * 128 + c0 + 4);
            #pragma unroll
            for (int i = 0; i < 4; i++) {
                float a = (kk == 0) ? av[i].x : (kk == 1) ? av[i].y
                        : (kk == 2) ? av[i].z : av[i].w;
                ull a2;
                SPLAT2(a2, __float_as_uint(a));
                FMA2(acc[i][0], a2, w0.x);
                FMA2(acc[i][1], a2, w0.y);
                FMA2(acc[i][2], a2, w1.x);
                FMA2(acc[i][3], a2, w1.y);
            }
        }
    }
    #pragma unroll
    for (int i = 0; i < 4; i++) {
        ulonglong2 s0; s0.x = acc[i][0]; s0.y = acc[i][1];
        ulonglong2 s1; s1.x = acc[i][2]; s1.y = acc[i][3];
        *(ulonglong2*)(actOut + (r0 + i) * PADR + c0)     = s0;
        *(ulonglong2*)(actOut + (r0 + i) * PADR + c0 + 4) = s1;
    }
}

__device__ __forceinline__ void gemm_input(const float* __restrict__ feat, int fstride, int K,
                                           float* __restrict__ actOut,
                                           const float* __restrict__ sWin,
                                           const float* __restrict__ bias_g,
                                           int ty, int tx)
{
    const int r0 = ty * 4, c0 = tx * 8;
    float acc[4][8];
    float4 bv0 = *(const float4*)(bias_g + c0);
    float4 bv1 = *(const float4*)(bias_g + c0 + 4);
    #pragma unroll
    for (int i = 0; i < 4; i++) {
        acc[i][0] = bv0.x; acc[i][1] = bv0.y; acc[i][2] = bv0.z; acc[i][3] = bv0.w;
        acc[i][4] = bv1.x; acc[i][5] = bv1.y; acc[i][6] = bv1.z; acc[i][7] = bv1.w;
    }
    for (int k = 0; k < K; k++) {
        float4 w0 = *(const float4*)(sWin + k * 128 + c0);
        float4 w1 = *(const float4*)(sWin + k * 128 + c0 + 4);
        #pragma unroll
        for (int i = 0; i < 4; i++) {
            float a = feat[(r0 + i) * fstride + k];
            acc[i][0] = fmaf(a, w0.x, acc[i][0]);
            acc[i][1] = fmaf(a, w0.y, acc[i][1]);
            acc[i][2] = fmaf(a, w0.z, acc[i][2]);
            acc[i][3] = fmaf(a, w0.w, acc[i][3]);
            acc[i][4] = fmaf(a, w1.x, acc[i][4]);
            acc[i][5] = fmaf(a, w1.y, acc[i][5]);
            acc[i][6] = fmaf(a, w1.z, acc[i][6]);
            acc[i][7] = fmaf(a, w1.w, acc[i][7]);
        }
    }
    #pragma unroll
    for (int i = 0; i < 4; i++) {
        *(float4*)(actOut + (r0 + i) * PADR + c0)     = make_float4(acc[i][0], acc[i][1], acc[i][2], acc[i][3]);
        *(float4*)(actOut + (r0 + i) * PADR + c0 + 4) = make_float4(acc[i][4], acc[i][5], acc[i][6], acc[i][7]);
    }
}

__device__ __forceinline__ float segdist(float px, float py, float ax, float ay,
                                         float abx, float aby, float s)
{
    float t = ((px - ax) * abx + (py - ay) * aby) / s;
    t = fminf(fmaxf(t, 0.f), 1.f);
    float dx = px - (ax + t * abx);
    float dy = py - (ay + t * aby);
    return sqrtf(dx * dx + dy * dy);
}

extern "C" __global__ void __launch_bounds__(256, 1)
ffp_branch(const float* __restrict__ init_x,
           const float* __restrict__ branch_w0, const float* __restrict__ branch_b0,
           const float* __restrict__ branch_ws, const float* __restrict__ branch_bs,
           const float* __restrict__ out_w)
{
    extern __shared__ float sm[];
    float* sW   = sm + B_W;
    float* act0 = sm + B_ACT0;
    float* act1 = sm + B_ACT1;
    float* feat = sm + B_FEAT;
    const int tid = threadIdx.x, ty = tid >> 4, tx = tid & 15;
    const int b = blockIdx.x;

    stage_copy(sW, branch_w0 + 2 * 128, 384, tid);
    if (tid < 64) {
        const float* ix = init_x + (b * 64 + tid) * 9;
        feat[tid * 4 + 0] = ix[2];
        feat[tid * 4 + 1] = ix[3];
        feat[tid * 4 + 2] = ix[4];
    }
    __syncthreads();
    gemm_input(feat, 4, 3, act0, sW, branch_b0, ty, tx);
    __syncthreads();
    stage_copy(sW, branch_ws, 16384, tid);
    __syncthreads();
    gemm_hidden_f2(act0, act1, sW, branch_bs, ty, tx, true);
    __syncthreads();
    stage_copy(sW, branch_ws + 16384, 16384, tid);
    __syncthreads();
    gemm_hidden_f2(act1, act0, sW, branch_bs + 128, ty, tx, true);
    __syncthreads();

    for (int idx = tid; idx < 64 * 384; idx += 256) {
        int o = idx / 384;
        int r = idx - o * 384;
        int k = r / 3;
        int j = r - k * 3;
        g_branchM[(b * 64 + o) * 384 + r] = act0[o * PADR + k] * out_w[k * 3 + j];
    }
}

// ------------------------------- main kernel -------------------------------
// smem layout (float offsets)
#define S_W1    0                 // 16384 : trunk H1, tf32, swizzled [n][k]
#define S_W2    16384             // 16384 : trunk H2
#define S_ACT   32768             // 16896 : 2 group slices of 8448 (64 x 132)
                                  //   per group: featT = +0 (64x20), featJ = +1280,
                                  //              scr aliases +0 (64x20)
#define S_W0T   49664             // 2304 : trunk W0t [n][k], stride 18, tf32
#define S_JW0T  51968             // 2304 : joint W0t
#define S_B0    54272
#define S_B1    54400
#define S_B2    54528
#define S_JB0   54656
#define S_JW1   54784             // 256 : [part][128]
#define S_MSH   55040             // 768 : 2 groups x 384 (part*128+k)
#define S_TOTAL 55808             // 223,232 B

#define ASTR 132                  // activation row stride
#define FSTR 20                   // feature / scratch row stride
#define WSTR 18                   // input-weight row stride
#define NT   512                  // threads
#define GSLICE 8448               // 64*132

// warp tile: 32 rows x 32 cols; group grid 2(row) x 4(col) over 64x128
__device__ __forceinline__ void layer_hidden(const float* __restrict__ sW,
                                             const float* __restrict__ act,
                                             float (*d)[4],
                                             int wr, int wc, int g, int t4)
{
    #pragma unroll
    for (int i = 0; i < 8; i++)
        d[i][0] = d[i][1] = d[i][2] = d[i][3] = 0.f;
    const float* a0p = act + (wr * 32 + g) * ASTR + t4;
    const float* b0p = sW + (wc * 32 + g) * 128 + t4;
    #pragma unroll 4
    for (int c = 0; c < 16; c++) {
        uint32_t A[2][4];
        #pragma unroll
        for (int rb = 0; rb < 2; rb++) {
            const float* ap = a0p + rb * 16 * ASTR + c * 8;
            A[rb][0] = __float_as_uint(ap[0]);
            A[rb][1] = __float_as_uint(ap[8 * ASTR]);
            A[rb][2] = __float_as_uint(ap[4]);
            A[rb][3] = __float_as_uint(ap[8 * ASTR + 4]);
        }
        const int w0 = ((2 * c) ^ g) << 2;
        const int w1 = ((2 * c + 1) ^ g) << 2;
        #pragma unroll
        for (int nt = 0; nt < 4; nt++) {
            const float* bp = b0p + nt * 8 * 128;
            uint32_t b0 = __float_as_uint(bp[w0]);
            uint32_t b1 = __float_as_uint(bp[w1]);
            mma8(d[nt],     A[0], b0, b1);
            mma8(d[4 + nt], A[1], b0, b1);
        }
    }
}

__device__ __forceinline__ void layer_input(const float* __restrict__ sWin,
                                            const float* __restrict__ feat,
                                            float (*d)[4],
                                            int wr, int wc, int g, int t4)
{
    #pragma unroll
    for (int i = 0; i < 8; i++)
        d[i][0] = d[i][1] = d[i][2] = d[i][3] = 0.f;
    const float* a0p = feat + (wr * 32 + g) * FSTR + t4;
    const float* b0p = sWin + (wc * 32 + g) * WSTR + t4;
    #pragma unroll
    for (int c = 0; c < 2; c++) {
        uint32_t A[2][4];
        #pragma unroll
        for (int rb = 0; rb < 2; rb++) {
            const float* ap = a0p + rb * 16 * FSTR + c * 8;
            A[rb][0] = __float_as_uint(ap[0]);
            A[rb][1] = __float_as_uint(ap[8 * FSTR]);
            A[rb][2] = __float_as_uint(ap[4]);
            A[rb][3] = __float_as_uint(ap[8 * FSTR + 4]);
        }
        #pragma unroll
        for (int nt = 0; nt < 4; nt++) {
            const float* bp = b0p + nt * 8 * WSTR + c * 8;
            uint32_t b0 = __float_as_uint(bp[0]);
            uint32_t b1 = __float_as_uint(bp[4]);
            mma8(d[nt],     A[0], b0, b1);
            mma8(d[4 + nt], A[1], b0, b1);
        }
    }
}

// relu(d + bias) -> tf32 -> act
__device__ __forceinline__ void writeback(float (*d)[4], float* __restrict__ act,
                                          const float* __restrict__ bias,
                                          int wr, int wc, int g, int t4)
{
    #pragma unroll
    for (int rb = 0; rb < 2; rb++) {
        const int r = wr * 32 + rb * 16 + g;
        #pragma unroll
        for (int nt = 0; nt < 4; nt++) {
            const int col = wc * 32 + nt * 8 + t4 * 2;
            float2 bb = *(const float2*)(bias + col);
            float* p = act + r * ASTR + col;
            const float* dd = d[rb * 4 + nt];
            p[0] = tf32f(fmaxf(dd[0] + bb.x, 0.f));
            p[1] = tf32f(fmaxf(dd[1] + bb.y, 0.f));
            p[8 * ASTR]     = tf32f(fmaxf(dd[2] + bb.x, 0.f));
            p[8 * ASTR + 1] = tf32f(fmaxf(dd[3] + bb.y, 0.f));
        }
    }
}

extern "C" __global__ void __launch_bounds__(NT, 1)
ffp_main(const float* __restrict__ init_x,  const float* __restrict__ query_x,
         const float* __restrict__ init_v,  const float* __restrict__ query_v,
         const float* __restrict__ init_av, const float* __restrict__ query_av,
         const float* __restrict__ trunk_w0, const float* __restrict__ trunk_b0,
         const float* __restrict__ trunk_ws, const float* __restrict__ trunk_bs,
         const float* __restrict__ out_b,
         const float* __restrict__ spring_w0, const float* __restrict__ spring_b0,
         const float* __restrict__ spring_w1, const float* __restrict__ spring_b1,
         const float* __restrict__ joint_w0, const float* __restrict__ joint_b0,
         const float* __restrict__ joint_w1, const float* __restrict__ joint_b1,
         float* __restrict__ out)
{
    extern __shared__ float sm[];
    const int tid = threadIdx.x;
    const int gid = tid >> 8;                 // worker group 0/1
    const int tg  = tid & 255;                // tid within group
    const int wid_g = tg >> 5, lane = tid & 31;
    const int wr = wid_g & 1, wc = wid_g >> 1;
    const int g = lane >> 2, t4 = lane & 3;
    const int barid = 1 + gid;

    float* actg  = sm + S_ACT + gid * GSLICE;
    float* featT = actg;                       // aliases act
    float* featJ = actg + 1280;
    float* scr   = actg;                       // aliases act (dead in epilogue)
    float* mshg  = sm + S_MSH + gid * 384;

    // ---- one-time weight staging (tf32), whole CTA ----
    for (int i = tid * 4; i < 4608; i += NT * 4)
        *(float4*)(sm + S_W0T + i) = make_float4(0.f, 0.f, 0.f, 0.f);
    __syncthreads();
    for (int idx = tid; idx < 16384; idx += NT) {
        int k = idx >> 7, n = idx & 127;
        int f = n * 128 + (((k >> 2) ^ (n & 7)) << 2) + (k & 3);
        sm[S_W1 + f] = tf32f(trunk_ws[idx]);
        sm[S_W2 + f] = tf32f(trunk_ws[16384 + idx]);
    }
    for (int idx = tid; idx < 9 * 128; idx += NT) {
        int k = idx >> 7, n = idx & 127;
        sm[S_W0T + n * WSTR + k] = tf32f(trunk_w0[idx]);
    }
    for (int idx = tid; idx < 15 * 128; idx += NT) {
        int k = idx >> 7, n = idx & 127;
        sm[S_JW0T + n * WSTR + k] = tf32f(joint_w0[idx]);
    }
    for (int i = tid; i < 128; i += NT) {
        sm[S_B0 + i]  = trunk_b0[i];
        sm[S_B1 + i]  = trunk_bs[i];
        sm[S_B2 + i]  = trunk_bs[128 + i];
        sm[S_JB0 + i] = joint_b0[i];
    }
    if (tid < 256) sm[S_JW1 + tid] = joint_w1[(tid & 127) * 2 + (tid >> 7)];
    __syncthreads();

    for (int pp = blockIdx.x; pp < 2048; pp += gridDim.x) {
        const int bo = (pp << 1) + gid;        // this group's (b,o)
        const int b = bo >> 6;

        // stage msh: part*128 + k
        for (int d0 = tg; d0 < 384; d0 += 256) {
            int part = d0 >> 7, k = d0 & 127;
            mshg[d0] = g_branchM[bo * 384 + k * 3 + part];
        }

        // ---- features (tg<64), masks kept in registers ----
        float relx = 0.f, rely = 0.f, maskD = 0.f, maskJ = 0.f, maskS = 0.f;
        if (tg < 64) {
            const int t = tg;
            const float* ix = init_x + bo * 9;
            const float* qx = query_x + (b * 64 + t) * 9;
            float i2 = ix[2], i3 = ix[3], i4 = ix[4], i7 = ix[7], i8 = ix[8];
            float q2 = qx[2], q3 = qx[3], q4 = qx[4], q7 = qx[7], q8 = qx[8];
            relx = qx[0] - ix[0]; rely = qx[1] - ix[1];
            float qvx = query_v[(b * 64 + t) * 2 + 0] - init_v[bo * 2 + 0];
            float qvy = query_v[(b * 64 + t) * 2 + 1] - init_v[bo * 2 + 1];
            float iav = init_av[bo];
            float qav = query_av[b * 64 + t] - iav;

            float sn1, cs1; sincosf(i3 * 100.f, &sn1, &cs1);
            float sn2, cs2; sincosf(q3 * 100.f, &sn2, &cs2);
            float o1x = i2 * 0.5f * cs1, o1y = i2 * 0.5f * sn1;
            float o2x = q2 * 0.5f * cs2, o2y = q2 * 0.5f * sn2;
            float ab1x = 2.f * o1x, ab1y = 2.f * o1y;
            float ab2x = 2.f * o2x, ab2y = 2.f * o2y;
            float ss1 = ab1x * ab1x + ab1y * ab1y + 1e-8f;
            float ss2 = ab2x * ab2x + ab2y * ab2y + 1e-8f;
            float A2x = relx - o2x, A2y = rely - o2y;
            float B2x = relx + o2x, B2y = rely + o2y;
            float d1 = segdist(A2x, A2y, -o1x, -o1y, ab1x, ab1y, ss1);
            float d2 = segdist(B2x, B2y, -o1x, -o1y, ab1x, ab1y, ss1);
            float d3 = segdist(-o1x, -o1y, A2x, A2y, ab2x, ab2y, ss2);
            float d4 = segdist(o1x, o1y, A2x, A2y, ab2x, ab2y, ss2);
            float dist = fminf(fminf(d1, d2), fminf(d3, d4)) - i4 - q4;
            maskD = (dist <= 0.f) ? 1.f : 0.f;
            float ti = truncf(i7), tq = truncf(q7);
            maskJ = (ti == tq && i7 > 0.f) ? 1.f : 0.f;
            maskS = (i8 == q8 && i8 > 0.f) ? 1.f : 0.f;

            uint32_t ft[16], fj[16];
            ft[0] = f2tf32(relx); ft[1] = f2tf32(rely);
            ft[2] = f2tf32(q2);   ft[3] = f2tf32(q3);  ft[4] = f2tf32(q4);
            ft[5] = f2tf32(qvx);  ft[6] = f2tf32(qvy); ft[7] = f2tf32(qav);
            ft[8] = f2tf32(dist * maskD * 100.f);
            #pragma unroll
            for (int j = 9; j < 16; j++) ft[j] = 0u;
            fj[0] = 0u; fj[1] = 0u;
            fj[2] = f2tf32(i2);  fj[3] = f2tf32(i3);  fj[4] = f2tf32(i4);
            fj[5] = ft[0]; fj[6] = ft[1];
            fj[7] = ft[2]; fj[8] = ft[3]; fj[9] = ft[4];
            fj[10] = ft[5]; fj[11] = ft[6];
            fj[12] = f2tf32(iav); fj[13] = ft[7];
            fj[14] = f2tf32(i7 - ti); fj[15] = 0u;
            #pragma unroll
            for (int j = 0; j < 4; j++) {
                *(float4*)(featT + t * FSTR + j * 4) = *(float4*)(ft + j * 4);
                *(float4*)(featJ + t * FSTR + j * 4) = *(float4*)(fj + j * 4);
            }
        }
        BARG(barid);   // (1) features + msh ready

        float d[8][4];
        float pj[4][2];    // joint epilogue partials (registers)

        // ---- joint L0 -> pj ----
        {
            layer_input(sm + S_JW0T, featJ, d, wr, wc, g, t4);
            #pragma unroll
            for (int q = 0; q < 4; q++) pj[q][0] = pj[q][1] = 0.f;
            #pragma unroll
            for (int rb = 0; rb < 2; rb++)
            #pragma unroll
            for (int nt = 0; nt < 4; nt++) {
                const int col = wc * 32 + nt * 8 + 2 * t4;
                float2 jb = *(const float2*)(sm + S_JB0 + col);
                float2 w0v = *(const float2*)(sm + S_JW1 + col);
                float2 w1v = *(const float2*)(sm + S_JW1 + 128 + col);
                const float* dd = d[rb * 4 + nt];
                float h0 = fmaxf(dd[0] + jb.x, 0.f), h1 = fmaxf(dd[1] + jb.y, 0.f);
                float h2 = fmaxf(dd[2] + jb.x, 0.f), h3 = fmaxf(dd[3] + jb.y, 0.f);
                pj[rb * 2][0]     += h0 * w0v.x + h1 * w0v.y;
                pj[rb * 2][1]     += h0 * w1v.x + h1 * w1v.y;
                pj[rb * 2 + 1][0] += h2 * w0v.x + h3 * w0v.y;
                pj[rb * 2 + 1][1] += h2 * w1v.x + h3 * w1v.y;
            }
        }

        // ---- trunk L0 ----
        layer_input(sm + S_W0T, featT, d, wr, wc, g, t4);
        BARG(barid);   // (2) feat reads done; act may be overwritten
        writeback(d, actg, sm + S_B0, wr, wc, g, t4);
        BARG(barid);   // (3)

        // ---- trunk H1 ----
        layer_hidden(sm + S_W1, actg, d, wr, wc, g, t4);
        BARG(barid);   // (4)
        writeback(d, actg, sm + S_B1, wr, wc, g, t4);
        BARG(barid);   // (5)

        // ---- trunk H2 (fragments consumed directly) ----
        layer_hidden(sm + S_W2, actg, d, wr, wc, g, t4);
        float p[4][3];
        {
            #pragma unroll
            for (int q = 0; q < 4; q++) p[q][0] = p[q][1] = p[q][2] = 0.f;
            #pragma unroll
            for (int rb = 0; rb < 2; rb++)
            #pragma unroll
            for (int nt = 0; nt < 4; nt++) {
                const int col = wc * 32 + nt * 8 + 2 * t4;
                float2 bb = *(const float2*)(sm + S_B2 + col);
                float2 m0 = *(const float2*)(mshg + col);
                float2 m1 = *(const float2*)(mshg + 128 + col);
                float2 m2 = *(const float2*)(mshg + 256 + col);
                const float* dd = d[rb * 4 + nt];
                float h0 = dd[0] + bb.x, h1 = dd[1] + bb.y;
                float h2 = dd[2] + bb.x, h3 = dd[3] + bb.y;
                p[rb * 2][0]     += h0 * m0.x + h1 * m0.y;
                p[rb * 2][1]     += h0 * m1.x + h1 * m1.y;
                p[rb * 2][2]     += h0 * m2.x + h1 * m2.y;
                p[rb * 2 + 1][0] += h2 * m0.x + h3 * m0.y;
                p[rb * 2 + 1][1] += h2 * m1.x + h3 * m1.y;
                p[rb * 2 + 1][2] += h2 * m2.x + h3 * m2.y;
            }
        }
        BARG(barid);   // (6) act reads done; scr (alias) writable

        // ---- shfl-reduce partials -> scr[row*20 + wc*5 + {0..4}] ----
        #pragma unroll
        for (int q = 0; q < 4; q++) {
            const int row = wr * 32 + (q >> 1) * 16 + g + (q & 1) * 8;
            #pragma unroll
            for (int j = 0; j < 3; j++) {
                float v = p[q][j];
                v += __shfl_xor_sync(0xffffffffu, v, 1);
                v += __shfl_xor_sync(0xffffffffu, v, 2);
                if (t4 == 0) scr[row * FSTR + wc * 5 + j] = v;
            }
            #pragma unroll
            for (int j = 0; j < 2; j++) {
                float v = pj[q][j];
                v += __shfl_xor_sync(0xffffffffu, v, 1);
                v += __shfl_xor_sync(0xffffffffu, v, 2);
                if (t4 == 0) scr[row * FSTR + wc * 5 + 3 + j] = v;
            }
        }
        BARG(barid);   // (7) scr complete

        // ---- combine + masks + spring + store ----
        if (tg < 64) {
            const int t = tg;
            const float* s = scr + t * FSTR;
            float f0 = (s[0] + s[5] + s[10] + s[15] + out_b[0]) * maskD;
            float f1 = (s[1] + s[6] + s[11] + s[16] + out_b[1]) * maskD;
            float f2 = (s[2] + s[7] + s[12] + s[17] + out_b[2]) * maskD;
            if (maskJ > 0.f) {
                f0 += s[3] + s[8] + s[13] + s[18] + joint_b1[0];
                f1 += s[4] + s[9] + s[14] + s[19] + joint_b1[1];
            }
            if (maskS > 0.f) {
                float len = sqrtf(relx * relx + rely * rely);
                float sf = spring_b1[0];
                for (int k = 0; k < 128; k++)
                    sf = fmaf(fmaxf(fmaf(len, spring_w0[k], spring_b0[k]), 0.f),
                              spring_w1[k], sf);
                float inv = 1.f / (len + 1e-8f);
                f0 = fmaf(sf, -relx * inv, f0);
                f1 = fmaf(sf, -rely * inv, f1);
            }
            float* op = out + (bo * 64 + t) * 3;
            op[0] = f0; op[1] = f1; op[2] = f2;
        }
        // no trailing barrier needed:
        //  - next feat write for row t is by the same thread that read scr row t
        //  - msh region is disjoint from scr/feat; its readers finished pre-(6)
    }
}

// ---------------------------------------------------------------------------

extern "C" void kernel_launch(void* const* d_in, const int* in_sizes, int n_in,
                              void* d_out, int out_size)
{
    const float* init_x    = (const float*)d_in[0];
    const float* query_x   = (const float*)d_in[1];
    const float* init_v    = (const float*)d_in[2];
    const float* query_v   = (const float*)d_in[3];
    const float* init_av   = (const float*)d_in[4];
    const float* query_av  = (const float*)d_in[5];
    const float* trunk_w0  = (const float*)d_in[6];
    const float* trunk_b0  = (const float*)d_in[7];
    const float* trunk_ws  = (const float*)d_in[8];
    const float* trunk_bs  = (const float*)d_in[9];
    const float* branch_w0 = (const float*)d_in[10];
    const float* branch_b0 = (const float*)d_in[11];
    const float* branch_ws = (const float*)d_in[12];
    const float* branch_bs = (const float*)d_in[13];
    const float* out_w     = (const float*)d_in[14];
    const float* out_b     = (const float*)d_in[15];
    const float* spring_w0 = (const float*)d_in[16];
    const float* spring_b0 = (const float*)d_in[17];
    const float* spring_w1 = (const float*)d_in[18];
    const float* spring_b1 = (const float*)d_in[19];
    const float* joint_w0  = (const float*)d_in[20];
    const float* joint_b0  = (const float*)d_in[21];
    const float* joint_w1  = (const float*)d_in[22];
    const float* joint_b1  = (const float*)d_in[23];
    float* out = (float*)d_out;

    int nsm = 148;
    cudaDeviceGetAttribute(&nsm, cudaDevAttrMultiProcessorCount, 0);

    const int smem_b = B_TOTAL * sizeof(float);
    const int smem_m = S_TOTAL * sizeof(float);
    cudaFuncSetAttribute(ffp_branch, cudaFuncAttributeMaxDynamicSharedMemorySize, smem_b);
    cudaFuncSetAttribute(ffp_main,   cudaFuncAttributeMaxDynamicSharedMemorySize, smem_m);

    ffp_branch<<<64, 256, smem_b>>>(init_x, branch_w0, branch_b0, branch_ws, branch_bs, out_w);
    ffp_main<<<nsm, NT, smem_m>>>(init_x, query_x, init_v, query_v, init_av, query_av,
                                  trunk_w0, trunk_b0, trunk_ws, trunk_bs,
                                  out_b,
                                  spring_w0, spring_b0, spring_w1, spring_b1,
                                  joint_w0, joint_b0, joint_w1, joint_b1,
                                  out);
}

// round 9
// speedup vs baseline: 1.0760x; 1.0710x over previous
#include <cuda_runtime.h>
#include <math.h>
#include <stdint.h>

// ===========================================================================
// ForceFieldPredictor R9: single fused persistent kernel.
//  Phase 1 (CTAs 0..63): branch MLP (fp32 f32x2) -> g_branchM
//  Global ticket barrier (replay-safe, monotonic)
//  Phase 2: two 8-warp groups per CTA, mma.sync tf32 trunk/joint MLPs.
//    NEW: k-pair-packed weight/activation layouts (stride 136) so A and B
//    fragments load as conflict-free LDS.64 (halves LDS instr + addr ALU).
//    Biases / jw1 / msh live in the 8-float padding holes of weight rows.
// ===========================================================================

typedef unsigned long long ull;

__device__ float g_branchM[4096 * 384];   // [b*64+o][k*3+j]
__device__ unsigned int g_bar;            // ticket barrier (monotonic)

// ---------------------------- small PTX helpers ----------------------------

__device__ __forceinline__ uint32_t f2tf32(float x) {
    uint32_t r; asm("cvt.rna.tf32.f32 %0, %1;" : "=r"(r) : "f"(x)); return r;
}
__device__ __forceinline__ float tf32f(float x) { return __uint_as_float(f2tf32(x)); }

__device__ __forceinline__ void mma8(float* d, const uint32_t* a, uint32_t b0, uint32_t b1) {
    asm volatile("mma.sync.aligned.m16n8k8.row.col.f32.tf32.tf32.f32 "
                 "{%0,%1,%2,%3}, {%4,%5,%6,%7}, {%8,%9}, {%0,%1,%2,%3};"
                 : "+f"(d[0]), "+f"(d[1]), "+f"(d[2]), "+f"(d[3])
                 : "r"(a[0]), "r"(a[1]), "r"(a[2]), "r"(a[3]), "r"(b0), "r"(b1));
}

#define BARG(id) asm volatile("bar.sync %0, %1;" :: "r"(id), "r"(256) : "memory")
#define FMA2(d, a, b) asm("fma.rn.f32x2 %0, %1, %2, %0;" : "+l"(d) : "l"(a), "l"(b))
#define SPLAT2(d, s)  asm("mov.b64 %0, {%1, %1};" : "=l"(d) : "r"(s))

// ---------------------------- smem layout (floats) -------------------------
// Weight rows are 136 floats: 128 packed weights + 8-float hole.
// HOLE(h): h-th float of the hole space (row h>>3, slot h&7), h in [0,2048).
#define S_W1    0                 // 17408 : trunk H1 (tf32, k-pair packed)
#define S_W2    17408             // 17408 : trunk H2
#define S_INW   34816             // 4608  : input weights, stride 36/row
                                  //         trunk W0t at +0..15, joint at +16..31
#define S_ACT   39424             // 2 x 8704 (64 rows x 136) group act slices
#define S_TOTAL 56832             // 227,328 B

#define HOLE(h) ((((h) >> 3) * 136) + 128 + ((h) & 7))
#define HB0   0                   // trunk b0      (128)
#define HB1   128                 // trunk b1      (128)
#define HB2   256                 // trunk b2      (128)
#define HJB   384                 // joint b0      (128)
#define HJW1  512                 // joint w1      (256: part*128+k)
#define HMSH  1024                // msh           (2 groups x 384)

#define ASTRP 136                 // packed act/weight row stride
#define FSTR  20                  // feature / scratch row stride
#define WSTR  36                  // input-weight row stride
#define NT    512
#define GSLICE 8704               // 64*136

// branch-phase buffers (reuse main regions before staging)
#define PADR 132
#define BR_W    0                 // 16384  (inside W1 region)
#define BR_A0   17408             // 8448   (inside W2 region)
#define BR_A1   25856             // 8448
#define BR_F    34816             // 256    (inside INW region)

// -------------------- branch-phase fp32 helpers (as R3) --------------------

__device__ __forceinline__ void stage_copy(float* dst, const float* src, int n, int tid)
{
    for (int i = tid * 4; i < n; i += 256 * 4)
        *(float4*)(dst + i) = *(const float4*)(src + i);
}

__device__ __forceinline__ void gemm_hidden_f2(const float* __restrict__ actIn,
                                               float* __restrict__ actOut,
                                               const float* __restrict__ sW,
                                               const float* __restrict__ bias_g,
                                               int ty, int tx, bool relu_in)
{
    const int r0 = ty * 4, c0 = tx * 8;
    ull acc[4][4];
    {
        ulonglong2 b0 = *(const ulonglong2*)(bias_g + c0);
        ulonglong2 b1 = *(const ulonglong2*)(bias_g + c0 + 4);
        #pragma unroll
        for (int i = 0; i < 4; i++) {
            acc[i][0] = b0.x; acc[i][1] = b0.y;
            acc[i][2] = b1.x; acc[i][3] = b1.y;
        }
    }
    for (int k = 0; k < 128; k += 4) {
        float4 av[4];
        #pragma unroll
        for (int i = 0; i < 4; i++) {
            float4 v = *(const float4*)(actIn + (r0 + i) * PADR + k);
            if (relu_in) {
                v.x = fmaxf(v.x, 0.f); v.y = fmaxf(v.y, 0.f);
                v.z = fmaxf(v.z, 0.f); v.w = fmaxf(v.w, 0.f);
            }
            av[i] = v;
        }
        #pragma unroll
        for (int kk = 0; kk < 4; kk++) {
            ulonglong2 w0 = *(const ulonglong2*)(sW + (k + kk) * 128 + c0);
            ulonglong2 w1 = *(const ulonglong2*)(sW + (k + kk) * 128 + c0 + 4);
            #pragma unroll
            for (int i = 0; i < 4; i++) {
                float a = (kk == 0) ? av[i].x : (kk == 1) ? av[i].y
                        : (kk == 2) ? av[i].z : av[i].w;
                ull a2;
                SPLAT2(a2, __float_as_uint(a));
                FMA2(acc[i][0], a2, w0.x);
                FMA2(acc[i][1], a2, w0.y);
                FMA2(acc[i][2], a2, w1.x);
                FMA2(acc[i][3], a2, w1.y);
            }
        }
    }
    #pragma unroll
    for (int i = 0; i < 4; i++) {
        ulonglong2 s0; s0.x = acc[i][0]; s0.y = acc[i][1];
        ulonglong2 s1; s1.x = acc[i][2]; s1.y = acc[i][3];
        *(ulonglong2*)(actOut + (r0 + i) * PADR + c0)     = s0;
        *(ulonglong2*)(actOut + (r0 + i) * PADR + c0 + 4) = s1;
    }
}

__device__ __forceinline__ void gemm_input_f32(const float* __restrict__ feat, int fstride, int K,
                                               float* __restrict__ actOut,
                                               const float* __restrict__ sWin,
                                               const float* __restrict__ bias_g,
                                               int ty, int tx)
{
    const int r0 = ty * 4, c0 = tx * 8;
    float acc[4][8];
    float4 bv0 = *(const float4*)(bias_g + c0);
    float4 bv1 = *(const float4*)(bias_g + c0 + 4);
    #pragma unroll
    for (int i = 0; i < 4; i++) {
        acc[i][0] = bv0.x; acc[i][1] = bv0.y; acc[i][2] = bv0.z; acc[i][3] = bv0.w;
        acc[i][4] = bv1.x; acc[i][5] = bv1.y; acc[i][6] = bv1.z; acc[i][7] = bv1.w;
    }
    for (int k = 0; k < K; k++) {
        float4 w0 = *(const float4*)(sWin + k * 128 + c0);
        float4 w1 = *(const float4*)(sWin + k * 128 + c0 + 4);
        #pragma unroll
        for (int i = 0; i < 4; i++) {
            float a = feat[(r0 + i) * fstride + k];
            acc[i][0] = fmaf(a, w0.x, acc[i][0]);
            acc[i][1] = fmaf(a, w0.y, acc[i][1]);
            acc[i][2] = fmaf(a, w0.z, acc[i][2]);
            acc[i][3] = fmaf(a, w0.w, acc[i][3]);
            acc[i][4] = fmaf(a, w1.x, acc[i][4]);
            acc[i][5] = fmaf(a, w1.y, acc[i][5]);
            acc[i][6] = fmaf(a, w1.z, acc[i][6]);
            acc[i][7] = fmaf(a, w1.w, acc[i][7]);
        }
    }
    #pragma unroll
    for (int i = 0; i < 4; i++) {
        *(float4*)(actOut + (r0 + i) * PADR + c0)     = make_float4(acc[i][0], acc[i][1], acc[i][2], acc[i][3]);
        *(float4*)(actOut + (r0 + i) * PADR + c0 + 4) = make_float4(acc[i][4], acc[i][5], acc[i][6], acc[i][7]);
    }
}

__device__ __forceinline__ float segdist(float px, float py, float ax, float ay,
                                         float abx, float aby, float s)
{
    float t = ((px - ax) * abx + (py - ay) * aby) / s;
    t = fminf(fmaxf(t, 0.f), 1.f);
    float dx = px - (ax + t * abx);
    float dy = py - (ay + t * aby);
    return sqrtf(dx * dx + dy * dy);
}

// ----------------------- tf32 MMA layer helpers ----------------------------
// warp (wr in 0..1, wc in 0..3) owns 32 rows x 32 cols of a 64x128 tile.

__device__ __forceinline__ void layer_hidden(const float* __restrict__ sW,
                                             const float* __restrict__ act,
                                             float (*d)[4],
                                             int wr, int wc, int g, int t4)
{
    #pragma unroll
    for (int i = 0; i < 8; i++)
        d[i][0] = d[i][1] = d[i][2] = d[i][3] = 0.f;
    const float* a0p = act + (wr * 32 + g) * ASTRP + t4 * 2;
    const float* b0p = sW + (wc * 32 + g) * ASTRP + t4 * 2;
    #pragma unroll 4
    for (int c = 0; c < 16; c++) {
        uint32_t A[2][4];
        #pragma unroll
        for (int rb = 0; rb < 2; rb++) {
            const float* ap = a0p + rb * 16 * ASTRP + c * 8;
            float2 lo = *(const float2*)(ap);
            float2 hi = *(const float2*)(ap + 8 * ASTRP);
            A[rb][0] = __float_as_uint(lo.x);
            A[rb][1] = __float_as_uint(hi.x);
            A[rb][2] = __float_as_uint(lo.y);
            A[rb][3] = __float_as_uint(hi.y);
        }
        #pragma unroll
        for (int nt = 0; nt < 4; nt++) {
            float2 b = *(const float2*)(b0p + nt * 8 * ASTRP + c * 8);
            uint32_t b0 = __float_as_uint(b.x);
            uint32_t b1 = __float_as_uint(b.y);
            mma8(d[nt],     A[0], b0, b1);
            mma8(d[4 + nt], A[1], b0, b1);
        }
    }
}

__device__ __forceinline__ void layer_input(const float* __restrict__ sWin,
                                            const float* __restrict__ feat,
                                            float (*d)[4],
                                            int wr, int wc, int g, int t4)
{
    #pragma unroll
    for (int i = 0; i < 8; i++)
        d[i][0] = d[i][1] = d[i][2] = d[i][3] = 0.f;
    const float* a0p = feat + (wr * 32 + g) * FSTR + t4;
    const float* b0p = sWin + (wc * 32 + g) * WSTR + t4;
    #pragma unroll
    for (int c = 0; c < 2; c++) {
        uint32_t A[2][4];
        #pragma unroll
        for (int rb = 0; rb < 2; rb++) {
            const float* ap = a0p + rb * 16 * FSTR + c * 8;
            A[rb][0] = __float_as_uint(ap[0]);
            A[rb][1] = __float_as_uint(ap[8 * FSTR]);
            A[rb][2] = __float_as_uint(ap[4]);
            A[rb][3] = __float_as_uint(ap[8 * FSTR + 4]);
        }
        #pragma unroll
        for (int nt = 0; nt < 4; nt++) {
            const float* bp = b0p + nt * 8 * WSTR + c * 8;
            uint32_t b0 = __float_as_uint(bp[0]);
            uint32_t b1 = __float_as_uint(bp[4]);
            mma8(d[nt],     A[0], b0, b1);
            mma8(d[4 + nt], A[1], b0, b1);
        }
    }
}

// relu(d + bias) -> tf32 -> act (k-pair packed layout)
__device__ __forceinline__ void writeback(float (*d)[4], float* __restrict__ act,
                                          const float* __restrict__ sm0, int bias_h,
                                          int wr, int wc, int g, int t4)
{
    const int p0 = ((2 * t4) & 3) * 2 + (t4 >> 1);   // [0,4,1,5][t4]
    #pragma unroll
    for (int rb = 0; rb < 2; rb++) {
        const int r = wr * 32 + rb * 16 + g;
        #pragma unroll
        for (int nt = 0; nt < 4; nt++) {
            const int col = wc * 32 + nt * 8 + t4 * 2;
            float2 bb = *(const float2*)(sm0 + HOLE(bias_h + col));
            float* p = act + r * ASTRP + wc * 32 + nt * 8;
            const float* dd = d[rb * 4 + nt];
            p[p0]     = tf32f(fmaxf(dd[0] + bb.x, 0.f));
            p[p0 + 2] = tf32f(fmaxf(dd[1] + bb.y, 0.f));
            p[8 * ASTRP + p0]     = tf32f(fmaxf(dd[2] + bb.x, 0.f));
            p[8 * ASTRP + p0 + 2] = tf32f(fmaxf(dd[3] + bb.y, 0.f));
        }
    }
}

// ------------------------------- fused kernel ------------------------------

extern "C" __global__ void __launch_bounds__(NT, 1)
ffp_fused(const float* __restrict__ init_x,  const float* __restrict__ query_x,
          const float* __restrict__ init_v,  const float* __restrict__ query_v,
          const float* __restrict__ init_av, const float* __restrict__ query_av,
          const float* __restrict__ trunk_w0, const float* __restrict__ trunk_b0,
          const float* __restrict__ trunk_ws, const float* __restrict__ trunk_bs,
          const float* __restrict__ branch_w0, const float* __restrict__ branch_b0,
          const float* __restrict__ branch_ws, const float* __restrict__ branch_bs,
          const float* __restrict__ out_w,   const float* __restrict__ out_b,
          const float* __restrict__ spring_w0, const float* __restrict__ spring_b0,
          const float* __restrict__ spring_w1, const float* __restrict__ spring_b1,
          const float* __restrict__ joint_w0, const float* __restrict__ joint_b0,
          const float* __restrict__ joint_w1, const float* __restrict__ joint_b1,
          float* __restrict__ out)
{
    extern __shared__ float sm[];
    const int tid = threadIdx.x;

    // ================= Phase 1: branch MLP (CTAs 0..63, fp32) ==============
    if (blockIdx.x < 64) {
        float* sW   = sm + BR_W;
        float* act0 = sm + BR_A0;
        float* act1 = sm + BR_A1;
        float* feat = sm + BR_F;
        const int ty = (tid & 255) >> 4, tx = tid & 15;
        const bool w = (tid < 256);
        const int b = blockIdx.x;

        if (w) stage_copy(sW, branch_w0 + 2 * 128, 384, tid);
        if (tid < 64) {
            const float* ix = init_x + (b * 64 + tid) * 9;
            feat[tid * 4 + 0] = ix[2];
            feat[tid * 4 + 1] = ix[3];
            feat[tid * 4 + 2] = ix[4];
        }
        __syncthreads();
        if (w) gemm_input_f32(feat, 4, 3, act0, sW, branch_b0, ty, tx);
        __syncthreads();
        if (w) stage_copy(sW, branch_ws, 16384, tid);
        __syncthreads();
        if (w) gemm_hidden_f2(act0, act1, sW, branch_bs, ty, tx, true);
        __syncthreads();
        if (w) stage_copy(sW, branch_ws + 16384, 16384, tid);
        __syncthreads();
        if (w) gemm_hidden_f2(act1, act0, sW, branch_bs + 128, ty, tx, true);
        __syncthreads();
        for (int idx = tid; idx < 64 * 384; idx += NT) {
            int o = idx / 384;
            int r = idx - o * 384;
            int k = r / 3;
            int j = r - k * 3;
            g_branchM[(b * 64 + o) * 384 + r] = act0[o * PADR + k] * out_w[k * 3 + j];
        }
        __syncthreads();
    }

    // ---- weight staging for phase 2 (all CTAs; overwrites branch bufs) ----
    __syncthreads();
    for (int i = tid * 4; i < 4608; i += NT * 4)
        *(float4*)(sm + S_INW + i) = make_float4(0.f, 0.f, 0.f, 0.f);
    __syncthreads();
    for (int idx = tid; idx < 16384; idx += NT) {
        int k = idx >> 7, n = idx & 127;
        int off = n * ASTRP + (k >> 3) * 8 + (k & 3) * 2 + ((k >> 2) & 1);
        sm[S_W1 + off] = tf32f(trunk_ws[idx]);
        sm[S_W2 + off] = tf32f(trunk_ws[16384 + idx]);
    }
    for (int idx = tid; idx < 9 * 128; idx += NT) {
        int k = idx >> 7, n = idx & 127;
        sm[S_INW + n * WSTR + k] = tf32f(trunk_w0[idx]);
    }
    for (int idx = tid; idx < 15 * 128; idx += NT) {
        int k = idx >> 7, n = idx & 127;
        sm[S_INW + n * WSTR + 16 + k] = tf32f(joint_w0[idx]);
    }
    for (int i = tid; i < 128; i += NT) {
        sm[HOLE(HB0 + i)] = trunk_b0[i];
        sm[HOLE(HB1 + i)] = trunk_bs[i];
        sm[HOLE(HB2 + i)] = trunk_bs[128 + i];
        sm[HOLE(HJB + i)] = joint_b0[i];
    }
    if (tid < 256) sm[HOLE(HJW1 + tid)] = joint_w1[(tid & 127) * 2 + (tid >> 7)];

    // ---- global ticket barrier (replay-safe: monotonic epochs) ----
    __threadfence();
    __syncthreads();
    if (tid == 0) {
        unsigned int grid = gridDim.x;
        unsigned int ticket = atomicAdd(&g_bar, 1u);
        unsigned int target = (ticket / grid + 1u) * grid;
        while (atomicAdd(&g_bar, 0u) < target) { __nanosleep(64); }
    }
    __syncthreads();
    __threadfence();

    // ================= Phase 2: persistent tf32 MLP loop ====================
    const int gid = tid >> 8;                 // worker group 0/1
    const int tg  = tid & 255;
    const int wid_g = tg >> 5, lane = tid & 31;
    const int wr = wid_g & 1, wc = wid_g >> 1;
    const int g = lane >> 2, t4 = lane & 3;
    const int barid = 1 + gid;

    float* actg  = sm + S_ACT + gid * GSLICE;
    float* featT = actg;                       // aliases act
    float* featJ = actg + 1280;
    float* scr   = actg;                       // aliases act (dead in epilogue)
    const int hmsh = HMSH + gid * 384;

    for (int pp = blockIdx.x; pp < 2048; pp += gridDim.x) {
        const int bo = (pp << 1) + gid;
        const int b = bo >> 6;

        // stage msh into weight-row holes
        for (int d0 = tg; d0 < 384; d0 += 256) {
            int part = d0 >> 7, k = d0 & 127;
            sm[HOLE(hmsh + d0)] = g_branchM[bo * 384 + k * 3 + part];
        }

        // ---- features (tg<64), masks in registers ----
        float relx = 0.f, rely = 0.f, maskD = 0.f, maskJ = 0.f, maskS = 0.f;
        if (tg < 64) {
            const int t = tg;
            const float* ix = init_x + bo * 9;
            const float* qx = query_x + (b * 64 + t) * 9;
            float i2 = ix[2], i3 = ix[3], i4 = ix[4], i7 = ix[7], i8 = ix[8];
            float q2 = qx[2], q3 = qx[3], q4 = qx[4], q7 = qx[7], q8 = qx[8];
            relx = qx[0] - ix[0]; rely = qx[1] - ix[1];
            float qvx = query_v[(b * 64 + t) * 2 + 0] - init_v[bo * 2 + 0];
            float qvy = query_v[(b * 64 + t) * 2 + 1] - init_v[bo * 2 + 1];
            float iav = init_av[bo];
            float qav = query_av[b * 64 + t] - iav;

            float sn1, cs1; sincosf(i3 * 100.f, &sn1, &cs1);
            float sn2, cs2; sincosf(q3 * 100.f, &sn2, &cs2);
            float o1x = i2 * 0.5f * cs1, o1y = i2 * 0.5f * sn1;
            float o2x = q2 * 0.5f * cs2, o2y = q2 * 0.5f * sn2;
            float ab1x = 2.f * o1x, ab1y = 2.f * o1y;
            float ab2x = 2.f * o2x, ab2y = 2.f * o2y;
            float ss1 = ab1x * ab1x + ab1y * ab1y + 1e-8f;
            float ss2 = ab2x * ab2x + ab2y * ab2y + 1e-8f;
            float A2x = relx - o2x, A2y = rely - o2y;
            float B2x = relx + o2x, B2y = rely + o2y;
            float d1 = segdist(A2x, A2y, -o1x, -o1y, ab1x, ab1y, ss1);
            float d2 = segdist(B2x, B2y, -o1x, -o1y, ab1x, ab1y, ss1);
            float d3 = segdist(-o1x, -o1y, A2x, A2y, ab2x, ab2y, ss2);
            float d4 = segdist(o1x, o1y, A2x, A2y, ab2x, ab2y, ss2);
            float dist = fminf(fminf(d1, d2), fminf(d3, d4)) - i4 - q4;
            maskD = (dist <= 0.f) ? 1.f : 0.f;
            float ti = truncf(i7), tq = truncf(q7);
            maskJ = (ti == tq && i7 > 0.f) ? 1.f : 0.f;
            maskS = (i8 == q8 && i8 > 0.f) ? 1.f : 0.f;

            uint32_t ft[16], fj[16];
            ft[0] = f2tf32(relx); ft[1] = f2tf32(rely);
            ft[2] = f2tf32(q2);   ft[3] = f2tf32(q3);  ft[4] = f2tf32(q4);
            ft[5] = f2tf32(qvx);  ft[6] = f2tf32(qvy); ft[7] = f2tf32(qav);
            ft[8] = f2tf32(dist * maskD * 100.f);
            #pragma unroll
            for (int j = 9; j < 16; j++) ft[j] = 0u;
            fj[0] = 0u; fj[1] = 0u;
            fj[2] = f2tf32(i2);  fj[3] = f2tf32(i3);  fj[4] = f2tf32(i4);
            fj[5] = ft[0]; fj[6] = ft[1];
            fj[7] = ft[2]; fj[8] = ft[3]; fj[9] = ft[4];
            fj[10] = ft[5]; fj[11] = ft[6];
            fj[12] = f2tf32(iav); fj[13] = ft[7];
            fj[14] = f2tf32(i7 - ti); fj[15] = 0u;
            #pragma unroll
            for (int j = 0; j < 4; j++) {
                *(float4*)(featT + t * FSTR + j * 4) = *(float4*)(ft + j * 4);
                *(float4*)(featJ + t * FSTR + j * 4) = *(float4*)(fj + j * 4);
            }
        }
        BARG(barid);   // (1) features + msh ready

        float d[8][4];
        float pj[4][2];

        // ---- joint L0 -> pj (registers) ----
        {
            layer_input(sm + S_INW + 16, featJ, d, wr, wc, g, t4);
            #pragma unroll
            for (int q = 0; q < 4; q++) pj[q][0] = pj[q][1] = 0.f;
            #pragma unroll
            for (int rb = 0; rb < 2; rb++)
            #pragma unroll
            for (int nt = 0; nt < 4; nt++) {
                const int col = wc * 32 + nt * 8 + 2 * t4;
                float2 jb  = *(const float2*)(sm + HOLE(HJB + col));
                float2 w0v = *(const float2*)(sm + HOLE(HJW1 + col));
                float2 w1v = *(const float2*)(sm + HOLE(HJW1 + 128 + col));
                const float* dd = d[rb * 4 + nt];
                float h0 = fmaxf(dd[0] + jb.x, 0.f), h1 = fmaxf(dd[1] + jb.y, 0.f);
                float h2 = fmaxf(dd[2] + jb.x, 0.f), h3 = fmaxf(dd[3] + jb.y, 0.f);
                pj[rb * 2][0]     += h0 * w0v.x + h1 * w0v.y;
                pj[rb * 2][1]     += h0 * w1v.x + h1 * w1v.y;
                pj[rb * 2 + 1][0] += h2 * w0v.x + h3 * w0v.y;
                pj[rb * 2 + 1][1] += h2 * w1v.x + h3 * w1v.y;
            }
        }

        // ---- trunk L0 ----
        layer_input(sm + S_INW, featT, d, wr, wc, g, t4);
        BARG(barid);   // (2) feat reads done
        writeback(d, actg, sm, HB0, wr, wc, g, t4);
        BARG(barid);   // (3)

        // ---- trunk H1 ----
        layer_hidden(sm + S_W1, actg, d, wr, wc, g, t4);
        BARG(barid);   // (4)
        writeback(d, actg, sm, HB1, wr, wc, g, t4);
        BARG(barid);   // (5)

        // ---- trunk H2 (fragments consumed directly) ----
        layer_hidden(sm + S_W2, actg, d, wr, wc, g, t4);
        float p[4][3];
        {
            #pragma unroll
            for (int q = 0; q < 4; q++) p[q][0] = p[q][1] = p[q][2] = 0.f;
            #pragma unroll
            for (int rb = 0; rb < 2; rb++)
            #pragma unroll
            for (int nt = 0; nt < 4; nt++) {
                const int col = wc * 32 + nt * 8 + 2 * t4;
                float2 bb = *(const float2*)(sm + HOLE(HB2 + col));
                float2 m0 = *(const float2*)(sm + HOLE(hmsh + col));
                float2 m1 = *(const float2*)(sm + HOLE(hmsh + 128 + col));
                float2 m2 = *(const float2*)(sm + HOLE(hmsh + 256 + col));
                const float* dd = d[rb * 4 + nt];
                float h0 = dd[0] + bb.x, h1 = dd[1] + bb.y;
                float h2 = dd[2] + bb.x, h3 = dd[3] + bb.y;
                p[rb * 2][0]     += h0 * m0.x + h1 * m0.y;
                p[rb * 2][1]     += h0 * m1.x + h1 * m1.y;
                p[rb * 2][2]     += h0 * m2.x + h1 * m2.y;
                p[rb * 2 + 1][0] += h2 * m0.x + h3 * m0.y;
                p[rb * 2 + 1][1] += h2 * m1.x + h3 * m1.y;
                p[rb * 2 + 1][2] += h2 * m2.x + h3 * m2.y;
            }
        }
        BARG(barid);   // (6) act reads done; scr writable

        #pragma unroll
        for (int q = 0; q < 4; q++) {
            const int row = wr * 32 + (q >> 1) * 16 + g + (q & 1) * 8;
            #pragma unroll
            for (int j = 0; j < 3; j++) {
                float v = p[q][j];
                v += __shfl_xor_sync(0xffffffffu, v, 1);
                v += __shfl_xor_sync(0xffffffffu, v, 2);
                if (t4 == 0) scr[row * FSTR + wc * 5 + j] = v;
            }
            #pragma unroll
            for (int j = 0; j < 2; j++) {
                float v = pj[q][j];
                v += __shfl_xor_sync(0xffffffffu, v, 1);
                v += __shfl_xor_sync(0xffffffffu, v, 2);
                if (t4 == 0) scr[row * FSTR + wc * 5 + 3 + j] = v;
            }
        }
        BARG(barid);   // (7) scr complete

        // ---- combine + masks + spring + store ----
        if (tg < 64) {
            const int t = tg;
            const float* s = scr + t * FSTR;
            float f0 = (s[0] + s[5] + s[10] + s[15] + out_b[0]) * maskD;
            float f1 = (s[1] + s[6] + s[11] + s[16] + out_b[1]) * maskD;
            float f2 = (s[2] + s[7] + s[12] + s[17] + out_b[2]) * maskD;
            if (maskJ > 0.f) {
                f0 += s[3] + s[8] + s[13] + s[18] + joint_b1[0];
                f1 += s[4] + s[9] + s[14] + s[19] + joint_b1[1];
            }
            if (maskS > 0.f) {
                float len = sqrtf(relx * relx + rely * rely);
                float sf = spring_b1[0];
                for (int k = 0; k < 128; k++)
                    sf = fmaf(fmaxf(fmaf(len, spring_w0[k], spring_b0[k]), 0.f),
                              spring_w1[k], sf);
                float inv = 1.f / (len + 1e-8f);
                f0 = fmaf(sf, -relx * inv, f0);
                f1 = fmaf(sf, -rely * inv, f1);
            }
            float* op = out + (bo * 64 + t) * 3;
            op[0] = f0; op[1] = f1; op[2] = f2;
        }
        // no trailing barrier (scr row t read + featT row t write = same thread;
        // msh holes: this iter's reads all precede bar(6) -> next writes safe)
    }
}

// ---------------------------------------------------------------------------

extern "C" void kernel_launch(void* const* d_in, const int* in_sizes, int n_in,
                              void* d_out, int out_size)
{
    const float* init_x    = (const float*)d_in[0];
    const float* query_x   = (const float*)d_in[1];
    const float* init_v    = (const float*)d_in[2];
    const float* query_v   = (const float*)d_in[3];
    const float* init_av   = (const float*)d_in[4];
    const float* query_av  = (const float*)d_in[5];
    const float* trunk_w0  = (const float*)d_in[6];
    const float* trunk_b0  = (const float*)d_in[7];
    const float* trunk_ws  = (const float*)d_in[8];
    const float* trunk_bs  = (const float*)d_in[9];
    const float* branch_w0 = (const float*)d_in[10];
    const float* branch_b0 = (const float*)d_in[11];
    const float* branch_ws = (const float*)d_in[12];
    const float* branch_bs = (const float*)d_in[13];
    const float* out_w     = (const float*)d_in[14];
    const float* out_b     = (const float*)d_in[15];
    const float* spring_w0 = (const float*)d_in[16];
    const float* spring_b0 = (const float*)d_in[17];
    const float* spring_w1 = (const float*)d_in[18];
    const float* spring_b1 = (const float*)d_in[19];
    const float* joint_w0  = (const float*)d_in[20];
    const float* joint_b0  = (const float*)d_in[21];
    const float* joint_w1  = (const float*)d_in[22];
    const float* joint_b1  = (const float*)d_in[23];
    float* out = (float*)d_out;

    int nsm = 148;
    cudaDeviceGetAttribute(&nsm, cudaDevAttrMultiProcessorCount, 0);

    const int smem = S_TOTAL * sizeof(float);
    cudaFuncSetAttribute(ffp_fused, cudaFuncAttributeMaxDynamicSharedMemorySize, smem);

    ffp_fused<<<nsm, NT, smem>>>(init_x, query_x, init_v, query_v, init_av, query_av,
                                 trunk_w0, trunk_b0, trunk_ws, trunk_bs,
                                 branch_w0, branch_b0, branch_ws, branch_bs,
                                 out_w, out_b,
                                 spring_w0, spring_b0, spring_w1, spring_b1,
                                 joint_w0, joint_b0, joint_w1, joint_b1,
                                 out);
}

// round 10
// speedup vs baseline: 2.0125x; 1.8703x over previous
#include <cuda_runtime.h>
#include <math.h>
#include <stdint.h>

// ===========================================================================
// ForceFieldPredictor R10: mask-compacted tf32 pipeline, single fused kernel.
//   Phase 0 (CTAs 0..31): branch MLP via tf32 mma -> g_branchM (planar).
//   Phase A (all CTAs):   row scan -> masks -> compacted trunk/joint lists
//                         (warp-ballot, order-preserving); spring inline.
//   Global ticket barrier.
//   Phase B: gathered 64-row tiles (trunk: L0+H1+H2+epilogue; joint: L0+dot)
//            with atomicAdd merge into zero-initialized out.
// ===========================================================================

typedef unsigned long long ull;

__device__ float g_branchM[4096 * 384];   // planar: [bo][part*128 + k]
__device__ unsigned int g_bar;            // ticket barrier (monotonic)
__device__ int g_cnt[2];                  // {trunkCnt, jointCnt} (memset per launch)
__device__ int g_trunkList[262144];
__device__ int g_jointList[262144];

// ---------------------------- small PTX helpers ----------------------------

__device__ __forceinline__ uint32_t f2tf32(float x) {
    uint32_t r; asm("cvt.rna.tf32.f32 %0, %1;" : "=r"(r) : "f"(x)); return r;
}
__device__ __forceinline__ float tf32f(float x) { return __uint_as_float(f2tf32(x)); }

__device__ __forceinline__ void mma8(float* d, const uint32_t* a, uint32_t b0, uint32_t b1) {
    asm volatile("mma.sync.aligned.m16n8k8.row.col.f32.tf32.tf32.f32 "
                 "{%0,%1,%2,%3}, {%4,%5,%6,%7}, {%8,%9}, {%0,%1,%2,%3};"
                 : "+f"(d[0]), "+f"(d[1]), "+f"(d[2]), "+f"(d[3])
                 : "r"(a[0]), "r"(a[1]), "r"(a[2]), "r"(a[3]), "r"(b0), "r"(b1));
}

#define BARG(id) asm volatile("bar.sync %0, %1;" :: "r"(id), "r"(256) : "memory")

// ---------------------------- smem layout (floats) -------------------------
#define S_W1    0                 // 16384 : hidden W1 (tf32, swizzled [n][k])
#define S_W2    16384             // 16384 : hidden W2
#define S_ACT   32768             // 2 x 8448 (64 rows x 132) group act slices
#define S_W0T   49664             // 2304 : input W0t [n][k], stride 18
#define S_JW0T  51968             // 2304 : joint W0t
#define S_B0    54272
#define S_B1    54400
#define S_B2    54528
#define S_JB0   54656
#define S_JW1   54784             // 256 : [part][128]
#define S_OUTW  55040             // 384 : out_w planar [part*128+k]
#define S_TROW  55424             // 128 : 2 groups x 64 rowids (int)
#define S_TBO   55552             // 128 : 2 groups x 64 bo     (int)
#define S_TOTAL 55680             // 222,720 B

#define ASTR 132
#define FSTR 20
#define WSTR 18
#define NT   512
#define GSLICE 8448

// ----------------------- tf32 MMA layer helpers (R8-proven) ----------------
// group = 256 threads; warp (wr in 0..1, wc in 0..3): 32 rows x 32 cols.

template<int C>
__device__ __forceinline__ void layer_input(const float* __restrict__ sWin,
                                            const float* __restrict__ feat,
                                            float (*d)[4],
                                            int wr, int wc, int g, int t4)
{
    #pragma unroll
    for (int i = 0; i < 8; i++)
        d[i][0] = d[i][1] = d[i][2] = d[i][3] = 0.f;
    const float* a0p = feat + (wr * 32 + g) * FSTR + t4;
    const float* b0p = sWin + (wc * 32 + g) * WSTR + t4;
    #pragma unroll
    for (int c = 0; c < C; c++) {
        uint32_t A[2][4];
        #pragma unroll
        for (int rb = 0; rb < 2; rb++) {
            const float* ap = a0p + rb * 16 * FSTR + c * 8;
            A[rb][0] = __float_as_uint(ap[0]);
            A[rb][1] = __float_as_uint(ap[8 * FSTR]);
            A[rb][2] = __float_as_uint(ap[4]);
            A[rb][3] = __float_as_uint(ap[8 * FSTR + 4]);
        }
        #pragma unroll
        for (int nt = 0; nt < 4; nt++) {
            const float* bp = b0p + nt * 8 * WSTR + c * 8;
            uint32_t b0 = __float_as_uint(bp[0]);
            uint32_t b1 = __float_as_uint(bp[4]);
            mma8(d[nt],     A[0], b0, b1);
            mma8(d[4 + nt], A[1], b0, b1);
        }
    }
}

__device__ __forceinline__ void layer_hidden(const float* __restrict__ sW,
                                             const float* __restrict__ act,
                                             float (*d)[4],
                                             int wr, int wc, int g, int t4)
{
    #pragma unroll
    for (int i = 0; i < 8; i++)
        d[i][0] = d[i][1] = d[i][2] = d[i][3] = 0.f;
    const float* a0p = act + (wr * 32 + g) * ASTR + t4;
    const float* b0p = sW + (wc * 32 + g) * 128 + t4;
    #pragma unroll 4
    for (int c = 0; c < 16; c++) {
        uint32_t A[2][4];
        #pragma unroll
        for (int rb = 0; rb < 2; rb++) {
            const float* ap = a0p + rb * 16 * ASTR + c * 8;
            A[rb][0] = __float_as_uint(ap[0]);
            A[rb][1] = __float_as_uint(ap[8 * ASTR]);
            A[rb][2] = __float_as_uint(ap[4]);
            A[rb][3] = __float_as_uint(ap[8 * ASTR + 4]);
        }
        const int w0 = ((2 * c) ^ g) << 2;
        const int w1 = ((2 * c + 1) ^ g) << 2;
        #pragma unroll
        for (int nt = 0; nt < 4; nt++) {
            const float* bp = b0p + nt * 8 * 128;
            uint32_t b0 = __float_as_uint(bp[w0]);
            uint32_t b1 = __float_as_uint(bp[w1]);
            mma8(d[nt],     A[0], b0, b1);
            mma8(d[4 + nt], A[1], b0, b1);
        }
    }
}

__device__ __forceinline__ void writeback(float (*d)[4], float* __restrict__ act,
                                          const float* __restrict__ bias,
                                          int wr, int wc, int g, int t4)
{
    #pragma unroll
    for (int rb = 0; rb < 2; rb++) {
        const int r = wr * 32 + rb * 16 + g;
        #pragma unroll
        for (int nt = 0; nt < 4; nt++) {
            const int col = wc * 32 + nt * 8 + t4 * 2;
            float2 bb = *(const float2*)(bias + col);
            float* p = act + r * ASTR + col;
            const float* dd = d[rb * 4 + nt];
            p[0] = tf32f(fmaxf(dd[0] + bb.x, 0.f));
            p[1] = tf32f(fmaxf(dd[1] + bb.y, 0.f));
            p[8 * ASTR]     = tf32f(fmaxf(dd[2] + bb.x, 0.f));
            p[8 * ASTR + 1] = tf32f(fmaxf(dd[3] + bb.y, 0.f));
        }
    }
}

// --------------------------- row feature computation -----------------------

__device__ __forceinline__ float segdist(float px, float py, float ax, float ay,
                                         float abx, float aby, float s)
{
    float t = ((px - ax) * abx + (py - ay) * aby) / s;
    t = fminf(fmaxf(t, 0.f), 1.f);
    float dx = px - (ax + t * abx);
    float dy = py - (ay + t * aby);
    return sqrtf(dx * dx + dy * dy);
}

struct RowF {
    float relx, rely, dist, maskD, maskJ, maskS;
    float i2, i3, i4, iav, i7f;
    float q2, q3, q4, qvx, qvy, qav;
};

__device__ __forceinline__ RowF rowCalc(int rowid,
    const float* __restrict__ init_x,  const float* __restrict__ query_x,
    const float* __restrict__ init_v,  const float* __restrict__ query_v,
    const float* __restrict__ init_av, const float* __restrict__ query_av)
{
    RowF f;
    const int bo = rowid >> 6, t = rowid & 63, b = rowid >> 12;
    const float* ix = init_x + bo * 9;
    const float* qx = query_x + (b * 64 + t) * 9;
    float i2 = ix[2], i3 = ix[3], i4 = ix[4], i7 = ix[7], i8 = ix[8];
    float q2 = qx[2], q3 = qx[3], q4 = qx[4], q7 = qx[7], q8 = qx[8];
    f.relx = qx[0] - ix[0]; f.rely = qx[1] - ix[1];
    f.qvx = query_v[(b * 64 + t) * 2 + 0] - init_v[bo * 2 + 0];
    f.qvy = query_v[(b * 64 + t) * 2 + 1] - init_v[bo * 2 + 1];
    f.iav = init_av[bo];
    f.qav = query_av[b * 64 + t] - f.iav;

    float sn1, cs1; sincosf(i3 * 100.f, &sn1, &cs1);
    float sn2, cs2; sincosf(q3 * 100.f, &sn2, &cs2);
    float o1x = i2 * 0.5f * cs1, o1y = i2 * 0.5f * sn1;
    float o2x = q2 * 0.5f * cs2, o2y = q2 * 0.5f * sn2;
    float ab1x = 2.f * o1x, ab1y = 2.f * o1y;
    float ab2x = 2.f * o2x, ab2y = 2.f * o2y;
    float ss1 = ab1x * ab1x + ab1y * ab1y + 1e-8f;
    float ss2 = ab2x * ab2x + ab2y * ab2y + 1e-8f;
    float A2x = f.relx - o2x, A2y = f.rely - o2y;
    float B2x = f.relx + o2x, B2y = f.rely + o2y;
    float d1 = segdist(A2x, A2y, -o1x, -o1y, ab1x, ab1y, ss1);
    float d2 = segdist(B2x, B2y, -o1x, -o1y, ab1x, ab1y, ss1);
    float d3 = segdist(-o1x, -o1y, A2x, A2y, ab2x, ab2y, ss2);
    float d4 = segdist(o1x, o1y, A2x, A2y, ab2x, ab2y, ss2);
    f.dist = fminf(fminf(d1, d2), fminf(d3, d4)) - i4 - q4;
    f.maskD = (f.dist <= 0.f) ? 1.f : 0.f;
    float ti = truncf(i7), tq = truncf(q7);
    f.maskJ = (ti == tq && i7 > 0.f) ? 1.f : 0.f;
    f.maskS = (i8 == q8 && i8 > 0.f) ? 1.f : 0.f;
    f.i2 = i2; f.i3 = i3; f.i4 = i4; f.i7f = i7 - ti;
    f.q2 = q2; f.q3 = q3; f.q4 = q4;
    return f;
}

// ------------------------------- fused kernel ------------------------------

extern "C" __global__ void __launch_bounds__(NT, 1)
ffp_all(const float* __restrict__ init_x,  const float* __restrict__ query_x,
        const float* __restrict__ init_v,  const float* __restrict__ query_v,
        const float* __restrict__ init_av, const float* __restrict__ query_av,
        const float* __restrict__ trunk_w0, const float* __restrict__ trunk_b0,
        const float* __restrict__ trunk_ws, const float* __restrict__ trunk_bs,
        const float* __restrict__ branch_w0, const float* __restrict__ branch_b0,
        const float* __restrict__ branch_ws, const float* __restrict__ branch_bs,
        const float* __restrict__ out_w,   const float* __restrict__ out_b,
        const float* __restrict__ spring_w0, const float* __restrict__ spring_b0,
        const float* __restrict__ spring_w1, const float* __restrict__ spring_b1,
        const float* __restrict__ joint_w0, const float* __restrict__ joint_b0,
        const float* __restrict__ joint_w1, const float* __restrict__ joint_b1,
        float* __restrict__ out)
{
    extern __shared__ float sm[];
    const int tid = threadIdx.x;
    const int gid = tid >> 8, tg = tid & 255;
    const int wid_g = tg >> 5, lane = tid & 31;
    const int wr = wid_g & 1, wc = wid_g >> 1;
    const int g = lane >> 2, t4 = lane & 3;
    const int barid = 1 + gid;

    float* actg  = sm + S_ACT + gid * GSLICE;
    float* featg = actg;                       // aliases act (released at L0 wb)
    int* tRow = (int*)(sm + S_TROW) + gid * 64;
    int* tBo  = (int*)(sm + S_TBO)  + gid * 64;

    // ================= Phase 0: branch MLP via tf32 (CTAs 0..31) ===========
    if (blockIdx.x < 32) {
        for (int i = tid * 4; i < 2304; i += NT * 4)
            *(float4*)(sm + S_W0T + i) = make_float4(0.f, 0.f, 0.f, 0.f);
        __syncthreads();
        for (int idx = tid; idx < 16384; idx += NT) {
            int k = idx >> 7, n = idx & 127;
            int off = n * 128 + (((k >> 2) ^ (n & 7)) << 2) + (k & 3);
            sm[S_W1 + off] = tf32f(branch_ws[idx]);
            sm[S_W2 + off] = tf32f(branch_ws[16384 + idx]);
        }
        for (int idx = tid; idx < 3 * 128; idx += NT) {
            int k = idx >> 7, n = idx & 127;
            sm[S_W0T + n * WSTR + k] = tf32f(branch_w0[(2 + k) * 128 + n]);
        }
        for (int i = tid; i < 128; i += NT) {
            sm[S_B0 + i] = branch_b0[i];
            sm[S_B1 + i] = branch_bs[i];
            sm[S_B2 + i] = branch_bs[128 + i];
        }
        for (int i = tid; i < 384; i += NT)
            sm[S_OUTW + i] = out_w[(i & 127) * 3 + (i >> 7)];
        __syncthreads();

        // one 64-row branch tile per group (tiles 0..63 over CTAs 0..31)
        {
            const int boBase = (blockIdx.x * 2 + gid) * 64;
            if (tg < 64) {
                const float* ix = init_x + (boBase + tg) * 9;
                float* fr = featg + tg * FSTR;
                fr[0] = tf32f(ix[2]); fr[1] = tf32f(ix[3]); fr[2] = tf32f(ix[4]);
                #pragma unroll
                for (int j = 3; j < 8; j++) fr[j] = 0.f;
            }
            BARG(barid);
            float d[8][4];
            layer_input<1>(sm + S_W0T, featg, d, wr, wc, g, t4);
            BARG(barid);
            writeback(d, actg, sm + S_B0, wr, wc, g, t4);
            BARG(barid);
            layer_hidden(sm + S_W1, actg, d, wr, wc, g, t4);
            BARG(barid);
            writeback(d, actg, sm + S_B1, wr, wc, g, t4);
            BARG(barid);
            layer_hidden(sm + S_W2, actg, d, wr, wc, g, t4);
            // fold: branchM[bo][part*128+col] = (h2+b2) * out_w
            #pragma unroll
            for (int rb = 0; rb < 2; rb++) {
                const int rA = wr * 32 + rb * 16 + g;
                const int rB = rA + 8;
                #pragma unroll
                for (int nt = 0; nt < 4; nt++) {
                    const int col = wc * 32 + nt * 8 + 2 * t4;
                    float2 bb = *(const float2*)(sm + S_B2 + col);
                    const float* dd = d[rb * 4 + nt];
                    float h0 = dd[0] + bb.x, h1 = dd[1] + bb.y;
                    float h2 = dd[2] + bb.x, h3 = dd[3] + bb.y;
                    #pragma unroll
                    for (int part = 0; part < 3; part++) {
                        float2 ow = *(const float2*)(sm + S_OUTW + part * 128 + col);
                        *(float2*)(g_branchM + (boBase + rA) * 384 + part * 128 + col)
                            = make_float2(h0 * ow.x, h1 * ow.y);
                        *(float2*)(g_branchM + (boBase + rB) * 384 + part * 128 + col)
                            = make_float2(h2 * ow.x, h3 * ow.y);
                    }
                }
            }
        }
        __syncthreads();
    }

    // ================= Phase A: row scan -> compacted lists =================
    {
        const int nScan = gridDim.x * NT;
        const int iters = (262144 + nScan - 1) / nScan;
        for (int it = 0; it < iters; it++) {
            const int rid = it * nScan + blockIdx.x * NT + tid;
            const bool av = (rid < 262144);
            float maskD = 0.f, maskJ = 0.f, maskS = 0.f, relx = 0.f, rely = 0.f;
            if (av) {
                RowF f = rowCalc(rid, init_x, query_x, init_v, query_v, init_av, query_av);
                maskD = f.maskD; maskJ = f.maskJ; maskS = f.maskS;
                relx = f.relx; rely = f.rely;
            }
            unsigned mD = __ballot_sync(0xffffffffu, maskD > 0.f);
            if (mD) {
                int base = 0;
                if (lane == 0) base = atomicAdd(&g_cnt[0], __popc(mD));
                base = __shfl_sync(0xffffffffu, base, 0);
                if (maskD > 0.f)
                    g_trunkList[base + __popc(mD & ((1u << lane) - 1u))] = rid;
            }
            unsigned mJ = __ballot_sync(0xffffffffu, maskJ > 0.f);
            if (mJ) {
                int base = 0;
                if (lane == 0) base = atomicAdd(&g_cnt[1], __popc(mJ));
                base = __shfl_sync(0xffffffffu, base, 0);
                if (maskJ > 0.f)
                    g_jointList[base + __popc(mJ & ((1u << lane) - 1u))] = rid;
            }
            if (maskS > 0.f) {   // essentially never fires; exact scalar path
                float len = sqrtf(relx * relx + rely * rely);
                float sf = __ldg(spring_b1);
                for (int k = 0; k < 128; k++)
                    sf = fmaf(fmaxf(fmaf(len, __ldg(spring_w0 + k), __ldg(spring_b0 + k)), 0.f),
                              __ldg(spring_w1 + k), sf);
                float inv = 1.f / (len + 1e-8f);
                atomicAdd(out + rid * 3 + 0, sf * (-relx * inv));
                atomicAdd(out + rid * 3 + 1, sf * (-rely * inv));
            }
        }
    }
    __syncthreads();

    // ---- stage trunk/joint weights ----
    for (int i = tid * 4; i < 4608; i += NT * 4)
        *(float4*)(sm + S_W0T + i) = make_float4(0.f, 0.f, 0.f, 0.f);
    __syncthreads();
    for (int idx = tid; idx < 16384; idx += NT) {
        int k = idx >> 7, n = idx & 127;
        int off = n * 128 + (((k >> 2) ^ (n & 7)) << 2) + (k & 3);
        sm[S_W1 + off] = tf32f(trunk_ws[idx]);
        sm[S_W2 + off] = tf32f(trunk_ws[16384 + idx]);
    }
    for (int idx = tid; idx < 9 * 128; idx += NT) {
        int k = idx >> 7, n = idx & 127;
        sm[S_W0T + n * WSTR + k] = tf32f(trunk_w0[idx]);
    }
    for (int idx = tid; idx < 15 * 128; idx += NT) {
        int k = idx >> 7, n = idx & 127;
        sm[S_JW0T + n * WSTR + k] = tf32f(joint_w0[idx]);
    }
    for (int i = tid; i < 128; i += NT) {
        sm[S_B0 + i]  = trunk_b0[i];
        sm[S_B1 + i]  = trunk_bs[i];
        sm[S_B2 + i]  = trunk_bs[128 + i];
        sm[S_JB0 + i] = joint_b0[i];
    }
    if (tid < 256) sm[S_JW1 + tid] = joint_w1[(tid & 127) * 2 + (tid >> 7)];

    // ---- global ticket barrier (replay-safe) ----
    __threadfence();
    __syncthreads();
    if (tid == 0) {
        unsigned int grid = gridDim.x;
        unsigned int ticket = atomicAdd(&g_bar, 1u);
        unsigned int target = (ticket / grid + 1u) * grid;
        while (atomicAdd(&g_bar, 0u) < target) { __nanosleep(64); }
    }
    __syncthreads();
    __threadfence();

    const int nT = *(volatile int*)&g_cnt[0];
    const int nJ = *(volatile int*)&g_cnt[1];
    const int nTT = (nT + 63) >> 6, nJT = (nJ + 63) >> 6;
    const int groupId = blockIdx.x * 2 + gid;
    const int nGroups = gridDim.x * 2;

    // ================= Phase B: gathered tiles ==============================
    for (int ti = groupId; ti < nTT + nJT; ti += nGroups) {
        if (ti < nTT) {
            // ------------------ trunk tile ------------------
            const int base = ti << 6;
            if (tg < 64) {
                const int i = base + tg;
                const int rowid = (i < nT) ? g_trunkList[i] : -1;
                tRow[tg] = rowid;
                tBo[tg]  = (rowid >= 0) ? (rowid >> 6) : 0;
                float* fr = featg + tg * FSTR;
                if (rowid >= 0) {
                    RowF f = rowCalc(rowid, init_x, query_x, init_v, query_v, init_av, query_av);
                    fr[0] = tf32f(f.relx); fr[1] = tf32f(f.rely);
                    fr[2] = tf32f(f.q2);   fr[3] = tf32f(f.q3);  fr[4] = tf32f(f.q4);
                    fr[5] = tf32f(f.qvx);  fr[6] = tf32f(f.qvy); fr[7] = tf32f(f.qav);
                    fr[8] = tf32f(f.dist * 100.f);
                    #pragma unroll
                    for (int j = 9; j < 16; j++) fr[j] = 0.f;
                } else {
                    #pragma unroll
                    for (int j = 0; j < 16; j++) fr[j] = 0.f;
                }
            }
            BARG(barid);
            float d[8][4];
            layer_input<2>(sm + S_W0T, featg, d, wr, wc, g, t4);
            BARG(barid);
            writeback(d, actg, sm + S_B0, wr, wc, g, t4);
            BARG(barid);
            layer_hidden(sm + S_W1, actg, d, wr, wc, g, t4);
            BARG(barid);
            writeback(d, actg, sm + S_B1, wr, wc, g, t4);
            BARG(barid);
            layer_hidden(sm + S_W2, actg, d, wr, wc, g, t4);

            // epilogue: p[q][part] = (h2+b2) . branchM[bo_q]
            int qbo[4], qrid[4];
            #pragma unroll
            for (int q = 0; q < 4; q++) {
                const int row = wr * 32 + (q >> 1) * 16 + g + (q & 1) * 8;
                qbo[q] = tBo[row]; qrid[q] = tRow[row];
            }
            float p[4][3];
            #pragma unroll
            for (int q = 0; q < 4; q++) p[q][0] = p[q][1] = p[q][2] = 0.f;
            #pragma unroll
            for (int rb = 0; rb < 2; rb++)
            #pragma unroll
            for (int nt = 0; nt < 4; nt++) {
                const int col = wc * 32 + nt * 8 + 2 * t4;
                float2 bb = *(const float2*)(sm + S_B2 + col);
                const float* dd = d[rb * 4 + nt];
                float h0 = dd[0] + bb.x, h1 = dd[1] + bb.y;
                float h2 = dd[2] + bb.x, h3 = dd[3] + bb.y;
                const float* mA = g_branchM + qbo[rb * 2] * 384 + col;
                const float* mB = g_branchM + qbo[rb * 2 + 1] * 384 + col;
                #pragma unroll
                for (int part = 0; part < 3; part++) {
                    float2 a = __ldg((const float2*)(mA + part * 128));
                    float2 b = __ldg((const float2*)(mB + part * 128));
                    p[rb * 2][part]     += h0 * a.x + h1 * a.y;
                    p[rb * 2 + 1][part] += h2 * b.x + h3 * b.y;
                }
            }
            #pragma unroll
            for (int q = 0; q < 4; q++)
            #pragma unroll
            for (int part = 0; part < 3; part++) {
                float v = p[q][part];
                v += __shfl_xor_sync(0xffffffffu, v, 1);
                v += __shfl_xor_sync(0xffffffffu, v, 2);
                if (t4 == 0 && qrid[q] >= 0)
                    atomicAdd(out + qrid[q] * 3 + part,
                              v + (wc == 0 ? __ldg(out_b + part) : 0.f));
            }
            BARG(barid);   // all actg/featg reads done before next tile writes
        } else {
            // ------------------ joint tile ------------------
            const int base = (ti - nTT) << 6;
            if (tg < 64) {
                const int i = base + tg;
                const int rowid = (i < nJ) ? g_jointList[i] : -1;
                tRow[tg] = rowid;
                float* fr = featg + tg * FSTR;
                if (rowid >= 0) {
                    RowF f = rowCalc(rowid, init_x, query_x, init_v, query_v, init_av, query_av);
                    fr[0] = 0.f; fr[1] = 0.f;
                    fr[2] = tf32f(f.i2);  fr[3] = tf32f(f.i3);  fr[4] = tf32f(f.i4);
                    fr[5] = tf32f(f.relx); fr[6] = tf32f(f.rely);
                    fr[7] = tf32f(f.q2);  fr[8] = tf32f(f.q3);  fr[9] = tf32f(f.q4);
                    fr[10] = tf32f(f.qvx); fr[11] = tf32f(f.qvy);
                    fr[12] = tf32f(f.iav); fr[13] = tf32f(f.qav);
                    fr[14] = tf32f(f.i7f); fr[15] = 0.f;
                } else {
                    #pragma unroll
                    for (int j = 0; j < 16; j++) fr[j] = 0.f;
                }
            }
            BARG(barid);
            float d[8][4];
            layer_input<2>(sm + S_JW0T, featg, d, wr, wc, g, t4);

            int qrid[4];
            #pragma unroll
            for (int q = 0; q < 4; q++) {
                const int row = wr * 32 + (q >> 1) * 16 + g + (q & 1) * 8;
                qrid[q] = tRow[row];
            }
            float pj[4][2];
            #pragma unroll
            for (int q = 0; q < 4; q++) pj[q][0] = pj[q][1] = 0.f;
            #pragma unroll
            for (int rb = 0; rb < 2; rb++)
            #pragma unroll
            for (int nt = 0; nt < 4; nt++) {
                const int col = wc * 32 + nt * 8 + 2 * t4;
                float2 jb  = *(const float2*)(sm + S_JB0 + col);
                float2 w0v = *(const float2*)(sm + S_JW1 + col);
                float2 w1v = *(const float2*)(sm + S_JW1 + 128 + col);
                const float* dd = d[rb * 4 + nt];
                float h0 = fmaxf(dd[0] + jb.x, 0.f), h1 = fmaxf(dd[1] + jb.y, 0.f);
                float h2 = fmaxf(dd[2] + jb.x, 0.f), h3 = fmaxf(dd[3] + jb.y, 0.f);
                pj[rb * 2][0]     += h0 * w0v.x + h1 * w0v.y;
                pj[rb * 2][1]     += h0 * w1v.x + h1 * w1v.y;
                pj[rb * 2 + 1][0] += h2 * w0v.x + h3 * w0v.y;
                pj[rb * 2 + 1][1] += h2 * w1v.x + h3 * w1v.y;
            }
            #pragma unroll
            for (int q = 0; q < 4; q++)
            #pragma unroll
            for (int part = 0; part < 2; part++) {
                float v = pj[q][part];
                v += __shfl_xor_sync(0xffffffffu, v, 1);
                v += __shfl_xor_sync(0xffffffffu, v, 2);
                if (t4 == 0 && qrid[q] >= 0)
                    atomicAdd(out + qrid[q] * 3 + part,
                              v + (wc == 0 ? __ldg(joint_b1 + part) : 0.f));
            }
            BARG(barid);   // featg reads done before next tile writes
        }
    }
}

// ---------------------------------------------------------------------------

extern "C" void kernel_launch(void* const* d_in, const int* in_sizes, int n_in,
                              void* d_out, int out_size)
{
    const float* init_x    = (const float*)d_in[0];
    const float* query_x   = (const float*)d_in[1];
    const float* init_v    = (const float*)d_in[2];
    const float* query_v   = (const float*)d_in[3];
    const float* init_av   = (const float*)d_in[4];
    const float* query_av  = (const float*)d_in[5];
    const float* trunk_w0  = (const float*)d_in[6];
    const float* trunk_b0  = (const float*)d_in[7];
    const float* trunk_ws  = (const float*)d_in[8];
    const float* trunk_bs  = (const float*)d_in[9];
    const float* branch_w0 = (const float*)d_in[10];
    const float* branch_b0 = (const float*)d_in[11];
    const float* branch_ws = (const float*)d_in[12];
    const float* branch_bs = (const float*)d_in[13];
    const float* out_w     = (const float*)d_in[14];
    const float* out_b     = (const float*)d_in[15];
    const float* spring_w0 = (const float*)d_in[16];
    const float* spring_b0 = (const float*)d_in[17];
    const float* spring_w1 = (const float*)d_in[18];
    const float* spring_b1 = (const float*)d_in[19];
    const float* joint_w0  = (const float*)d_in[20];
    const float* joint_b0  = (const float*)d_in[21];
    const float* joint_w1  = (const float*)d_in[22];
    const float* joint_b1  = (const float*)d_in[23];
    float* out = (float*)d_out;

    int nsm = 148;
    cudaDeviceGetAttribute(&nsm, cudaDevAttrMultiProcessorCount, 0);

    // reset counters + zero output (list/atomic pipeline requires both)
    void* cntPtr = nullptr;
    cudaGetSymbolAddress(&cntPtr, g_cnt);
    cudaMemsetAsync(cntPtr, 0, 2 * sizeof(int));
    cudaMemsetAsync(out, 0, (size_t)out_size * sizeof(float));

    const int smem = S_TOTAL * sizeof(float);
    cudaFuncSetAttribute(ffp_all, cudaFuncAttributeMaxDynamicSharedMemorySize, smem);

    ffp_all<<<nsm, NT, smem>>>(init_x, query_x, init_v, query_v, init_av, query_av,
                               trunk_w0, trunk_b0, trunk_ws, trunk_bs,
                               branch_w0, branch_b0, branch_ws, branch_bs,
                               out_w, out_b,
                               spring_w0, spring_b0, spring_w1, spring_b1,
                               joint_w0, joint_b0, joint_w1, joint_b1,
                               out);
}

// round 11
// speedup vs baseline: 2.0582x; 1.0227x over previous
#include <cuda_runtime.h>
#include <math.h>
#include <stdint.h>

// ===========================================================================
// ForceFieldPredictor R11: barrier-free overlapped pipeline.
//   Phase 0 (CTAs 0..31): branch MLP (tf32 mma) -> g_branchM, signals
//                         branchDone counter (64 group-tiles).
//   Scan: chunk-stolen (ticket) row scan -> masks -> compacted lists AND
//         cached tf32 feature rows (g_tFeat/g_jFeat); spring inline.
//   Phase B: dynamic tile pool (ticket): joint tiles first (need only scan),
//            trunk tiles gated on branchDone. atomicAdd merge into out.
//   layer_hidden: B-fragments pair-packed + chunk-XOR swizzled -> LDS.64.
// ===========================================================================

typedef unsigned long long ull;

__device__ float g_branchM[4096 * 384];     // planar: [bo][part*128 + k]
__device__ int   g_cnt[8];                  // 0:nT 1:nJ 2:tileTick 3:scanTick
                                            // 4:scanDone 5:branchDone (memset)
__device__ int   g_trunkList[262144];
__device__ int   g_jointList[262144];
__device__ float g_tFeat[262144 * 16];
__device__ float g_jFeat[262144 * 16];

// ---------------------------- small PTX helpers ----------------------------

__device__ __forceinline__ uint32_t f2tf32(float x) {
    uint32_t r; asm("cvt.rna.tf32.f32 %0, %1;" : "=r"(r) : "f"(x)); return r;
}
__device__ __forceinline__ float tf32f(float x) { return __uint_as_float(f2tf32(x)); }

__device__ __forceinline__ void mma8(float* d, const uint32_t* a, uint32_t b0, uint32_t b1) {
    asm volatile("mma.sync.aligned.m16n8k8.row.col.f32.tf32.tf32.f32 "
                 "{%0,%1,%2,%3}, {%4,%5,%6,%7}, {%8,%9}, {%0,%1,%2,%3};"
                 : "+f"(d[0]), "+f"(d[1]), "+f"(d[2]), "+f"(d[3])
                 : "r"(a[0]), "r"(a[1]), "r"(a[2]), "r"(a[3]), "r"(b0), "r"(b1));
}

#define BARG(id) asm volatile("bar.sync %0, %1;" :: "r"(id), "r"(256) : "memory")

// ---------------------------- smem layout (floats) -------------------------
#define S_W1    0                 // 16384 : hidden W1 (tf32, pair-packed XOR)
#define S_W2    16384             // 16384 : hidden W2
#define S_ACT   32768             // 2 x 8448 (64 rows x 132) group act slices
#define S_W0T   49664             // 2304 : input W0t [n][k], stride 18
#define S_JW0T  51968             // 2304 : joint W0t
#define S_B0    54272
#define S_B1    54400
#define S_B2    54528
#define S_JB0   54656
#define S_JW1   54784             // 256 : [part][128]
#define S_OUTW  55040             // 384 : out_w planar (phase 0 only)
#define S_TROW  55424             // 128 : 2 groups x 64 rowids (int)
#define S_TBO   55552             // 128 : 2 groups x 64 bo     (int)
#define S_TICK  55680             // 4   : ints {g0 slot, g1 slot, chunk slot}
#define S_TOTAL 55684             // 222,736 B

#define ASTR 132
#define FSTR 20
#define WSTR 18
#define NT   512
#define GSLICE 8448

// pair-packed chunk-XOR weight placement: W[n][k] ->
//   n*128 + ((k>>3) ^ (n&7))*8 + (k&3)*2 + ((k>>2)&1)
__device__ __forceinline__ int wswz(int n, int k) {
    return n * 128 + ((((k >> 3) ^ (n & 7)) << 3) + ((k & 3) << 1) + ((k >> 2) & 1));
}

// ----------------------- tf32 MMA layer helpers ----------------------------
// group = 256 threads; warp (wr in 0..1, wc in 0..3): 32 rows x 32 cols.

template<int C>
__device__ __forceinline__ void layer_input(const float* __restrict__ sWin,
                                            const float* __restrict__ feat,
                                            float (*d)[4],
                                            int wr, int wc, int g, int t4)
{
    #pragma unroll
    for (int i = 0; i < 8; i++)
        d[i][0] = d[i][1] = d[i][2] = d[i][3] = 0.f;
    const float* a0p = feat + (wr * 32 + g) * FSTR + t4;
    const float* b0p = sWin + (wc * 32 + g) * WSTR + t4;
    #pragma unroll
    for (int c = 0; c < C; c++) {
        uint32_t A[2][4];
        #pragma unroll
        for (int rb = 0; rb < 2; rb++) {
            const float* ap = a0p + rb * 16 * FSTR + c * 8;
            A[rb][0] = __float_as_uint(ap[0]);
            A[rb][1] = __float_as_uint(ap[8 * FSTR]);
            A[rb][2] = __float_as_uint(ap[4]);
            A[rb][3] = __float_as_uint(ap[8 * FSTR + 4]);
        }
        #pragma unroll
        for (int nt = 0; nt < 4; nt++) {
            const float* bp = b0p + nt * 8 * WSTR + c * 8;
            uint32_t b0 = __float_as_uint(bp[0]);
            uint32_t b1 = __float_as_uint(bp[4]);
            mma8(d[nt],     A[0], b0, b1);
            mma8(d[4 + nt], A[1], b0, b1);
        }
    }
}

__device__ __forceinline__ void layer_hidden(const float* __restrict__ sW,
                                             const float* __restrict__ act,
                                             float (*d)[4],
                                             int wr, int wc, int g, int t4)
{
    #pragma unroll
    for (int i = 0; i < 8; i++)
        d[i][0] = d[i][1] = d[i][2] = d[i][3] = 0.f;
    const float* a0p = act + (wr * 32 + g) * ASTR + t4;
    const float* b0p = sW + (wc * 32 + g) * 128;
    #pragma unroll 4
    for (int c = 0; c < 16; c++) {
        uint32_t A[2][4];
        #pragma unroll
        for (int rb = 0; rb < 2; rb++) {
            const float* ap = a0p + rb * 16 * ASTR + c * 8;
            A[rb][0] = __float_as_uint(ap[0]);
            A[rb][1] = __float_as_uint(ap[8 * ASTR]);
            A[rb][2] = __float_as_uint(ap[4]);
            A[rb][3] = __float_as_uint(ap[8 * ASTR + 4]);
        }
        const int coff = ((c ^ g) << 3) + (t4 << 1);
        #pragma unroll
        for (int nt = 0; nt < 4; nt++) {
            float2 b = *(const float2*)(b0p + nt * 1024 + coff);
            uint32_t b0 = __float_as_uint(b.x);
            uint32_t b1 = __float_as_uint(b.y);
            mma8(d[nt],     A[0], b0, b1);
            mma8(d[4 + nt], A[1], b0, b1);
        }
    }
}

__device__ __forceinline__ void writeback(float (*d)[4], float* __restrict__ act,
                                          const float* __restrict__ bias,
                                          int wr, int wc, int g, int t4)
{
    #pragma unroll
    for (int rb = 0; rb < 2; rb++) {
        const int r = wr * 32 + rb * 16 + g;
        #pragma unroll
        for (int nt = 0; nt < 4; nt++) {
            const int col = wc * 32 + nt * 8 + t4 * 2;
            float2 bb = *(const float2*)(bias + col);
            float* p = act + r * ASTR + col;
            const float* dd = d[rb * 4 + nt];
            p[0] = tf32f(fmaxf(dd[0] + bb.x, 0.f));
            p[1] = tf32f(fmaxf(dd[1] + bb.y, 0.f));
            p[8 * ASTR]     = tf32f(fmaxf(dd[2] + bb.x, 0.f));
            p[8 * ASTR + 1] = tf32f(fmaxf(dd[3] + bb.y, 0.f));
        }
    }
}

// --------------------------- row feature computation -----------------------

__device__ __forceinline__ float segdist(float px, float py, float ax, float ay,
                                         float abx, float aby, float s)
{
    float t = ((px - ax) * abx + (py - ay) * aby) / s;
    t = fminf(fmaxf(t, 0.f), 1.f);
    float dx = px - (ax + t * abx);
    float dy = py - (ay + t * aby);
    return sqrtf(dx * dx + dy * dy);
}

struct RowF {
    float relx, rely, dist, maskD, maskJ, maskS;
    float i2, i3, i4, iav, i7f;
    float q2, q3, q4, qvx, qvy, qav;
};

__device__ __forceinline__ RowF rowCalc(int rowid,
    const float* __restrict__ init_x,  const float* __restrict__ query_x,
    const float* __restrict__ init_v,  const float* __restrict__ query_v,
    const float* __restrict__ init_av, const float* __restrict__ query_av)
{
    RowF f;
    const int bo = rowid >> 6, t = rowid & 63, b = rowid >> 12;
    const float* ix = init_x + bo * 9;
    const float* qx = query_x + (b * 64 + t) * 9;
    float i2 = ix[2], i3 = ix[3], i4 = ix[4], i7 = ix[7], i8 = ix[8];
    float q2 = qx[2], q3 = qx[3], q4 = qx[4], q7 = qx[7], q8 = qx[8];
    f.relx = qx[0] - ix[0]; f.rely = qx[1] - ix[1];
    f.qvx = query_v[(b * 64 + t) * 2 + 0] - init_v[bo * 2 + 0];
    f.qvy = query_v[(b * 64 + t) * 2 + 1] - init_v[bo * 2 + 1];
    f.iav = init_av[bo];
    f.qav = query_av[b * 64 + t] - f.iav;

    float sn1, cs1; sincosf(i3 * 100.f, &sn1, &cs1);
    float sn2, cs2; sincosf(q3 * 100.f, &sn2, &cs2);
    float o1x = i2 * 0.5f * cs1, o1y = i2 * 0.5f * sn1;
    float o2x = q2 * 0.5f * cs2, o2y = q2 * 0.5f * sn2;
    float ab1x = 2.f * o1x, ab1y = 2.f * o1y;
    float ab2x = 2.f * o2x, ab2y = 2.f * o2y;
    float ss1 = ab1x * ab1x + ab1y * ab1y + 1e-8f;
    float ss2 = ab2x * ab2x + ab2y * ab2y + 1e-8f;
    float A2x = f.relx - o2x, A2y = f.rely - o2y;
    float B2x = f.relx + o2x, B2y = f.rely + o2y;
    float d1 = segdist(A2x, A2y, -o1x, -o1y, ab1x, ab1y, ss1);
    float d2 = segdist(B2x, B2y, -o1x, -o1y, ab1x, ab1y, ss1);
    float d3 = segdist(-o1x, -o1y, A2x, A2y, ab2x, ab2y, ss2);
    float d4 = segdist(o1x, o1y, A2x, A2y, ab2x, ab2y, ss2);
    f.dist = fminf(fminf(d1, d2), fminf(d3, d4)) - i4 - q4;
    f.maskD = (f.dist <= 0.f) ? 1.f : 0.f;
    float ti = truncf(i7), tq = truncf(q7);
    f.maskJ = (ti == tq && i7 > 0.f) ? 1.f : 0.f;
    f.maskS = (i8 == q8 && i8 > 0.f) ? 1.f : 0.f;
    f.i2 = i2; f.i3 = i3; f.i4 = i4; f.i7f = i7 - ti;
    f.q2 = q2; f.q3 = q3; f.q4 = q4;
    return f;
}

// ------------------------------- fused kernel ------------------------------

extern "C" __global__ void __launch_bounds__(NT, 1)
ffp_all(const float* __restrict__ init_x,  const float* __restrict__ query_x,
        const float* __restrict__ init_v,  const float* __restrict__ query_v,
        const float* __restrict__ init_av, const float* __restrict__ query_av,
        const float* __restrict__ trunk_w0, const float* __restrict__ trunk_b0,
        const float* __restrict__ trunk_ws, const float* __restrict__ trunk_bs,
        const float* __restrict__ branch_w0, const float* __restrict__ branch_b0,
        const float* __restrict__ branch_ws, const float* __restrict__ branch_bs,
        const float* __restrict__ out_w,   const float* __restrict__ out_b,
        const float* __restrict__ spring_w0, const float* __restrict__ spring_b0,
        const float* __restrict__ spring_w1, const float* __restrict__ spring_b1,
        const float* __restrict__ joint_w0, const float* __restrict__ joint_b0,
        const float* __restrict__ joint_w1, const float* __restrict__ joint_b1,
        float* __restrict__ out)
{
    extern __shared__ float sm[];
    const int tid = threadIdx.x;
    const int gid = tid >> 8, tg = tid & 255;
    const int wid_g = tg >> 5, lane = tid & 31;
    const int wr = wid_g & 1, wc = wid_g >> 1;
    const int g = lane >> 2, t4 = lane & 3;
    const int barid = 1 + gid;

    float* actg  = sm + S_ACT + gid * GSLICE;
    float* featg = actg;                       // aliases act
    float* scr   = actg;                       // aliases act (dead in epilogue)
    int* tRow = (int*)(sm + S_TROW) + gid * 64;
    int* tBo  = (int*)(sm + S_TBO)  + gid * 64;
    int* tick = (int*)(sm + S_TICK);

    // ================= Phase 0: branch MLP via tf32 (CTAs 0..31) ===========
    if (blockIdx.x < 32) {
        for (int i = tid * 4; i < 2304; i += NT * 4)
            *(float4*)(sm + S_W0T + i) = make_float4(0.f, 0.f, 0.f, 0.f);
        __syncthreads();
        for (int idx = tid; idx < 16384; idx += NT) {
            int k = idx >> 7, n = idx & 127;
            int off = wswz(n, k);
            sm[S_W1 + off] = tf32f(branch_ws[idx]);
            sm[S_W2 + off] = tf32f(branch_ws[16384 + idx]);
        }
        for (int idx = tid; idx < 3 * 128; idx += NT) {
            int k = idx >> 7, n = idx & 127;
            sm[S_W0T + n * WSTR + k] = tf32f(branch_w0[(2 + k) * 128 + n]);
        }
        for (int i = tid; i < 128; i += NT) {
            sm[S_B0 + i] = branch_b0[i];
            sm[S_B1 + i] = branch_bs[i];
            sm[S_B2 + i] = branch_bs[128 + i];
        }
        for (int i = tid; i < 384; i += NT)
            sm[S_OUTW + i] = out_w[(i & 127) * 3 + (i >> 7)];
        __syncthreads();

        {
            const int boBase = (blockIdx.x * 2 + gid) * 64;
            if (tg < 64) {
                const float* ix = init_x + (boBase + tg) * 9;
                float* fr = featg + tg * FSTR;
                fr[0] = tf32f(ix[2]); fr[1] = tf32f(ix[3]); fr[2] = tf32f(ix[4]);
                #pragma unroll
                for (int j = 3; j < 8; j++) fr[j] = 0.f;
            }
            BARG(barid);
            float d[8][4];
            layer_input<1>(sm + S_W0T, featg, d, wr, wc, g, t4);
            BARG(barid);
            writeback(d, actg, sm + S_B0, wr, wc, g, t4);
            BARG(barid);
            layer_hidden(sm + S_W1, actg, d, wr, wc, g, t4);
            BARG(barid);
            writeback(d, actg, sm + S_B1, wr, wc, g, t4);
            BARG(barid);
            layer_hidden(sm + S_W2, actg, d, wr, wc, g, t4);
            #pragma unroll
            for (int rb = 0; rb < 2; rb++) {
                const int rA = wr * 32 + rb * 16 + g;
                const int rB = rA + 8;
                #pragma unroll
                for (int nt = 0; nt < 4; nt++) {
                    const int col = wc * 32 + nt * 8 + 2 * t4;
                    float2 bb = *(const float2*)(sm + S_B2 + col);
                    const float* dd = d[rb * 4 + nt];
                    float h0 = dd[0] + bb.x, h1 = dd[1] + bb.y;
                    float h2 = dd[2] + bb.x, h3 = dd[3] + bb.y;
                    #pragma unroll
                    for (int part = 0; part < 3; part++) {
                        float2 ow = *(const float2*)(sm + S_OUTW + part * 128 + col);
                        *(float2*)(g_branchM + (boBase + rA) * 384 + part * 128 + col)
                            = make_float2(h0 * ow.x, h1 * ow.y);
                        *(float2*)(g_branchM + (boBase + rB) * 384 + part * 128 + col)
                            = make_float2(h2 * ow.x, h3 * ow.y);
                    }
                }
            }
            BARG(barid);
            if (tg == 0) { __threadfence(); atomicAdd(&g_cnt[5], 1); }
        }
        __syncthreads();
    }

    // ---- stage trunk/joint weights (all CTAs) ----
    for (int i = tid * 4; i < 4608; i += NT * 4)
        *(float4*)(sm + S_W0T + i) = make_float4(0.f, 0.f, 0.f, 0.f);
    __syncthreads();
    for (int idx = tid; idx < 16384; idx += NT) {
        int k = idx >> 7, n = idx & 127;
        int off = wswz(n, k);
        sm[S_W1 + off] = tf32f(trunk_ws[idx]);
        sm[S_W2 + off] = tf32f(trunk_ws[16384 + idx]);
    }
    for (int idx = tid; idx < 9 * 128; idx += NT) {
        int k = idx >> 7, n = idx & 127;
        sm[S_W0T + n * WSTR + k] = tf32f(trunk_w0[idx]);
    }
    for (int idx = tid; idx < 15 * 128; idx += NT) {
        int k = idx >> 7, n = idx & 127;
        sm[S_JW0T + n * WSTR + k] = tf32f(joint_w0[idx]);
    }
    for (int i = tid; i < 128; i += NT) {
        sm[S_B0 + i]  = trunk_b0[i];
        sm[S_B1 + i]  = trunk_bs[i];
        sm[S_B2 + i]  = trunk_bs[128 + i];
        sm[S_JB0 + i] = joint_b0[i];
    }
    if (tid < 256) sm[S_JW1 + tid] = joint_w1[(tid & 127) * 2 + (tid >> 7)];
    __syncthreads();

    // ================= Scan: chunk-stolen rows =============================
    for (;;) {
        if (tid == 0) tick[2] = atomicAdd(&g_cnt[3], 1);
        __syncthreads();
        const int ch = tick[2];
        __syncthreads();
        if (ch >= 128) break;
        #pragma unroll
        for (int i = 0; i < 4; i++) {
            const int rid = ch * 2048 + i * 512 + tid;
            RowF f = rowCalc(rid, init_x, query_x, init_v, query_v, init_av, query_av);
            unsigned mD = __ballot_sync(0xffffffffu, f.maskD > 0.f);
            if (mD) {
                int base = 0;
                if (lane == 0) base = atomicAdd(&g_cnt[0], __popc(mD));
                base = __shfl_sync(0xffffffffu, base, 0);
                if (f.maskD > 0.f) {
                    int pos = base + __popc(mD & ((1u << lane) - 1u));
                    g_trunkList[pos] = rid;
                    float4* fp = (float4*)(g_tFeat + pos * 16);
                    fp[0] = make_float4(tf32f(f.relx), tf32f(f.rely), tf32f(f.q2), tf32f(f.q3));
                    fp[1] = make_float4(tf32f(f.q4), tf32f(f.qvx), tf32f(f.qvy), tf32f(f.qav));
                    fp[2] = make_float4(tf32f(f.dist * 100.f), 0.f, 0.f, 0.f);
                    fp[3] = make_float4(0.f, 0.f, 0.f, 0.f);
                }
            }
            unsigned mJ = __ballot_sync(0xffffffffu, f.maskJ > 0.f);
            if (mJ) {
                int base = 0;
                if (lane == 0) base = atomicAdd(&g_cnt[1], __popc(mJ));
                base = __shfl_sync(0xffffffffu, base, 0);
                if (f.maskJ > 0.f) {
                    int pos = base + __popc(mJ & ((1u << lane) - 1u));
                    g_jointList[pos] = rid;
                    float4* fp = (float4*)(g_jFeat + pos * 16);
                    fp[0] = make_float4(0.f, 0.f, tf32f(f.i2), tf32f(f.i3));
                    fp[1] = make_float4(tf32f(f.i4), tf32f(f.relx), tf32f(f.rely), tf32f(f.q2));
                    fp[2] = make_float4(tf32f(f.q3), tf32f(f.q4), tf32f(f.qvx), tf32f(f.qvy));
                    fp[3] = make_float4(tf32f(f.iav), tf32f(f.qav), tf32f(f.i7f), 0.f);
                }
            }
            if (f.maskS > 0.f) {   // essentially never; exact scalar path
                float len = sqrtf(f.relx * f.relx + f.rely * f.rely);
                float sf = __ldg(spring_b1);
                for (int k = 0; k < 128; k++)
                    sf = fmaf(fmaxf(fmaf(len, __ldg(spring_w0 + k), __ldg(spring_b0 + k)), 0.f),
                              __ldg(spring_w1 + k), sf);
                float inv = 1.f / (len + 1e-8f);
                atomicAdd(out + rid * 3 + 0, sf * (-f.relx * inv));
                atomicAdd(out + rid * 3 + 1, sf * (-f.rely * inv));
            }
        }
        __threadfence();
        __syncthreads();
        if (tid == 0) atomicAdd(&g_cnt[4], 1);
    }

    // ---- wait for scan completion (all chunks) ----
    if (tid == 0) {
        while (*(volatile int*)&g_cnt[4] < 128) __nanosleep(64);
    }
    __syncthreads();
    __threadfence();
    const int nT = *(volatile int*)&g_cnt[0];
    const int nJ = *(volatile int*)&g_cnt[1];
    const int nJT = (nJ + 63) >> 6, nTT = (nT + 63) >> 6;

    // ================= Phase B: stolen tiles (joint first) ==================
    bool branchOK = false;
    for (;;) {
        if (tg == 0) tick[gid] = atomicAdd(&g_cnt[2], 1);
        BARG(barid);
        const int ti = tick[gid];
        BARG(barid);
        if (ti >= nJT + nTT) break;

        if (ti >= nJT) {
            // ------------------ trunk tile ------------------
            if (!branchOK) {
                while (*(volatile int*)&g_cnt[5] < 64) __nanosleep(32);
                __threadfence();
                branchOK = true;
            }
            const int base = (ti - nJT) << 6;
            if (tg < 64) {
                const int i = base + tg;
                const int rowid = (i < nT) ? g_trunkList[i] : -1;
                tRow[tg] = rowid;
                tBo[tg]  = (rowid >= 0) ? (rowid >> 6) : 0;
                float* fr = featg + tg * FSTR;
                if (rowid >= 0) {
                    const float4* fp = (const float4*)(g_tFeat + i * 16);
                    *(float4*)(fr)      = fp[0];
                    *(float4*)(fr + 4)  = fp[1];
                    *(float4*)(fr + 8)  = fp[2];
                    *(float4*)(fr + 12) = fp[3];
                } else {
                    #pragma unroll
                    for (int j = 0; j < 16; j += 4)
                        *(float4*)(fr + j) = make_float4(0.f, 0.f, 0.f, 0.f);
                }
            }
            BARG(barid);
            float d[8][4];
            layer_input<2>(sm + S_W0T, featg, d, wr, wc, g, t4);
            BARG(barid);
            writeback(d, actg, sm + S_B0, wr, wc, g, t4);
            BARG(barid);
            layer_hidden(sm + S_W1, actg, d, wr, wc, g, t4);
            BARG(barid);
            writeback(d, actg, sm + S_B1, wr, wc, g, t4);
            BARG(barid);
            layer_hidden(sm + S_W2, actg, d, wr, wc, g, t4);

            int qbo[4], qrid[4];
            #pragma unroll
            for (int q = 0; q < 4; q++) {
                const int row = wr * 32 + (q >> 1) * 16 + g + (q & 1) * 8;
                qbo[q] = tBo[row]; qrid[q] = tRow[row];
            }
            float p[4][3];
            #pragma unroll
            for (int q = 0; q < 4; q++) p[q][0] = p[q][1] = p[q][2] = 0.f;
            #pragma unroll
            for (int rb = 0; rb < 2; rb++)
            #pragma unroll
            for (int nt = 0; nt < 4; nt++) {
                const int col = wc * 32 + nt * 8 + 2 * t4;
                float2 bb = *(const float2*)(sm + S_B2 + col);
                const float* dd = d[rb * 4 + nt];
                float h0 = dd[0] + bb.x, h1 = dd[1] + bb.y;
                float h2 = dd[2] + bb.x, h3 = dd[3] + bb.y;
                const float* mA = g_branchM + qbo[rb * 2] * 384 + col;
                const float* mB = g_branchM + qbo[rb * 2 + 1] * 384 + col;
                #pragma unroll
                for (int part = 0; part < 3; part++) {
                    float2 a = __ldg((const float2*)(mA + part * 128));
                    float2 b = __ldg((const float2*)(mB + part * 128));
                    p[rb * 2][part]     += h0 * a.x + h1 * a.y;
                    p[rb * 2 + 1][part] += h2 * b.x + h3 * b.y;
                }
            }
            #pragma unroll
            for (int q = 0; q < 4; q++)
            #pragma unroll
            for (int part = 0; part < 3; part++) {
                float v = p[q][part];
                v += __shfl_xor_sync(0xffffffffu, v, 1);
                v += __shfl_xor_sync(0xffffffffu, v, 2);
                if (t4 == 0 && qrid[q] >= 0)
                    atomicAdd(out + qrid[q] * 3 + part,
                              v + (wc == 0 ? __ldg(out_b + part) : 0.f));
            }
            BARG(barid);   // actg/featg reads done before next tile writes
        } else {
            // ------------------ joint tile ------------------
            const int base = ti << 6;
            if (tg < 64) {
                const int i = base + tg;
                const int rowid = (i < nJ) ? g_jointList[i] : -1;
                tRow[tg] = rowid;
                float* fr = featg + tg * FSTR;
                if (rowid >= 0) {
                    const float4* fp = (const float4*)(g_jFeat + i * 16);
                    *(float4*)(fr)      = fp[0];
                    *(float4*)(fr + 4)  = fp[1];
                    *(float4*)(fr + 8)  = fp[2];
                    *(float4*)(fr + 12) = fp[3];
                } else {
                    #pragma unroll
                    for (int j = 0; j < 16; j += 4)
                        *(float4*)(fr + j) = make_float4(0.f, 0.f, 0.f, 0.f);
                }
            }
            BARG(barid);
            float d[8][4];
            layer_input<2>(sm + S_JW0T, featg, d, wr, wc, g, t4);

            int qrid[4];
            #pragma unroll
            for (int q = 0; q < 4; q++) {
                const int row = wr * 32 + (q >> 1) * 16 + g + (q & 1) * 8;
                qrid[q] = tRow[row];
            }
            float pj[4][2];
            #pragma unroll
            for (int q = 0; q < 4; q++) pj[q][0] = pj[q][1] = 0.f;
            #pragma unroll
            for (int rb = 0; rb < 2; rb++)
            #pragma unroll
            for (int nt = 0; nt < 4; nt++) {
                const int col = wc * 32 + nt * 8 + 2 * t4;
                float2 jb  = *(const float2*)(sm + S_JB0 + col);
                float2 w0v = *(const float2*)(sm + S_JW1 + col);
                float2 w1v = *(const float2*)(sm + S_JW1 + 128 + col);
                const float* dd = d[rb * 4 + nt];
                float h0 = fmaxf(dd[0] + jb.x, 0.f), h1 = fmaxf(dd[1] + jb.y, 0.f);
                float h2 = fmaxf(dd[2] + jb.x, 0.f), h3 = fmaxf(dd[3] + jb.y, 0.f);
                pj[rb * 2][0]     += h0 * w0v.x + h1 * w0v.y;
                pj[rb * 2][1]     += h0 * w1v.x + h1 * w1v.y;
                pj[rb * 2 + 1][0] += h2 * w0v.x + h3 * w0v.y;
                pj[rb * 2 + 1][1] += h2 * w1v.x + h3 * w1v.y;
            }
            #pragma unroll
            for (int q = 0; q < 4; q++)
            #pragma unroll
            for (int part = 0; part < 2; part++) {
                float v = pj[q][part];
                v += __shfl_xor_sync(0xffffffffu, v, 1);
                v += __shfl_xor_sync(0xffffffffu, v, 2);
                if (t4 == 0 && qrid[q] >= 0)
                    atomicAdd(out + qrid[q] * 3 + part,
                              v + (wc == 0 ? __ldg(joint_b1 + part) : 0.f));
            }
            BARG(barid);   // featg reads done before next tile writes
        }
    }
}

// ---------------------------------------------------------------------------

extern "C" void kernel_launch(void* const* d_in, const int* in_sizes, int n_in,
                              void* d_out, int out_size)
{
    const float* init_x    = (const float*)d_in[0];
    const float* query_x   = (const float*)d_in[1];
    const float* init_v    = (const float*)d_in[2];
    const float* query_v   = (const float*)d_in[3];
    const float* init_av   = (const float*)d_in[4];
    const float* query_av  = (const float*)d_in[5];
    const float* trunk_w0  = (const float*)d_in[6];
    const float* trunk_b0  = (const float*)d_in[7];
    const float* trunk_ws  = (const float*)d_in[8];
    const float* trunk_bs  = (const float*)d_in[9];
    const float* branch_w0 = (const float*)d_in[10];
    const float* branch_b0 = (const float*)d_in[11];
    const float* branch_ws = (const float*)d_in[12];
    const float* branch_bs = (const float*)d_in[13];
    const float* out_w     = (const float*)d_in[14];
    const float* out_b     = (const float*)d_in[15];
    const float* spring_w0 = (const float*)d_in[16];
    const float* spring_b0 = (const float*)d_in[17];
    const float* spring_w1 = (const float*)d_in[18];
    const float* spring_b1 = (const float*)d_in[19];
    const float* joint_w0  = (const float*)d_in[20];
    const float* joint_b0  = (const float*)d_in[21];
    const float* joint_w1  = (const float*)d_in[22];
    const float* joint_b1  = (const float*)d_in[23];
    float* out = (float*)d_out;

    int nsm = 148;
    cudaDeviceGetAttribute(&nsm, cudaDevAttrMultiProcessorCount, 0);

    // reset counters + zero output (list/atomic pipeline requires both)
    void* cntPtr = nullptr;
    cudaGetSymbolAddress(&cntPtr, g_cnt);
    cudaMemsetAsync(cntPtr, 0, 8 * sizeof(int));
    cudaMemsetAsync(out, 0, (size_t)out_size * sizeof(float));

    const int smem = S_TOTAL * sizeof(float);
    cudaFuncSetAttribute(ffp_all, cudaFuncAttributeMaxDynamicSharedMemorySize, smem);

    ffp_all<<<nsm, NT, smem>>>(init_x, query_x, init_v, query_v, init_av, query_av,
                               trunk_w0, trunk_b0, trunk_ws, trunk_bs,
                               branch_w0, branch_b0, branch_ws, branch_bs,
                               out_w, out_b,
                               spring_w0, spring_b0, spring_w1, spring_b1,
                               joint_w0, joint_b0, joint_w1, joint_b1,
                               out);
}

// round 12
// speedup vs baseline: 2.1144x; 1.0273x over previous
#include <cuda_runtime.h>
#include <math.h>
#include <stdint.h>

// ===========================================================================
// ForceFieldPredictor R12: stripped per-tile skeleton.
//   - A-fragments for input layers gathered straight from g_tFeat/g_jFeat
//     (position-indexed) -> no feature smem staging, no staging barrier.
//   - 4 barriers per trunk tile, 1 per joint tile; rowid/ticket smem is
//     parity double-buffered (iteration-distance-2 safety via barrier #1).
//   - branchDone gate moved to the first trunk EPILOGUE per group: trunk
//     MMA overlaps the branch phase.
//   - ticket prefetch (next ticket fetched at tile start).
// ===========================================================================

typedef unsigned long long ull;

__device__ float g_branchM[4096 * 384];     // planar: [bo][part*128 + k]
__device__ int   g_cnt[8];                  // 0:nT 1:nJ 2:tileTick 3:scanTick
                                            // 4:scanDone 5:branchDone (memset)
__device__ int   g_trunkList[262144];
__device__ int   g_jointList[262144];
__device__ float g_tFeat[262144 * 16];
__device__ float g_jFeat[262144 * 16];

// ---------------------------- small PTX helpers ----------------------------

__device__ __forceinline__ uint32_t f2tf32(float x) {
    uint32_t r; asm("cvt.rna.tf32.f32 %0, %1;" : "=r"(r) : "f"(x)); return r;
}
__device__ __forceinline__ float tf32f(float x) { return __uint_as_float(f2tf32(x)); }

__device__ __forceinline__ void mma8(float* d, const uint32_t* a, uint32_t b0, uint32_t b1) {
    asm volatile("mma.sync.aligned.m16n8k8.row.col.f32.tf32.tf32.f32 "
                 "{%0,%1,%2,%3}, {%4,%5,%6,%7}, {%8,%9}, {%0,%1,%2,%3};"
                 : "+f"(d[0]), "+f"(d[1]), "+f"(d[2]), "+f"(d[3])
                 : "r"(a[0]), "r"(a[1]), "r"(a[2]), "r"(a[3]), "r"(b0), "r"(b1));
}

#define BARG(id) asm volatile("bar.sync %0, %1;" :: "r"(id), "r"(256) : "memory")

// ---------------------------- smem layout (floats) -------------------------
#define S_W1    0                 // 16384 : hidden W1 (tf32, pair-packed XOR)
#define S_W2    16384             // 16384 : hidden W2
#define S_ACT   32768             // 2 x 8448 (64 rows x 132) group act slices
#define S_W0T   49664             // 2304 : input W0t [n][k], stride 18
#define S_JW0T  51968             // 2304 : joint W0t
#define S_B0    54272
#define S_B1    54400
#define S_B2    54528
#define S_JB0   54656
#define S_JW1   54784             // 256 : [part][128]
#define S_OUTW  55040             // 384 : out_w planar (phase 0 only)
#define S_TROW  55424             // 256 ints : 2 groups x 2 parity x 64 rowids
#define S_TBO   55680             // 256 ints : 2 groups x 2 parity x 64 bo
#define S_TICK  55936             // 8 ints   : 2 groups x 2 parity tickets + scan slot
#define S_TOTAL 55944             // 223,776 B

#define ASTR 132
#define WSTR 18
#define NT   512
#define GSLICE 8448
#define PADR 132                  // branch-phase fp32 layouts reuse tf32 path now

// pair-packed chunk-XOR weight placement: W[n][k] ->
//   n*128 + ((k>>3) ^ (n&7))*8 + (k&3)*2 + ((k>>2)&1)
__device__ __forceinline__ int wswz(int n, int k) {
    return n * 128 + ((((k >> 3) ^ (n & 7)) << 3) + ((k & 3) << 1) + ((k >> 2) & 1));
}

// ----------------------- tf32 MMA layer helpers ----------------------------
// group = 256 threads; warp (wr in 0..1, wc in 0..3): 32 rows x 32 cols.

// input layer, A prefetched in registers A[c][rb][4]
template<int C>
__device__ __forceinline__ void layer_input_regs(const float* __restrict__ sWin,
                                                 const uint32_t A[][2][4],
                                                 float (*d)[4], int wc, int g, int t4)
{
    #pragma unroll
    for (int i = 0; i < 8; i++)
        d[i][0] = d[i][1] = d[i][2] = d[i][3] = 0.f;
    const float* b0p = sWin + (wc * 32 + g) * WSTR + t4;
    #pragma unroll
    for (int c = 0; c < C; c++) {
        #pragma unroll
        for (int nt = 0; nt < 4; nt++) {
            const float* bp = b0p + nt * 8 * WSTR + c * 8;
            uint32_t b0 = __float_as_uint(bp[0]);
            uint32_t b1 = __float_as_uint(bp[4]);
            mma8(d[nt],     A[c][0], b0, b1);
            mma8(d[4 + nt], A[c][1], b0, b1);
        }
    }
}

__device__ __forceinline__ void layer_hidden(const float* __restrict__ sW,
                                             const float* __restrict__ act,
                                             float (*d)[4],
                                             int wr, int wc, int g, int t4)
{
    #pragma unroll
    for (int i = 0; i < 8; i++)
        d[i][0] = d[i][1] = d[i][2] = d[i][3] = 0.f;
    const float* a0p = act + (wr * 32 + g) * ASTR + t4;
    const float* b0p = sW + (wc * 32 + g) * 128;
    #pragma unroll 4
    for (int c = 0; c < 16; c++) {
        uint32_t A[2][4];
        #pragma unroll
        for (int rb = 0; rb < 2; rb++) {
            const float* ap = a0p + rb * 16 * ASTR + c * 8;
            A[rb][0] = __float_as_uint(ap[0]);
            A[rb][1] = __float_as_uint(ap[8 * ASTR]);
            A[rb][2] = __float_as_uint(ap[4]);
            A[rb][3] = __float_as_uint(ap[8 * ASTR + 4]);
        }
        const int coff = ((c ^ g) << 3) + (t4 << 1);
        #pragma unroll
        for (int nt = 0; nt < 4; nt++) {
            float2 b = *(const float2*)(b0p + nt * 1024 + coff);
            uint32_t b0 = __float_as_uint(b.x);
            uint32_t b1 = __float_as_uint(b.y);
            mma8(d[nt],     A[0], b0, b1);
            mma8(d[4 + nt], A[1], b0, b1);
        }
    }
}

__device__ __forceinline__ void writeback(float (*d)[4], float* __restrict__ act,
                                          const float* __restrict__ bias,
                                          int wr, int wc, int g, int t4)
{
    #pragma unroll
    for (int rb = 0; rb < 2; rb++) {
        const int r = wr * 32 + rb * 16 + g;
        #pragma unroll
        for (int nt = 0; nt < 4; nt++) {
            const int col = wc * 32 + nt * 8 + t4 * 2;
            float2 bb = *(const float2*)(bias + col);
            float* p = act + r * ASTR + col;
            const float* dd = d[rb * 4 + nt];
            p[0] = tf32f(fmaxf(dd[0] + bb.x, 0.f));
            p[1] = tf32f(fmaxf(dd[1] + bb.y, 0.f));
            p[8 * ASTR]     = tf32f(fmaxf(dd[2] + bb.x, 0.f));
            p[8 * ASTR + 1] = tf32f(fmaxf(dd[3] + bb.y, 0.f));
        }
    }
}

// --------------------------- row feature computation -----------------------

__device__ __forceinline__ float segdist(float px, float py, float ax, float ay,
                                         float abx, float aby, float s)
{
    float t = ((px - ax) * abx + (py - ay) * aby) / s;
    t = fminf(fmaxf(t, 0.f), 1.f);
    float dx = px - (ax + t * abx);
    float dy = py - (ay + t * aby);
    return sqrtf(dx * dx + dy * dy);
}

struct RowF {
    float relx, rely, dist, maskD, maskJ, maskS;
    float i2, i3, i4, iav, i7f;
    float q2, q3, q4, qvx, qvy, qav;
};

__device__ __forceinline__ RowF rowCalc(int rowid,
    const float* __restrict__ init_x,  const float* __restrict__ query_x,
    const float* __restrict__ init_v,  const float* __restrict__ query_v,
    const float* __restrict__ init_av, const float* __restrict__ query_av)
{
    RowF f;
    const int bo = rowid >> 6, t = rowid & 63, b = rowid >> 12;
    const float* ix = init_x + bo * 9;
    const float* qx = query_x + (b * 64 + t) * 9;
    float i2 = ix[2], i3 = ix[3], i4 = ix[4], i7 = ix[7], i8 = ix[8];
    float q2 = qx[2], q3 = qx[3], q4 = qx[4], q7 = qx[7], q8 = qx[8];
    f.relx = qx[0] - ix[0]; f.rely = qx[1] - ix[1];
    f.qvx = query_v[(b * 64 + t) * 2 + 0] - init_v[bo * 2 + 0];
    f.qvy = query_v[(b * 64 + t) * 2 + 1] - init_v[bo * 2 + 1];
    f.iav = init_av[bo];
    f.qav = query_av[b * 64 + t] - f.iav;

    float sn1, cs1; sincosf(i3 * 100.f, &sn1, &cs1);
    float sn2, cs2; sincosf(q3 * 100.f, &sn2, &cs2);
    float o1x = i2 * 0.5f * cs1, o1y = i2 * 0.5f * sn1;
    float o2x = q2 * 0.5f * cs2, o2y = q2 * 0.5f * sn2;
    float ab1x = 2.f * o1x, ab1y = 2.f * o1y;
    float ab2x = 2.f * o2x, ab2y = 2.f * o2y;
    float ss1 = ab1x * ab1x + ab1y * ab1y + 1e-8f;
    float ss2 = ab2x * ab2x + ab2y * ab2y + 1e-8f;
    float A2x = f.relx - o2x, A2y = f.rely - o2y;
    float B2x = f.relx + o2x, B2y = f.rely + o2y;
    float d1 = segdist(A2x, A2y, -o1x, -o1y, ab1x, ab1y, ss1);
    float d2 = segdist(B2x, B2y, -o1x, -o1y, ab1x, ab1y, ss1);
    float d3 = segdist(-o1x, -o1y, A2x, A2y, ab2x, ab2y, ss2);
    float d4 = segdist(o1x, o1y, A2x, A2y, ab2x, ab2y, ss2);
    f.dist = fminf(fminf(d1, d2), fminf(d3, d4)) - i4 - q4;
    f.maskD = (f.dist <= 0.f) ? 1.f : 0.f;
    float ti = truncf(i7), tq = truncf(q7);
    f.maskJ = (ti == tq && i7 > 0.f) ? 1.f : 0.f;
    f.maskS = (i8 == q8 && i8 > 0.f) ? 1.f : 0.f;
    f.i2 = i2; f.i3 = i3; f.i4 = i4; f.i7f = i7 - ti;
    f.q2 = q2; f.q3 = q3; f.q4 = q4;
    return f;
}

// ------------------------------- fused kernel ------------------------------

extern "C" __global__ void __launch_bounds__(NT, 1)
ffp_all(const float* __restrict__ init_x,  const float* __restrict__ query_x,
        const float* __restrict__ init_v,  const float* __restrict__ query_v,
        const float* __restrict__ init_av, const float* __restrict__ query_av,
        const float* __restrict__ trunk_w0, const float* __restrict__ trunk_b0,
        const float* __restrict__ trunk_ws, const float* __restrict__ trunk_bs,
        const float* __restrict__ branch_w0, const float* __restrict__ branch_b0,
        const float* __restrict__ branch_ws, const float* __restrict__ branch_bs,
        const float* __restrict__ out_w,   const float* __restrict__ out_b,
        const float* __restrict__ spring_w0, const float* __restrict__ spring_b0,
        const float* __restrict__ spring_w1, const float* __restrict__ spring_b1,
        const float* __restrict__ joint_w0, const float* __restrict__ joint_b0,
        const float* __restrict__ joint_w1, const float* __restrict__ joint_b1,
        float* __restrict__ out)
{
    extern __shared__ float sm[];
    const int tid = threadIdx.x;
    const int gid = tid >> 8, tg = tid & 255;
    const int wid_g = tg >> 5, lane = tid & 31;
    const int wr = wid_g & 1, wc = wid_g >> 1;
    const int g = lane >> 2, t4 = lane & 3;
    const int barid = 1 + gid;

    float* actg = sm + S_ACT + gid * GSLICE;
    float* featg = actg;                      // branch phase only
    int* trowB = (int*)(sm + S_TROW) + gid * 128;   // [parity][64]
    int* tboB  = (int*)(sm + S_TBO)  + gid * 128;
    int* tickB = (int*)(sm + S_TICK) + gid * 2;     // [parity]
    int* scanT = (int*)(sm + S_TICK) + 4;

    // ================= Phase 0: branch MLP via tf32 (CTAs 0..31) ===========
    if (blockIdx.x < 32) {
        for (int i = tid * 4; i < 2304; i += NT * 4)
            *(float4*)(sm + S_W0T + i) = make_float4(0.f, 0.f, 0.f, 0.f);
        __syncthreads();
        for (int idx = tid; idx < 16384; idx += NT) {
            int k = idx >> 7, n = idx & 127;
            int off = wswz(n, k);
            sm[S_W1 + off] = tf32f(branch_ws[idx]);
            sm[S_W2 + off] = tf32f(branch_ws[16384 + idx]);
        }
        for (int idx = tid; idx < 3 * 128; idx += NT) {
            int k = idx >> 7, n = idx & 127;
            sm[S_W0T + n * WSTR + k] = tf32f(branch_w0[(2 + k) * 128 + n]);
        }
        for (int i = tid; i < 128; i += NT) {
            sm[S_B0 + i] = branch_b0[i];
            sm[S_B1 + i] = branch_bs[i];
            sm[S_B2 + i] = branch_bs[128 + i];
        }
        for (int i = tid; i < 384; i += NT)
            sm[S_OUTW + i] = out_w[(i & 127) * 3 + (i >> 7)];
        __syncthreads();

        {
            const int boBase = (blockIdx.x * 2 + gid) * 64;
            // features via registers (3 cols only)
            uint32_t A[1][2][4];
            {
                const int r0 = wr * 32 + g;
                #pragma unroll
                for (int rb = 0; rb < 2; rb++) {
                    const float* ix0 = init_x + (boBase + r0 + rb * 16) * 9;
                    const float* ix8 = init_x + (boBase + r0 + rb * 16 + 8) * 9;
                    A[0][rb][0] = (t4 < 3) ? f2tf32(__ldg(ix0 + 2 + t4)) : 0u;
                    A[0][rb][1] = (t4 < 3) ? f2tf32(__ldg(ix8 + 2 + t4)) : 0u;
                    A[0][rb][2] = 0u;   // cols 4..7 zero
                    A[0][rb][3] = 0u;
                }
            }
            float d[8][4];
            layer_input_regs<1>(sm + S_W0T, A, d, wc, g, t4);
            writeback(d, actg, sm + S_B0, wr, wc, g, t4);
            BARG(barid);
            layer_hidden(sm + S_W1, actg, d, wr, wc, g, t4);
            BARG(barid);
            writeback(d, actg, sm + S_B1, wr, wc, g, t4);
            BARG(barid);
            layer_hidden(sm + S_W2, actg, d, wr, wc, g, t4);
            #pragma unroll
            for (int rb = 0; rb < 2; rb++) {
                const int rA = wr * 32 + rb * 16 + g;
                const int rB = rA + 8;
                #pragma unroll
                for (int nt = 0; nt < 4; nt++) {
                    const int col = wc * 32 + nt * 8 + 2 * t4;
                    float2 bb = *(const float2*)(sm + S_B2 + col);
                    const float* dd = d[rb * 4 + nt];
                    float h0 = dd[0] + bb.x, h1 = dd[1] + bb.y;
                    float h2 = dd[2] + bb.x, h3 = dd[3] + bb.y;
                    #pragma unroll
                    for (int part = 0; part < 3; part++) {
                        float2 ow = *(const float2*)(sm + S_OUTW + part * 128 + col);
                        *(float2*)(g_branchM + (boBase + rA) * 384 + part * 128 + col)
                            = make_float2(h0 * ow.x, h1 * ow.y);
                        *(float2*)(g_branchM + (boBase + rB) * 384 + part * 128 + col)
                            = make_float2(h2 * ow.x, h3 * ow.y);
                    }
                }
            }
            BARG(barid);
            if (tg == 0) { __threadfence(); atomicAdd(&g_cnt[5], 1); }
        }
        __syncthreads();
    }

    // ---- stage trunk/joint weights (all CTAs) ----
    for (int i = tid * 4; i < 4608; i += NT * 4)
        *(float4*)(sm + S_W0T + i) = make_float4(0.f, 0.f, 0.f, 0.f);
    __syncthreads();
    for (int idx = tid; idx < 16384; idx += NT) {
        int k = idx >> 7, n = idx & 127;
        int off = wswz(n, k);
        sm[S_W1 + off] = tf32f(trunk_ws[idx]);
        sm[S_W2 + off] = tf32f(trunk_ws[16384 + idx]);
    }
    for (int idx = tid; idx < 9 * 128; idx += NT) {
        int k = idx >> 7, n = idx & 127;
        sm[S_W0T + n * WSTR + k] = tf32f(trunk_w0[idx]);
    }
    for (int idx = tid; idx < 15 * 128; idx += NT) {
        int k = idx >> 7, n = idx & 127;
        sm[S_JW0T + n * WSTR + k] = tf32f(joint_w0[idx]);
    }
    for (int i = tid; i < 128; i += NT) {
        sm[S_B0 + i]  = trunk_b0[i];
        sm[S_B1 + i]  = trunk_bs[i];
        sm[S_B2 + i]  = trunk_bs[128 + i];
        sm[S_JB0 + i] = joint_b0[i];
    }
    if (tid < 256) sm[S_JW1 + tid] = joint_w1[(tid & 127) * 2 + (tid >> 7)];
    __syncthreads();

    // ================= Scan: chunk-stolen rows =============================
    for (;;) {
        if (tid == 0) *scanT = atomicAdd(&g_cnt[3], 1);
        __syncthreads();
        const int ch = *scanT;
        __syncthreads();
        if (ch >= 128) break;
        #pragma unroll
        for (int i = 0; i < 4; i++) {
            const int rid = ch * 2048 + i * 512 + tid;
            RowF f = rowCalc(rid, init_x, query_x, init_v, query_v, init_av, query_av);
            unsigned mD = __ballot_sync(0xffffffffu, f.maskD > 0.f);
            if (mD) {
                int base = 0;
                if (lane == 0) base = atomicAdd(&g_cnt[0], __popc(mD));
                base = __shfl_sync(0xffffffffu, base, 0);
                if (f.maskD > 0.f) {
                    int pos = base + __popc(mD & ((1u << lane) - 1u));
                    g_trunkList[pos] = rid;
                    float4* fp = (float4*)(g_tFeat + pos * 16);
                    fp[0] = make_float4(tf32f(f.relx), tf32f(f.rely), tf32f(f.q2), tf32f(f.q3));
                    fp[1] = make_float4(tf32f(f.q4), tf32f(f.qvx), tf32f(f.qvy), tf32f(f.qav));
                    fp[2] = make_float4(tf32f(f.dist * 100.f), 0.f, 0.f, 0.f);
                    fp[3] = make_float4(0.f, 0.f, 0.f, 0.f);
                }
            }
            unsigned mJ = __ballot_sync(0xffffffffu, f.maskJ > 0.f);
            if (mJ) {
                int base = 0;
                if (lane == 0) base = atomicAdd(&g_cnt[1], __popc(mJ));
                base = __shfl_sync(0xffffffffu, base, 0);
                if (f.maskJ > 0.f) {
                    int pos = base + __popc(mJ & ((1u << lane) - 1u));
                    g_jointList[pos] = rid;
                    float4* fp = (float4*)(g_jFeat + pos * 16);
                    fp[0] = make_float4(0.f, 0.f, tf32f(f.i2), tf32f(f.i3));
                    fp[1] = make_float4(tf32f(f.i4), tf32f(f.relx), tf32f(f.rely), tf32f(f.q2));
                    fp[2] = make_float4(tf32f(f.q3), tf32f(f.q4), tf32f(f.qvx), tf32f(f.qvy));
                    fp[3] = make_float4(tf32f(f.iav), tf32f(f.qav), tf32f(f.i7f), 0.f);
                }
            }
            if (f.maskS > 0.f) {   // essentially never; exact scalar path
                float len = sqrtf(f.relx * f.relx + f.rely * f.rely);
                float sf = __ldg(spring_b1);
                for (int k = 0; k < 128; k++)
                    sf = fmaf(fmaxf(fmaf(len, __ldg(spring_w0 + k), __ldg(spring_b0 + k)), 0.f),
                              __ldg(spring_w1 + k), sf);
                float inv = 1.f / (len + 1e-8f);
                atomicAdd(out + rid * 3 + 0, sf * (-f.relx * inv));
                atomicAdd(out + rid * 3 + 1, sf * (-f.rely * inv));
            }
        }
        __threadfence();
        __syncthreads();
        if (tid == 0) atomicAdd(&g_cnt[4], 1);
    }

    // ---- wait for scan completion ----
    if (tid == 0) {
        while (*(volatile int*)&g_cnt[4] < 128) __nanosleep(64);
    }
    __syncthreads();
    __threadfence();
    const int nT = *(volatile int*)&g_cnt[0];
    const int nJ = *(volatile int*)&g_cnt[1];
    const int nJT = (nJ + 63) >> 6, nTT = (nT + 63) >> 6;
    const int nTot = nJT + nTT;

    // ================= Phase B: stolen tiles, stripped skeleton =============
    if (tg == 0) tickB[0] = atomicAdd(&g_cnt[2], 1);
    BARG(barid);
    int curTi = tickB[0];
    int cp = 0;                   // current tile parity
    bool branchOK = false;

    while (curTi < nTot) {
        const bool isTrunk = (curTi >= nJT);
        const int base = isTrunk ? ((curTi - nJT) << 6) : (curTi << 6);
        const int nList = isTrunk ? nT : nJ;
        const float* gF = isTrunk ? g_tFeat : g_jFeat;
        const int* gL = isTrunk ? g_trunkList : g_jointList;
        int* tRow = trowB + cp * 64;
        int* tBo  = tboB  + cp * 64;

        // stage rowids (parity-buffered; safe per distance-2 argument)
        if (tg < 64) {
            const int i = base + tg;
            const int rowid = (i < nList) ? __ldg(gL + i) : -1;
            tRow[tg] = rowid;
            tBo[tg]  = (rowid >= 0) ? (rowid >> 6) : 0;
        }
        // next ticket into opposite parity slot
        if (tg == 0) tickB[cp ^ 1] = atomicAdd(&g_cnt[2], 1);

        // gather A fragments straight from global (position-indexed)
        uint32_t A[2][2][4];
        {
            const float* p0 = gF + (base + wr * 32 + g) * 16 + t4;
            #pragma unroll
            for (int rb = 0; rb < 2; rb++) {
                const float* pr = p0 + rb * 256;      // 16 rows * 16 floats
                #pragma unroll
                for (int c = 0; c < 2; c++) {
                    A[c][rb][0] = __float_as_uint(__ldg(pr + c * 8));
                    A[c][rb][1] = __float_as_uint(__ldg(pr + 128 + c * 8));
                    A[c][rb][2] = __float_as_uint(__ldg(pr + c * 8 + 4));
                    A[c][rb][3] = __float_as_uint(__ldg(pr + 128 + c * 8 + 4));
                }
            }
        }
        float d[8][4];
        layer_input_regs<2>(sm + (isTrunk ? S_W0T : S_JW0T), A, d, wc, g, t4);

        BARG(barid);           // #1: prev-tile act reads done; tick/tRow visible
        const int nextTi = tickB[cp ^ 1];

        if (isTrunk) {
            writeback(d, actg, sm + S_B0, wr, wc, g, t4);
            BARG(barid);       // #2
            layer_hidden(sm + S_W1, actg, d, wr, wc, g, t4);
            BARG(barid);       // #3
            writeback(d, actg, sm + S_B1, wr, wc, g, t4);
            BARG(barid);       // #4
            layer_hidden(sm + S_W2, actg, d, wr, wc, g, t4);

            if (!branchOK) {   // gate only the epilogue on branch completion
                while (*(volatile int*)&g_cnt[5] < 64) __nanosleep(32);
                __threadfence();
                branchOK = true;
            }

            int qbo[4], qrid[4];
            #pragma unroll
            for (int q = 0; q < 4; q++) {
                const int row = wr * 32 + (q >> 1) * 16 + g + (q & 1) * 8;
                qbo[q] = tBo[row]; qrid[q] = tRow[row];
            }
            float p[4][3];
            #pragma unroll
            for (int q = 0; q < 4; q++) p[q][0] = p[q][1] = p[q][2] = 0.f;
            #pragma unroll
            for (int rb = 0; rb < 2; rb++)
            #pragma unroll
            for (int nt = 0; nt < 4; nt++) {
                const int col = wc * 32 + nt * 8 + 2 * t4;
                float2 bb = *(const float2*)(sm + S_B2 + col);
                const float* dd = d[rb * 4 + nt];
                float h0 = dd[0] + bb.x, h1 = dd[1] + bb.y;
                float h2 = dd[2] + bb.x, h3 = dd[3] + bb.y;
                const float* mA = g_branchM + qbo[rb * 2] * 384 + col;
                const float* mB = g_branchM + qbo[rb * 2 + 1] * 384 + col;
                #pragma unroll
                for (int part = 0; part < 3; part++) {
                    float2 a = __ldg((const float2*)(mA + part * 128));
                    float2 b = __ldg((const float2*)(mB + part * 128));
                    p[rb * 2][part]     += h0 * a.x + h1 * a.y;
                    p[rb * 2 + 1][part] += h2 * b.x + h3 * b.y;
                }
            }
            #pragma unroll
            for (int q = 0; q < 4; q++)
            #pragma unroll
            for (int part = 0; part < 3; part++) {
                float v = p[q][part];
                v += __shfl_xor_sync(0xffffffffu, v, 1);
                v += __shfl_xor_sync(0xffffffffu, v, 2);
                if (t4 == 0 && qrid[q] >= 0)
                    atomicAdd(out + qrid[q] * 3 + part,
                              v + (wc == 0 ? __ldg(out_b + part) : 0.f));
            }
        } else {
            int qrid[4];
            #pragma unroll
            for (int q = 0; q < 4; q++) {
                const int row = wr * 32 + (q >> 1) * 16 + g + (q & 1) * 8;
                qrid[q] = tRow[row];
            }
            float pj[4][2];
            #pragma unroll
            for (int q = 0; q < 4; q++) pj[q][0] = pj[q][1] = 0.f;
            #pragma unroll
            for (int rb = 0; rb < 2; rb++)
            #pragma unroll
            for (int nt = 0; nt < 4; nt++) {
                const int col = wc * 32 + nt * 8 + 2 * t4;
                float2 jb  = *(const float2*)(sm + S_JB0 + col);
                float2 w0v = *(const float2*)(sm + S_JW1 + col);
                float2 w1v = *(const float2*)(sm + S_JW1 + 128 + col);
                const float* dd = d[rb * 4 + nt];
                float h0 = fmaxf(dd[0] + jb.x, 0.f), h1 = fmaxf(dd[1] + jb.y, 0.f);
                float h2 = fmaxf(dd[2] + jb.x, 0.f), h3 = fmaxf(dd[3] + jb.y, 0.f);
                pj[rb * 2][0]     += h0 * w0v.x + h1 * w0v.y;
                pj[rb * 2][1]     += h0 * w1v.x + h1 * w1v.y;
                pj[rb * 2 + 1][0] += h2 * w0v.x + h3 * w0v.y;
                pj[rb * 2 + 1][1] += h2 * w1v.x + h3 * w1v.y;
            }
            #pragma unroll
            for (int q = 0; q < 4; q++)
            #pragma unroll
            for (int part = 0; part < 2; part++) {
                float v = pj[q][part];
                v += __shfl_xor_sync(0xffffffffu, v, 1);
                v += __shfl_xor_sync(0xffffffffu, v, 2);
                if (t4 == 0 && qrid[q] >= 0)
                    atomicAdd(out + qrid[q] * 3 + part,
                              v + (wc == 0 ? __ldg(joint_b1 + part) : 0.f));
            }
        }
        curTi = nextTi;
        cp ^= 1;
    }
}

// ---------------------------------------------------------------------------

extern "C" void kernel_launch(void* const* d_in, const int* in_sizes, int n_in,
                              void* d_out, int out_size)
{
    const float* init_x    = (const float*)d_in[0];
    const float* query_x   = (const float*)d_in[1];
    const float* init_v    = (const float*)d_in[2];
    const float* query_v   = (const float*)d_in[3];
    const float* init_av   = (const float*)d_in[4];
    const float* query_av  = (const float*)d_in[5];
    const float* trunk_w0  = (const float*)d_in[6];
    const float* trunk_b0  = (const float*)d_in[7];
    const float* trunk_ws  = (const float*)d_in[8];
    const float* trunk_bs  = (const float*)d_in[9];
    const float* branch_w0 = (const float*)d_in[10];
    const float* branch_b0 = (const float*)d_in[11];
    const float* branch_ws = (const float*)d_in[12];
    const float* branch_bs = (const float*)d_in[13];
    const float* out_w     = (const float*)d_in[14];
    const float* out_b     = (const float*)d_in[15];
    const float* spring_w0 = (const float*)d_in[16];
    const float* spring_b0 = (const float*)d_in[17];
    const float* spring_w1 = (const float*)d_in[18];
    const float* spring_b1 = (const float*)d_in[19];
    const float* joint_w0  = (const float*)d_in[20];
    const float* joint_b0  = (const float*)d_in[21];
    const float* joint_w1  = (const float*)d_in[22];
    const float* joint_b1  = (const float*)d_in[23];
    float* out = (float*)d_out;

    int nsm = 148;
    cudaDeviceGetAttribute(&nsm, cudaDevAttrMultiProcessorCount, 0);

    void* cntPtr = nullptr;
    cudaGetSymbolAddress(&cntPtr, g_cnt);
    cudaMemsetAsync(cntPtr, 0, 8 * sizeof(int));
    cudaMemsetAsync(out, 0, (size_t)out_size * sizeof(float));

    const int smem = S_TOTAL * sizeof(float);
    cudaFuncSetAttribute(ffp_all, cudaFuncAttributeMaxDynamicSharedMemorySize, smem);

    ffp_all<<<nsm, NT, smem>>>(init_x, query_x, init_v, query_v, init_av, query_av,
                               trunk_w0, trunk_b0, trunk_ws, trunk_bs,
                               branch_w0, branch_b0, branch_ws, branch_bs,
                               out_w, out_b,
                               spring_w0, spring_b0, spring_w1, spring_b1,
                               joint_w0, joint_b0, joint_w1, joint_b1,
                               out);
}

// round 16
// speedup vs baseline: 2.4429x; 1.1554x over previous
#include <cuda_runtime.h>
#include <math.h>
#include <stdint.h>

// ===========================================================================
// ForceFieldPredictor R14 (= R13 fixed): Phase B as 8 independent warp-pair
// chains per CTA.
//   Pair = 2 warps (64 thr) owning a 16-row tile stream; pair-scoped named
//   barriers (bar.sync 1+pid, 64); private 16x132 act slice per pair.
//   Trunk tile: ldg A -> L0 -> wb -> H1 -> wb -> H2 -> branchM epilogue,
//   4 pair-barriers. Joint tile: ldg A -> L0 -> dot, 1 pair-barrier.
//   Phase 0 (branch MLP) and scan unchanged from R12.
// ===========================================================================

typedef unsigned long long ull;

__device__ float g_branchM[4096 * 384];     // planar: [bo][part*128 + k]
__device__ int   g_cnt[8];                  // 0:nT 1:nJ 2:tileTick 3:scanTick
                                            // 4:scanDone 5:branchDone (memset)
__device__ int   g_trunkList[262144 + 16];
__device__ int   g_jointList[262144 + 16];
__device__ float g_tFeat[(262144 + 16) * 16];
__device__ float g_jFeat[(262144 + 16) * 16];

// ---------------------------- small PTX helpers ----------------------------

__device__ __forceinline__ uint32_t f2tf32(float x) {
    uint32_t r; asm("cvt.rna.tf32.f32 %0, %1;" : "=r"(r) : "f"(x)); return r;
}
__device__ __forceinline__ float tf32f(float x) { return __uint_as_float(f2tf32(x)); }

__device__ __forceinline__ void mma8(float* d, const uint32_t* a, uint32_t b0, uint32_t b1) {
    asm volatile("mma.sync.aligned.m16n8k8.row.col.f32.tf32.tf32.f32 "
                 "{%0,%1,%2,%3}, {%4,%5,%6,%7}, {%8,%9}, {%0,%1,%2,%3};"
                 : "+f"(d[0]), "+f"(d[1]), "+f"(d[2]), "+f"(d[3])
                 : "r"(a[0]), "r"(a[1]), "r"(a[2]), "r"(a[3]), "r"(b0), "r"(b1));
}

#define BARG(id)  asm volatile("bar.sync %0, %1;" :: "r"(id), "r"(256) : "memory")
#define BARP(id)  asm volatile("bar.sync %0, %1;" :: "r"(id), "r"(64)  : "memory")

// ---------------------------- smem layout (floats) -------------------------
#define S_W1    0                 // 16384 : hidden W1 (tf32, pair-packed XOR)
#define S_W2    16384             // 16384 : hidden W2
#define S_ACT   32768             // 16896 : phase0: 2x(64x132); phaseB: 8x(16x132)
#define S_W0T   49664             // 2304 : input W0t [n][k], stride 18
#define S_JW0T  51968             // 2304 : joint W0t
#define S_B0    54272
#define S_B1    54400
#define S_B2    54528
#define S_JB0   54656
#define S_JW1   54784             // 256 : [part][128]
#define S_OUTW  55040             // 384 : out_w planar (phase 0 only)
#define S_TICK  55424             // 18 ints: 8 pairs x 2 parity + scan slot
#define S_TOTAL 55444

#define ASTR 132
#define WSTR 18
#define NT   512
#define GSLICE 8448               // phase-0 group act slice (64 x 132)
#define PSLICE 2112               // phase-B pair act slice (16 x 132)

// pair-packed chunk-XOR weight placement: W[n][k] ->
//   n*128 + ((k>>3) ^ (n&7))*8 + (k&3)*2 + ((k>>2)&1)
__device__ __forceinline__ int wswz(int n, int k) {
    return n * 128 + ((((k >> 3) ^ (n & 7)) << 3) + ((k & 3) << 1) + ((k >> 2) & 1));
}

// ------------------ phase-0 group helpers (8-warp, as R12) -----------------

template<int C>
__device__ __forceinline__ void layer_input_regs(const float* __restrict__ sWin,
                                                 const uint32_t A[][2][4],
                                                 float (*d)[4], int wc, int g, int t4)
{
    #pragma unroll
    for (int i = 0; i < 8; i++)
        d[i][0] = d[i][1] = d[i][2] = d[i][3] = 0.f;
    const float* b0p = sWin + (wc * 32 + g) * WSTR + t4;
    #pragma unroll
    for (int c = 0; c < C; c++) {
        #pragma unroll
        for (int nt = 0; nt < 4; nt++) {
            const float* bp = b0p + nt * 8 * WSTR + c * 8;
            uint32_t b0 = __float_as_uint(bp[0]);
            uint32_t b1 = __float_as_uint(bp[4]);
            mma8(d[nt],     A[c][0], b0, b1);
            mma8(d[4 + nt], A[c][1], b0, b1);
        }
    }
}

__device__ __forceinline__ void layer_hidden(const float* __restrict__ sW,
                                             const float* __restrict__ act,
                                             float (*d)[4],
                                             int wr, int wc, int g, int t4)
{
    #pragma unroll
    for (int i = 0; i < 8; i++)
        d[i][0] = d[i][1] = d[i][2] = d[i][3] = 0.f;
    const float* a0p = act + (wr * 32 + g) * ASTR + t4;
    const float* b0p = sW + (wc * 32 + g) * 128;
    #pragma unroll 4
    for (int c = 0; c < 16; c++) {
        uint32_t A[2][4];
        #pragma unroll
        for (int rb = 0; rb < 2; rb++) {
            const float* ap = a0p + rb * 16 * ASTR + c * 8;
            A[rb][0] = __float_as_uint(ap[0]);
            A[rb][1] = __float_as_uint(ap[8 * ASTR]);
            A[rb][2] = __float_as_uint(ap[4]);
            A[rb][3] = __float_as_uint(ap[8 * ASTR + 4]);
        }
        const int coff = ((c ^ g) << 3) + (t4 << 1);
        #pragma unroll
        for (int nt = 0; nt < 4; nt++) {
            float2 b = *(const float2*)(b0p + nt * 1024 + coff);
            uint32_t b0 = __float_as_uint(b.x);
            uint32_t b1 = __float_as_uint(b.y);
            mma8(d[nt],     A[0], b0, b1);
            mma8(d[4 + nt], A[1], b0, b1);
        }
    }
}

__device__ __forceinline__ void writeback(float (*d)[4], float* __restrict__ act,
                                          const float* __restrict__ bias,
                                          int wr, int wc, int g, int t4)
{
    #pragma unroll
    for (int rb = 0; rb < 2; rb++) {
        const int r = wr * 32 + rb * 16 + g;
        #pragma unroll
        for (int nt = 0; nt < 4; nt++) {
            const int col = wc * 32 + nt * 8 + t4 * 2;
            float2 bb = *(const float2*)(bias + col);
            float* p = act + r * ASTR + col;
            const float* dd = d[rb * 4 + nt];
            p[0] = tf32f(fmaxf(dd[0] + bb.x, 0.f));
            p[1] = tf32f(fmaxf(dd[1] + bb.y, 0.f));
            p[8 * ASTR]     = tf32f(fmaxf(dd[2] + bb.x, 0.f));
            p[8 * ASTR + 1] = tf32f(fmaxf(dd[3] + bb.y, 0.f));
        }
    }
}

// ------------------ phase-B pair helpers (16-row warp tile) ----------------
// warp covers 16 rows x 64 cols (8 n-blocks at cols wp*64 + n*8).

__device__ __forceinline__ void l0_16v(const float* __restrict__ sWin,
                                       const uint32_t A[2][4],
                                       float (*d)[4], int wp, int g, int t4)
{
    #pragma unroll
    for (int i = 0; i < 8; i++)
        d[i][0] = d[i][1] = d[i][2] = d[i][3] = 0.f;
    const float* b0p = sWin + (wp * 64 + g) * WSTR + t4;
    #pragma unroll
    for (int c = 0; c < 2; c++) {
        #pragma unroll
        for (int n = 0; n < 8; n++) {
            const float* bp = b0p + n * 8 * WSTR + c * 8;
            uint32_t b0 = __float_as_uint(bp[0]);
            uint32_t b1 = __float_as_uint(bp[4]);
            mma8(d[n], A[c], b0, b1);
        }
    }
}

__device__ __forceinline__ void hidden16(const float* __restrict__ sW,
                                         const float* __restrict__ act,
                                         float (*d)[4], int wp, int g, int t4)
{
    #pragma unroll
    for (int i = 0; i < 8; i++)
        d[i][0] = d[i][1] = d[i][2] = d[i][3] = 0.f;
    const float* a0p = act + g * ASTR + t4;
    const float* b0p = sW + (wp * 64 + g) * 128;
    #pragma unroll 4
    for (int c = 0; c < 16; c++) {
        uint32_t A[4];
        const float* ap = a0p + c * 8;
        A[0] = __float_as_uint(ap[0]);
        A[1] = __float_as_uint(ap[8 * ASTR]);
        A[2] = __float_as_uint(ap[4]);
        A[3] = __float_as_uint(ap[8 * ASTR + 4]);
        const int coff = ((c ^ g) << 3) + (t4 << 1);
        #pragma unroll
        for (int n = 0; n < 8; n++) {
            float2 b = *(const float2*)(b0p + n * 1024 + coff);
            mma8(d[n], A, __float_as_uint(b.x), __float_as_uint(b.y));
        }
    }
}

__device__ __forceinline__ void wb16(float (*d)[4], float* __restrict__ pact,
                                     const float* __restrict__ bias,
                                     int wp, int g, int t4)
{
    #pragma unroll
    for (int n = 0; n < 8; n++) {
        const int col = wp * 64 + n * 8 + t4 * 2;
        float2 bb = *(const float2*)(bias + col);
        float* p = pact + g * ASTR + col;
        const float* dd = d[n];
        p[0] = tf32f(fmaxf(dd[0] + bb.x, 0.f));
        p[1] = tf32f(fmaxf(dd[1] + bb.y, 0.f));
        p[8 * ASTR]     = tf32f(fmaxf(dd[2] + bb.x, 0.f));
        p[8 * ASTR + 1] = tf32f(fmaxf(dd[3] + bb.y, 0.f));
    }
}

// --------------------------- row feature computation -----------------------

__device__ __forceinline__ float segdist(float px, float py, float ax, float ay,
                                         float abx, float aby, float s)
{
    float t = ((px - ax) * abx + (py - ay) * aby) / s;
    t = fminf(fmaxf(t, 0.f), 1.f);
    float dx = px - (ax + t * abx);
    float dy = py - (ay + t * aby);
    return sqrtf(dx * dx + dy * dy);
}

struct RowF {
    float relx, rely, dist, maskD, maskJ, maskS;
    float i2, i3, i4, iav, i7f;
    float q2, q3, q4, qvx, qvy, qav;
};

__device__ __forceinline__ RowF rowCalc(int rowid,
    const float* __restrict__ init_x,  const float* __restrict__ query_x,
    const float* __restrict__ init_v,  const float* __restrict__ query_v,
    const float* __restrict__ init_av, const float* __restrict__ query_av)
{
    RowF f;
    const int bo = rowid >> 6, t = rowid & 63, b = rowid >> 12;
    const float* ix = init_x + bo * 9;
    const float* qx = query_x + (b * 64 + t) * 9;
    float i2 = ix[2], i3 = ix[3], i4 = ix[4], i7 = ix[7], i8 = ix[8];
    float q2 = qx[2], q3 = qx[3], q4 = qx[4], q7 = qx[7], q8 = qx[8];
    f.relx = qx[0] - ix[0]; f.rely = qx[1] - ix[1];
    f.qvx = query_v[(b * 64 + t) * 2 + 0] - init_v[bo * 2 + 0];
    f.qvy = query_v[(b * 64 + t) * 2 + 1] - init_v[bo * 2 + 1];
    f.iav = init_av[bo];
    f.qav = query_av[b * 64 + t] - f.iav;

    float sn1, cs1; sincosf(i3 * 100.f, &sn1, &cs1);
    float sn2, cs2; sincosf(q3 * 100.f, &sn2, &cs2);
    float o1x = i2 * 0.5f * cs1, o1y = i2 * 0.5f * sn1;
    float o2x = q2 * 0.5f * cs2, o2y = q2 * 0.5f * sn2;
    float ab1x = 2.f * o1x, ab1y = 2.f * o1y;
    float ab2x = 2.f * o2x, ab2y = 2.f * o2y;
    float ss1 = ab1x * ab1x + ab1y * ab1y + 1e-8f;
    float ss2 = ab2x * ab2x + ab2y * ab2y + 1e-8f;
    float A2x = f.relx - o2x, A2y = f.rely - o2y;
    float B2x = f.relx + o2x, B2y = f.rely + o2y;
    float d1 = segdist(A2x, A2y, -o1x, -o1y, ab1x, ab1y, ss1);
    float d2 = segdist(B2x, B2y, -o1x, -o1y, ab1x, ab1y, ss1);
    float d3 = segdist(-o1x, -o1y, A2x, A2y, ab2x, ab2y, ss2);
    float d4 = segdist(o1x, o1y, A2x, A2y, ab2x, ab2y, ss2);
    f.dist = fminf(fminf(d1, d2), fminf(d3, d4)) - i4 - q4;
    f.maskD = (f.dist <= 0.f) ? 1.f : 0.f;
    float ti = truncf(i7), tq = truncf(q7);
    f.maskJ = (ti == tq && i7 > 0.f) ? 1.f : 0.f;
    f.maskS = (i8 == q8 && i8 > 0.f) ? 1.f : 0.f;
    f.i2 = i2; f.i3 = i3; f.i4 = i4; f.i7f = i7 - ti;
    f.q2 = q2; f.q3 = q3; f.q4 = q4;
    return f;
}

// ------------------------------- fused kernel ------------------------------

extern "C" __global__ void __launch_bounds__(NT, 1)
ffp_all(const float* __restrict__ init_x,  const float* __restrict__ query_x,
        const float* __restrict__ init_v,  const float* __restrict__ query_v,
        const float* __restrict__ init_av, const float* __restrict__ query_av,
        const float* __restrict__ trunk_w0, const float* __restrict__ trunk_b0,
        const float* __restrict__ trunk_ws, const float* __restrict__ trunk_bs,
        const float* __restrict__ branch_w0, const float* __restrict__ branch_b0,
        const float* __restrict__ branch_ws, const float* __restrict__ branch_bs,
        const float* __restrict__ out_w,   const float* __restrict__ out_b,
        const float* __restrict__ spring_w0, const float* __restrict__ spring_b0,
        const float* __restrict__ spring_w1, const float* __restrict__ spring_b1,
        const float* __restrict__ joint_w0, const float* __restrict__ joint_b0,
        const float* __restrict__ joint_w1, const float* __restrict__ joint_b1,
        float* __restrict__ out)
{
    extern __shared__ float sm[];
    const int tid = threadIdx.x;
    const int lane = tid & 31;
    const int g = lane >> 2, t4 = lane & 3;
    // phase-0 group indices
    const int gid = tid >> 8, tg = tid & 255;
    const int wid_g = tg >> 5;
    const int wr = wid_g & 1, wc = wid_g >> 1;
    const int barid = 1 + gid;
    int* scanT = (int*)(sm + S_TICK) + 16;

    // ================= Phase 0: branch MLP via tf32 (CTAs 0..31) ===========
    if (blockIdx.x < 32) {
        float* actg = sm + S_ACT + gid * GSLICE;
        for (int i = tid * 4; i < 2304; i += NT * 4)
            *(float4*)(sm + S_W0T + i) = make_float4(0.f, 0.f, 0.f, 0.f);
        __syncthreads();
        for (int idx = tid; idx < 16384; idx += NT) {
            int k = idx >> 7, n = idx & 127;
            int off = wswz(n, k);
            sm[S_W1 + off] = tf32f(branch_ws[idx]);
            sm[S_W2 + off] = tf32f(branch_ws[16384 + idx]);
        }
        for (int idx = tid; idx < 3 * 128; idx += NT) {
            int k = idx >> 7, n = idx & 127;
            sm[S_W0T + n * WSTR + k] = tf32f(branch_w0[(2 + k) * 128 + n]);
        }
        for (int i = tid; i < 128; i += NT) {
            sm[S_B0 + i] = branch_b0[i];
            sm[S_B1 + i] = branch_bs[i];
            sm[S_B2 + i] = branch_bs[128 + i];
        }
        for (int i = tid; i < 384; i += NT)
            sm[S_OUTW + i] = out_w[(i & 127) * 3 + (i >> 7)];
        __syncthreads();

        {
            const int boBase = (blockIdx.x * 2 + gid) * 64;
            uint32_t A[1][2][4];
            {
                const int r0 = wr * 32 + g;
                #pragma unroll
                for (int rb = 0; rb < 2; rb++) {
                    const float* ix0 = init_x + (boBase + r0 + rb * 16) * 9;
                    const float* ix8 = init_x + (boBase + r0 + rb * 16 + 8) * 9;
                    A[0][rb][0] = (t4 < 3) ? f2tf32(__ldg(ix0 + 2 + t4)) : 0u;
                    A[0][rb][1] = (t4 < 3) ? f2tf32(__ldg(ix8 + 2 + t4)) : 0u;
                    A[0][rb][2] = 0u;
                    A[0][rb][3] = 0u;
                }
            }
            float d[8][4];
            layer_input_regs<1>(sm + S_W0T, A, d, wc, g, t4);
            writeback(d, actg, sm + S_B0, wr, wc, g, t4);
            BARG(barid);
            layer_hidden(sm + S_W1, actg, d, wr, wc, g, t4);
            BARG(barid);
            writeback(d, actg, sm + S_B1, wr, wc, g, t4);
            BARG(barid);
            layer_hidden(sm + S_W2, actg, d, wr, wc, g, t4);
            #pragma unroll
            for (int rb = 0; rb < 2; rb++) {
                const int rA = wr * 32 + rb * 16 + g;
                const int rB = rA + 8;
                #pragma unroll
                for (int nt = 0; nt < 4; nt++) {
                    const int col = wc * 32 + nt * 8 + 2 * t4;
                    float2 bb = *(const float2*)(sm + S_B2 + col);
                    const float* dd = d[rb * 4 + nt];
                    float h0 = dd[0] + bb.x, h1 = dd[1] + bb.y;
                    float h2 = dd[2] + bb.x, h3 = dd[3] + bb.y;
                    #pragma unroll
                    for (int part = 0; part < 3; part++) {
                        float2 ow = *(const float2*)(sm + S_OUTW + part * 128 + col);
                        *(float2*)(g_branchM + (boBase + rA) * 384 + part * 128 + col)
                            = make_float2(h0 * ow.x, h1 * ow.y);
                        *(float2*)(g_branchM + (boBase + rB) * 384 + part * 128 + col)
                            = make_float2(h2 * ow.x, h3 * ow.y);
                    }
                }
            }
            BARG(barid);
            if (tg == 0) { __threadfence(); atomicAdd(&g_cnt[5], 1); }
        }
        __syncthreads();
    }

    // ---- stage trunk/joint weights (all CTAs) ----
    for (int i = tid * 4; i < 4608; i += NT * 4)
        *(float4*)(sm + S_W0T + i) = make_float4(0.f, 0.f, 0.f, 0.f);
    __syncthreads();
    for (int idx = tid; idx < 16384; idx += NT) {
        int k = idx >> 7, n = idx & 127;
        int off = wswz(n, k);
        sm[S_W1 + off] = tf32f(trunk_ws[idx]);
        sm[S_W2 + off] = tf32f(trunk_ws[16384 + idx]);
    }
    for (int idx = tid; idx < 9 * 128; idx += NT) {
        int k = idx >> 7, n = idx & 127;
        sm[S_W0T + n * WSTR + k] = tf32f(trunk_w0[idx]);
    }
    for (int idx = tid; idx < 15 * 128; idx += NT) {
        int k = idx >> 7, n = idx & 127;
        sm[S_JW0T + n * WSTR + k] = tf32f(joint_w0[idx]);
    }
    for (int i = tid; i < 128; i += NT) {
        sm[S_B0 + i]  = trunk_b0[i];
        sm[S_B1 + i]  = trunk_bs[i];
        sm[S_B2 + i]  = trunk_bs[128 + i];
        sm[S_JB0 + i] = joint_b0[i];
    }
    if (tid < 256) sm[S_JW1 + tid] = joint_w1[(tid & 127) * 2 + (tid >> 7)];
    __syncthreads();

    // ================= Scan: chunk-stolen rows =============================
    for (;;) {
        if (tid == 0) *scanT = atomicAdd(&g_cnt[3], 1);
        __syncthreads();
        const int ch = *scanT;
        __syncthreads();
        if (ch >= 128) break;
        #pragma unroll
        for (int i = 0; i < 4; i++) {
            const int rid = ch * 2048 + i * 512 + tid;
            RowF f = rowCalc(rid, init_x, query_x, init_v, query_v, init_av, query_av);
            unsigned mD = __ballot_sync(0xffffffffu, f.maskD > 0.f);
            if (mD) {
                int base = 0;
                if (lane == 0) base = atomicAdd(&g_cnt[0], __popc(mD));
                base = __shfl_sync(0xffffffffu, base, 0);
                if (f.maskD > 0.f) {
                    int pos = base + __popc(mD & ((1u << lane) - 1u));
                    g_trunkList[pos] = rid;
                    float4* fp = (float4*)(g_tFeat + pos * 16);
                    fp[0] = make_float4(tf32f(f.relx), tf32f(f.rely), tf32f(f.q2), tf32f(f.q3));
                    fp[1] = make_float4(tf32f(f.q4), tf32f(f.qvx), tf32f(f.qvy), tf32f(f.qav));
                    fp[2] = make_float4(tf32f(f.dist * 100.f), 0.f, 0.f, 0.f);
                    fp[3] = make_float4(0.f, 0.f, 0.f, 0.f);
                }
            }
            unsigned mJ = __ballot_sync(0xffffffffu, f.maskJ > 0.f);
            if (mJ) {
                int base = 0;
                if (lane == 0) base = atomicAdd(&g_cnt[1], __popc(mJ));
                base = __shfl_sync(0xffffffffu, base, 0);
                if (f.maskJ > 0.f) {
                    int pos = base + __popc(mJ & ((1u << lane) - 1u));
                    g_jointList[pos] = rid;
                    float4* fp = (float4*)(g_jFeat + pos * 16);
                    fp[0] = make_float4(0.f, 0.f, tf32f(f.i2), tf32f(f.i3));
                    fp[1] = make_float4(tf32f(f.i4), tf32f(f.relx), tf32f(f.rely), tf32f(f.q2));
                    fp[2] = make_float4(tf32f(f.q3), tf32f(f.q4), tf32f(f.qvx), tf32f(f.qvy));
                    fp[3] = make_float4(tf32f(f.iav), tf32f(f.qav), tf32f(f.i7f), 0.f);
                }
            }
            if (f.maskS > 0.f) {   // essentially never; exact scalar path
                float len = sqrtf(f.relx * f.relx + f.rely * f.rely);
                float sf = __ldg(spring_b1);
                for (int k = 0; k < 128; k++)
                    sf = fmaf(fmaxf(fmaf(len, __ldg(spring_w0 + k), __ldg(spring_b0 + k)), 0.f),
                              __ldg(spring_w1 + k), sf);
                float inv = 1.f / (len + 1e-8f);
                atomicAdd(out + rid * 3 + 0, sf * (-f.relx * inv));
                atomicAdd(out + rid * 3 + 1, sf * (-f.rely * inv));
            }
        }
        __threadfence();
        __syncthreads();
        if (tid == 0) atomicAdd(&g_cnt[4], 1);
    }

    // ---- wait for scan completion ----
    if (tid == 0) {
        while (*(volatile int*)&g_cnt[4] < 128) __nanosleep(64);
    }
    __syncthreads();
    __threadfence();
    const int nT = *(volatile int*)&g_cnt[0];
    const int nJ = *(volatile int*)&g_cnt[1];
    const int nJ16 = (nJ + 15) >> 4, nT16 = (nT + 15) >> 4;
    const int nTot = nJ16 + nT16;

    // ================= Phase B: 8 independent pair chains ===================
    const int pid = tid >> 6;               // pair 0..7
    const int wp  = (tid >> 5) & 1;         // warp-in-pair
    const int pbar = 1 + pid;
    float* pact = sm + S_ACT + pid * PSLICE;
    int* ptick = (int*)(sm + S_TICK) + pid * 2;

    if (wp == 0 && lane == 0) ptick[0] = atomicAdd(&g_cnt[2], 1);
    BARP(pbar);
    int cp = 0;
    int cur = ptick[0];
    bool branchOK = false;

    while (cur < nTot) {
        if (wp == 0 && lane == 0) ptick[cp ^ 1] = atomicAdd(&g_cnt[2], 1);
        const bool isTrunk = (cur >= nJ16);
        const int base = (isTrunk ? (cur - nJ16) : cur) << 4;
        const int nList = isTrunk ? nT : nJ;
        const int* gL = isTrunk ? g_trunkList : g_jointList;
        const float* gF = isTrunk ? g_tFeat : g_jFeat;
        const int i0 = base + g, i8 = base + g + 8;
        const int rid0 = (i0 < nList) ? __ldg(gL + i0) : -1;
        const int rid8 = (i8 < nList) ? __ldg(gL + i8) : -1;

        uint32_t A[2][4];
        {
            const float* p0 = gF + i0 * 16 + t4;
            const float* p8 = gF + i8 * 16 + t4;
            #pragma unroll
            for (int c = 0; c < 2; c++) {
                A[c][0] = __float_as_uint(__ldg(p0 + c * 8));
                A[c][1] = __float_as_uint(__ldg(p8 + c * 8));
                A[c][2] = __float_as_uint(__ldg(p0 + c * 8 + 4));
                A[c][3] = __float_as_uint(__ldg(p8 + c * 8 + 4));
            }
        }
        float d[8][4];
        int nxt;

        if (isTrunk) {
            l0_16v(sm + S_W0T, A, d, wp, g, t4);
            wb16(d, pact, sm + S_B0, wp, g, t4);
            BARP(pbar);                 // #1 (also: ptick visible)
            nxt = ptick[cp ^ 1];
            hidden16(sm + S_W1, pact, d, wp, g, t4);
            BARP(pbar);                 // #2
            wb16(d, pact, sm + S_B1, wp, g, t4);
            BARP(pbar);                 // #3
            hidden16(sm + S_W2, pact, d, wp, g, t4);

            if (!branchOK) {
                while (*(volatile int*)&g_cnt[5] < 64) __nanosleep(32);
                __threadfence();
                branchOK = true;
            }
            const int bo0 = (rid0 >= 0) ? (rid0 >> 6) : 0;
            const int bo8 = (rid8 >= 0) ? (rid8 >> 6) : 0;
            float p0a[3] = {0.f, 0.f, 0.f}, p8a[3] = {0.f, 0.f, 0.f};
            #pragma unroll
            for (int n = 0; n < 8; n++) {
                const int col = wp * 64 + n * 8 + 2 * t4;
                float2 bb = *(const float2*)(sm + S_B2 + col);
                const float* dd = d[n];
                float h0 = dd[0] + bb.x, h1 = dd[1] + bb.y;
                float h2 = dd[2] + bb.x, h3 = dd[3] + bb.y;
                const float* mA = g_branchM + bo0 * 384 + col;
                const float* mB = g_branchM + bo8 * 384 + col;
                #pragma unroll
                for (int part = 0; part < 3; part++) {
                    float2 a = __ldg((const float2*)(mA + part * 128));
                    float2 b = __ldg((const float2*)(mB + part * 128));
                    p0a[part] += h0 * a.x + h1 * a.y;
                    p8a[part] += h2 * b.x + h3 * b.y;
                }
            }
            #pragma unroll
            for (int part = 0; part < 3; part++) {
                float v = p0a[part];
                v += __shfl_xor_sync(0xffffffffu, v, 1);
                v += __shfl_xor_sync(0xffffffffu, v, 2);
                if (t4 == 0 && rid0 >= 0)
                    atomicAdd(out + rid0 * 3 + part,
                              v + (wp == 0 ? __ldg(out_b + part) : 0.f));
                float w = p8a[part];
                w += __shfl_xor_sync(0xffffffffu, w, 1);
                w += __shfl_xor_sync(0xffffffffu, w, 2);
                if (t4 == 0 && rid8 >= 0)
                    atomicAdd(out + rid8 * 3 + part,
                              w + (wp == 0 ? __ldg(out_b + part) : 0.f));
            }
            BARP(pbar);                 // #4: pact reads done before next wb
        } else {
            l0_16v(sm + S_JW0T, A, d, wp, g, t4);
            float p0a[2] = {0.f, 0.f}, p8a[2] = {0.f, 0.f};
            #pragma unroll
            for (int n = 0; n < 8; n++) {
                const int col = wp * 64 + n * 8 + 2 * t4;
                float2 jb  = *(const float2*)(sm + S_JB0 + col);
                float2 w0v = *(const float2*)(sm + S_JW1 + col);
                float2 w1v = *(const float2*)(sm + S_JW1 + 128 + col);
                const float* dd = d[n];
                float h0 = fmaxf(dd[0] + jb.x, 0.f), h1 = fmaxf(dd[1] + jb.y, 0.f);
                float h2 = fmaxf(dd[2] + jb.x, 0.f), h3 = fmaxf(dd[3] + jb.y, 0.f);
                p0a[0] += h0 * w0v.x + h1 * w0v.y;
                p0a[1] += h0 * w1v.x + h1 * w1v.y;
                p8a[0] += h2 * w0v.x + h3 * w0v.y;
                p8a[1] += h2 * w1v.x + h3 * w1v.y;
            }
            #pragma unroll
            for (int part = 0; part < 2; part++) {
                float v = p0a[part];
                v += __shfl_xor_sync(0xffffffffu, v, 1);
                v += __shfl_xor_sync(0xffffffffu, v, 2);
                if (t4 == 0 && rid0 >= 0)
                    atomicAdd(out + rid0 * 3 + part,
                              v + (wp == 0 ? __ldg(joint_b1 + part) : 0.f));
                float w = p8a[part];
                w += __shfl_xor_sync(0xffffffffu, w, 1);
                w += __shfl_xor_sync(0xffffffffu, w, 2);
                if (t4 == 0 && rid8 >= 0)
                    atomicAdd(out + rid8 * 3 + part,
                              w + (wp == 0 ? __ldg(joint_b1 + part) : 0.f));
            }
            BARP(pbar);                 // ticket visibility
            nxt = ptick[cp ^ 1];
        }
        cur = nxt;
        cp ^= 1;
    }
}

// ---------------------------------------------------------------------------

extern "C" void kernel_launch(void* const* d_in, const int* in_sizes, int n_in,
                              void* d_out, int out_size)
{
    const float* init_x    = (const float*)d_in[0];
    const float* query_x   = (const float*)d_in[1];
    const float* init_v    = (const float*)d_in[2];
    const float* query_v   = (const float*)d_in[3];
    const float* init_av   = (const float*)d_in[4];
    const float* query_av  = (const float*)d_in[5];
    const float* trunk_w0  = (const float*)d_in[6];
    const float* trunk_b0  = (const float*)d_in[7];
    const float* trunk_ws  = (const float*)d_in[8];
    const float* trunk_bs  = (const float*)d_in[9];
    const float* branch_w0 = (const float*)d_in[10];
    const float* branch_b0 = (const float*)d_in[11];
    const float* branch_ws = (const float*)d_in[12];
    const float* branch_bs = (const float*)d_in[13];
    const float* out_w     = (const float*)d_in[14];
    const float* out_b     = (const float*)d_in[15];
    const float* spring_w0 = (const float*)d_in[16];
    const float* spring_b0 = (const float*)d_in[17];
    const float* spring_w1 = (const float*)d_in[18];
    const float* spring_b1 = (const float*)d_in[19];
    const float* joint_w0  = (const float*)d_in[20];
    const float* joint_b0  = (const float*)d_in[21];
    const float* joint_w1  = (const float*)d_in[22];
    const float* joint_b1  = (const float*)d_in[23];
    float* out = (float*)d_out;

    int nsm = 148;
    cudaDeviceGetAttribute(&nsm, cudaDevAttrMultiProcessorCount, 0);

    void* cntPtr = nullptr;
    cudaGetSymbolAddress(&cntPtr, g_cnt);
    cudaMemsetAsync(cntPtr, 0, 8 * sizeof(int));
    cudaMemsetAsync(out, 0, (size_t)out_size * sizeof(float));

    const int smem = S_TOTAL * sizeof(float);
    cudaFuncSetAttribute(ffp_all, cudaFuncAttributeMaxDynamicSharedMemorySize, smem);

    ffp_all<<<nsm, NT, smem>>>(init_x, query_x, init_v, query_v, init_av, query_av,
                               trunk_w0, trunk_b0, trunk_ws, trunk_bs,
                               branch_w0, branch_b0, branch_ws, branch_bs,
                               out_w, out_b,
                               spring_w0, spring_b0, spring_w1, spring_b1,
                               joint_w0, joint_b0, joint_w1, joint_b1,
                               out);
}